// round 11
// baseline (speedup 1.0000x reference)
#include <cuda_runtime.h>
#include <cuda_bf16.h>
#include <math.h>
#include <stdint.h>

#define NNODES 32768
#define NEDGES 524288
#define NB     32
#define NPG    1024
#define CH     128
#define CIN    64
#define SLOTCAP 72

// ================= helpers =================
__device__ __forceinline__ uint32_t smem_u32(const void* p) {
    uint32_t a;
    asm("{ .reg .u64 t; cvta.to.shared.u64 t, %1; cvt.u32.u64 %0, t; }" : "=r"(a) : "l"(p));
    return a;
}
__device__ __forceinline__ void ffma2(unsigned long long& d, unsigned long long a, unsigned long long b) {
    asm("fma.rn.f32x2 %0, %1, %2, %0;" : "+l"(d) : "l"(a), "l"(b));
}
__device__ __forceinline__ unsigned long long dup_f32(float v) {
    unsigned long long r;
    asm("mov.b64 %0, {%1, %1};" : "=l"(r) : "f"(v));
    return r;
}
__device__ __forceinline__ float2 u2f(unsigned long long v) {
    float2 f;
    asm("mov.b64 {%0, %1}, %2;" : "=f"(f.x), "=f"(f.y) : "l"(v));
    return f;
}
#define CP_ASYNC16(dst, src) asm volatile("cp.async.ca.shared.global [%0], [%1], 16;" :: "r"(dst), "l"(src))
#define CP_COMMIT()          asm volatile("cp.async.commit_group;" ::: "memory")
#define CP_WAIT(n)           asm volatile("cp.async.wait_group %0;" :: "n"(n) : "memory")

#define MMA_BF16(cf, a0, a1, a2, a3, b0, b1) \
    asm volatile("mma.sync.aligned.m16n8k16.row.col.f32.bf16.bf16.f32 " \
        "{%0,%1,%2,%3},{%4,%5,%6,%7},{%8,%9},{%0,%1,%2,%3};" \
        : "+f"((cf)[0]), "+f"((cf)[1]), "+f"((cf)[2]), "+f"((cf)[3]) \
        : "r"(a0), "r"(a1), "r"(a2), "r"(a3), "r"(b0), "r"(b1))

__device__ __forceinline__ uint32_t pack_hi(float a, float b) {
    __nv_bfloat162 h;
    h.x = __float2bfloat16_rn(a); h.y = __float2bfloat16_rn(b);
    return *reinterpret_cast<uint32_t*>(&h);
}
__device__ __forceinline__ uint32_t pack_lo(float a, float b) {
    __nv_bfloat16 ha = __float2bfloat16_rn(a), hb = __float2bfloat16_rn(b);
    __nv_bfloat162 l;
    l.x = __float2bfloat16_rn(a - __bfloat162float(ha));
    l.y = __float2bfloat16_rn(b - __bfloat162float(hb));
    return *reinterpret_cast<uint32_t*>(&l);
}
__device__ __forceinline__ void split1(float v, __nv_bfloat16& h, __nv_bfloat16& l) {
    h = __float2bfloat16_rn(v);
    l = __float2bfloat16_rn(v - __bfloat162float(h));
}

// ================= device scratch =================
// Gather sources have 8 extra rows; row NNODES is never written => stays zero
// (sentinel target for padded CSR slots).
__device__ int   g_deg[NNODES];
__device__ int   g_srcbuf[NNODES * SLOTCAP];
__device__ float g_dinv[NNODES];

__device__ float g_xs [(NNODES + 8) * CIN];   // dinv-prescaled x
__device__ float g_lin[(NNODES + 8) * CH];    // dinv-prescaled GEMM out
__device__ float g_s  [(NNODES + 8) * CH];
__device__ float g_y  [NNODES * CH];
__device__ float g_h  [NNODES * CH];

__device__ __align__(16) __nv_bfloat16 g_axh[NNODES * CIN], g_axl[NNODES * CIN];
__device__ __align__(16) __nv_bfloat16 g_hah[NNODES * CH],  g_hal[NNODES * CH];
__device__ __align__(16) __nv_bfloat16 g_hbh[NNODES * CH],  g_hbl[NNODES * CH];
__device__ __align__(16) __nv_bfloat16 g_hTh[CH * NNODES],  g_hTl[CH * NNODES];
__device__ __align__(16) __nv_bfloat16 g_sTh[CH * NNODES],  g_sTl[CH * NNODES];
__device__ __align__(16) __nv_bfloat16 g_tTh[CH * NNODES],  g_tTl[CH * NNODES];
__device__ __align__(16) __nv_bfloat16 g_w1ah[CH * CIN], g_w1al[CH * CIN];
__device__ __align__(16) __nv_bfloat16 g_w1bh[CH * CH],  g_w1bl[CH * CH];
__device__ __align__(16) __nv_bfloat16 g_wp1h[CH * CH],  g_wp1l[CH * CH];

__device__ float g_xpart[8 * NB * CH * CH];
__device__ float g_apart[8 * NB * CH * CH];
__device__ float g_x2  [NB * CH * CH];
__device__ float g_A2  [NB * CH * CH];
__device__ float g_An  [NB * CH * CH];

__device__ float g_sumA[CH], g_ssA[CH], g_sumB[CH], g_ssB[CH];
__device__ float g_s2a[CH], g_q2a[CH], g_s2b[CH], g_q2b[CH];
__device__ int   g_bar;

// ================= graph structure (one-pass bucket CSR) =================
__global__ void k_zero_deg() {
    int i = blockIdx.x * 256 + threadIdx.x;
    g_deg[i] = 0;
    if (i < 128) { g_sumA[i] = 0.f; g_ssA[i] = 0.f; g_sumB[i] = 0.f; g_ssB[i] = 0.f; }
}
__global__ void k_build(const int* __restrict__ ei) {
    int e = blockIdx.x * 256 + threadIdx.x;
    if (e < NEDGES) {
        int d = ei[NEDGES + e];
        int p = atomicAdd(&g_deg[d], 1);
        g_srcbuf[d * SLOTCAP + p] = ei[e];
    }
}

// weights transpose + bf16 split; dinv; sentinel-pad; x prescale (grid-stride)
__global__ void k_wsplit(const float* __restrict__ w1a, const float* __restrict__ w1b,
                         const float* __restrict__ wp1, const float* __restrict__ x) {
    int idx = blockIdx.x * 256 + threadIdx.x;      // 160 blocks = 40960
    if (idx < NNODES) {
        int deg = g_deg[idx];
        g_dinv[idx] = rsqrtf((float)deg + 1.0f);
        int npad = (deg + 7) & ~7;
        if (npad > SLOTCAP) npad = SLOTCAP;
        for (int p = deg; p < npad; p++) g_srcbuf[idx * SLOTCAP + p] = NNODES;
    }
    if (idx < 8192) {
        int n = idx >> 6, k = idx & 63;
        split1(w1a[k * 128 + n], g_w1ah[idx], g_w1al[idx]);
    } else if (idx < 24576) {
        int j = idx - 8192;
        int n = j >> 7, k = j & 127;
        split1(w1b[k * 128 + n], g_w1bh[j], g_w1bl[j]);
    } else if (idx < 40960) {
        int j = idx - 24576;
        int n = j >> 7, k = j & 127;
        split1(wp1[k * 128 + n], g_wp1h[j], g_wp1l[j]);
    }
    // prescale x by dinv (recompute rsqrt inline; no cross-block ordering needed)
    const int TOT = NNODES * 32;   // float2 chunks
    for (int j = idx; j < TOT; j += 160 * 256) {
        int row = j >> 5, c2 = (j & 31) * 2;
        float d = rsqrtf((float)g_deg[row] + 1.0f);
        float2 v = *reinterpret_cast<const float2*>(x + (long long)row * 64 + c2);
        v.x *= d; v.y *= d;
        *reinterpret_cast<float2*>(g_xs + (long long)row * 64 + c2) = v;
    }
}

// ================= bf16-split mma.sync GEMM =================
template<bool POOLED, bool STATS>
__global__ __launch_bounds__(256) void k_mma(
    const __nv_bfloat16* __restrict__ Ah, const __nv_bfloat16* __restrict__ Al, long long pA,
    const __nv_bfloat16* __restrict__ B1h, const __nv_bfloat16* __restrict__ B1l,
    const __nv_bfloat16* __restrict__ B2h, const __nv_bfloat16* __restrict__ B2l, long long pB,
    const float* __restrict__ bias, const float* __restrict__ rowscale,
    float* __restrict__ C1, float* __restrict__ C2, int K)
{
    extern __shared__ __align__(16) char smem[];
    __nv_bfloat16* SB = reinterpret_cast<__nv_bfloat16*>(smem);
    float* sstat = reinterpret_cast<float*>(smem + 49152);
    int t = threadIdx.x, lane = t & 31;
    int warpm = ((t >> 5) & 3) * 32, warpn = (t >> 7) * 64;

    const __nv_bfloat16 *Ahb, *Alb, *Bhb, *Blb;
    float* Cb;
    long long m0 = 0;
    if (POOLED) {
        int g = blockIdx.z;
        int half = blockIdx.y >> 3, chunk = blockIdx.y & 7;
        long long ko = (long long)g * 1024 + (long long)chunk * 128;
        Ahb = Ah + ko; Alb = Al + ko;
        Bhb = (half ? B2h : B1h) + ko;
        Blb = (half ? B2l : B1l) + ko;
        Cb = (half ? C2 : C1) + (long long)(chunk * NB + g) * (CH * CH);
    } else {
        m0 = (long long)blockIdx.x * 128;
        Ahb = Ah + m0 * pA; Alb = Al + m0 * pA;
        Bhb = B1h; Blb = B1l;
        Cb = C1 + m0 * 128;
    }
    if (STATS) { sstat[t] = 0.f; }

    uint32_t sbase = smem_u32(SB);
    int sr = t >> 1, sc = t & 1;
    uint32_t dofs = sbase + sr * 48 + sc * 16;
    CP_ASYNC16(dofs,         Ahb + (long long)sr * pA + sc * 8);
    CP_ASYNC16(dofs + 6144,  Alb + (long long)sr * pA + sc * 8);
    CP_ASYNC16(dofs + 12288, Bhb + (long long)sr * pB + sc * 8);
    CP_ASYNC16(dofs + 18432, Blb + (long long)sr * pB + sc * 8);
    CP_COMMIT();

    float c[2][8][4];
#pragma unroll
    for (int i = 0; i < 2; i++)
#pragma unroll
        for (int j = 0; j < 8; j++)
#pragma unroll
            for (int q = 0; q < 4; q++) c[i][j][q] = 0.f;

    int g8 = lane >> 2, kc = (lane & 3) * 2;
    int NT = K >> 4;
    for (int kt = 0; kt < NT; kt++) {
        if (kt + 1 < NT) {
            int k0 = (kt + 1) << 4;
            uint32_t d2 = dofs + ((kt + 1) & 1) * 24576;
            CP_ASYNC16(d2,         Ahb + (long long)sr * pA + k0 + sc * 8);
            CP_ASYNC16(d2 + 6144,  Alb + (long long)sr * pA + k0 + sc * 8);
            CP_ASYNC16(d2 + 12288, Bhb + (long long)sr * pB + k0 + sc * 8);
            CP_ASYNC16(d2 + 18432, Blb + (long long)sr * pB + k0 + sc * 8);
            CP_COMMIT();
            CP_WAIT(1);
        } else {
            CP_WAIT(0);
        }
        __syncthreads();
        const __nv_bfloat16* P = SB + (kt & 1) * 12288;
        uint32_t ah[2][4], al[2][4];
#pragma unroll
        for (int mt = 0; mt < 2; mt++) {
            int mb = warpm + mt * 16 + g8;
            ah[mt][0] = *(const uint32_t*)(P + mb * 24 + kc);
            ah[mt][1] = *(const uint32_t*)(P + (mb + 8) * 24 + kc);
            ah[mt][2] = *(const uint32_t*)(P + mb * 24 + kc + 8);
            ah[mt][3] = *(const uint32_t*)(P + (mb + 8) * 24 + kc + 8);
            al[mt][0] = *(const uint32_t*)(P + 3072 + mb * 24 + kc);
            al[mt][1] = *(const uint32_t*)(P + 3072 + (mb + 8) * 24 + kc);
            al[mt][2] = *(const uint32_t*)(P + 3072 + mb * 24 + kc + 8);
            al[mt][3] = *(const uint32_t*)(P + 3072 + (mb + 8) * 24 + kc + 8);
        }
#pragma unroll
        for (int nt = 0; nt < 8; nt++) {
            int nb = warpn + nt * 8 + g8;
            uint32_t bh0 = *(const uint32_t*)(P + 6144 + nb * 24 + kc);
            uint32_t bh1 = *(const uint32_t*)(P + 6144 + nb * 24 + kc + 8);
            uint32_t bl0 = *(const uint32_t*)(P + 9216 + nb * 24 + kc);
            uint32_t bl1 = *(const uint32_t*)(P + 9216 + nb * 24 + kc + 8);
#pragma unroll
            for (int mt = 0; mt < 2; mt++) {
                MMA_BF16(c[mt][nt], ah[mt][0], ah[mt][1], ah[mt][2], ah[mt][3], bh0, bh1);
                MMA_BF16(c[mt][nt], ah[mt][0], ah[mt][1], ah[mt][2], ah[mt][3], bl0, bl1);
                MMA_BF16(c[mt][nt], al[mt][0], al[mt][1], al[mt][2], al[mt][3], bh0, bh1);
            }
        }
        __syncthreads();
    }

    float cs[8][2], cq[8][2];
    if (STATS) {
#pragma unroll
        for (int j = 0; j < 8; j++) { cs[j][0] = cs[j][1] = 0.f; cq[j][0] = cq[j][1] = 0.f; }
    }
#pragma unroll
    for (int mt = 0; mt < 2; mt++) {
        int row = warpm + mt * 16 + g8;
        float rs0 = rowscale ? rowscale[m0 + row] : 1.f;
        float rs1 = rowscale ? rowscale[m0 + row + 8] : 1.f;
#pragma unroll
        for (int nt = 0; nt < 8; nt++) {
            int col = warpn + nt * 8 + kc;
            float b0 = bias ? bias[col] : 0.f;
            float b1 = bias ? bias[col + 1] : 0.f;
            float v00 = (c[mt][nt][0] + b0) * rs0, v01 = (c[mt][nt][1] + b1) * rs0;
            float v10 = (c[mt][nt][2] + b0) * rs1, v11 = (c[mt][nt][3] + b1) * rs1;
            *reinterpret_cast<float2*>(Cb + (long long)row * 128 + col) = make_float2(v00, v01);
            *reinterpret_cast<float2*>(Cb + (long long)(row + 8) * 128 + col) = make_float2(v10, v11);
            if (STATS) {
                cs[nt][0] += v00 + v10; cq[nt][0] += v00 * v00 + v10 * v10;
                cs[nt][1] += v01 + v11; cq[nt][1] += v01 * v01 + v11 * v11;
            }
        }
    }
    if (STATS) {
        __syncthreads();
#pragma unroll
        for (int nt = 0; nt < 8; nt++) {
            int col = warpn + nt * 8 + kc;
            atomicAdd(&sstat[col], cs[nt][0]);
            atomicAdd(&sstat[col + 1], cs[nt][1]);
            atomicAdd(&sstat[128 + col], cq[nt][0]);
            atomicAdd(&sstat[128 + col + 1], cq[nt][1]);
        }
        __syncthreads();
        if (t < 128) {
            atomicAdd(&g_sumA[t], sstat[t]);
            atomicAdd(&g_ssA[t], sstat[128 + t]);
        }
    }
}

// ================= warp-per-node aggregation (dual accumulators) =================
// MODE 0: gcn+bias (+stats, fp32 out); 1: gcn+bias+softmax (fp32 + sT bf16); 2: plain sum (tT bf16)
template<int MODE>
__global__ __launch_bounds__(256) void k_aggw(
    const float* __restrict__ in, const float* __restrict__ bias, float* __restrict__ out,
    __nv_bfloat16* __restrict__ oTh, __nv_bfloat16* __restrict__ oTl)
{
    __shared__ float sred[8][128];
    __shared__ float st[8][132];
    int t = threadIdx.x, w = t >> 5, lane = t & 31;
    int i = blockIdx.x * 8 + w;
    int e0 = i * SLOTCAP;
    int n = g_deg[i];
    int npad = (n + 7) & ~7;
    if (npad > SLOTCAP) npad = SLOTCAP;
    float4 accA = {0.f, 0.f, 0.f, 0.f}, accB = {0.f, 0.f, 0.f, 0.f};
    for (int c0 = 0; c0 < npad; c0 += 32) {
        int m = npad - c0; if (m > 32) m = 32;
        int src = (lane < m) ? g_srcbuf[e0 + c0 + lane] : 0;
        for (int kk = 0; kk < m; kk += 8) {
#pragma unroll
            for (int u = 0; u < 8; u += 2) {
                int s0 = __shfl_sync(0xffffffffu, src, kk + u);
                int s1 = __shfl_sync(0xffffffffu, src, kk + u + 1);
                float4 h0 = *reinterpret_cast<const float4*>(in + (long long)s0 * 128 + lane * 4);
                float4 h1 = *reinterpret_cast<const float4*>(in + (long long)s1 * 128 + lane * 4);
                accA.x += h0.x; accA.y += h0.y; accA.z += h0.z; accA.w += h0.w;
                accB.x += h1.x; accB.y += h1.y; accB.z += h1.z; accB.w += h1.w;
            }
        }
    }
    float ax = accA.x + accB.x, ay = accA.y + accB.y;
    float az = accA.z + accB.z, aw = accA.w + accB.w;
    float di = g_dinv[i];
    float vx, vy, vz, vw;
    if (MODE != 2) {
        float4 hv = *reinterpret_cast<const float4*>(in + (long long)i * 128 + lane * 4);
        vx = di * (ax + hv.x) + bias[lane * 4 + 0];
        vy = di * (ay + hv.y) + bias[lane * 4 + 1];
        vz = di * (az + hv.z) + bias[lane * 4 + 2];
        vw = di * (aw + hv.w) + bias[lane * 4 + 3];
    } else {
        vx = ax; vy = ay; vz = az; vw = aw;
    }
    if (MODE == 1) {
        float mx = fmaxf(fmaxf(vx, vy), fmaxf(vz, vw));
#pragma unroll
        for (int o = 16; o; o >>= 1) mx = fmaxf(mx, __shfl_xor_sync(0xffffffffu, mx, o));
        vx = __expf(vx - mx); vy = __expf(vy - mx); vz = __expf(vz - mx); vw = __expf(vw - mx);
        float sm = vx + vy + vz + vw;
#pragma unroll
        for (int o = 16; o; o >>= 1) sm += __shfl_xor_sync(0xffffffffu, sm, o);
        float inv = 1.f / sm;
        vx *= inv; vy *= inv; vz *= inv; vw *= inv;
    }
    if (MODE != 2) {
        float4 o4 = { vx, vy, vz, vw };
        *reinterpret_cast<float4*>(out + (long long)i * 128 + lane * 4) = o4;
    }
    if (MODE == 0) {
        sred[w][lane * 4 + 0] = vx; sred[w][lane * 4 + 1] = vy;
        sred[w][lane * 4 + 2] = vz; sred[w][lane * 4 + 3] = vw;
        __syncthreads();
        if (t < 128) {
            float s = 0.f, q = 0.f;
#pragma unroll
            for (int ww = 0; ww < 8; ww++) { float v = sred[ww][t]; s += v; q += v * v; }
            atomicAdd(&g_sumB[t], s);
            atomicAdd(&g_ssB[t], q);
        }
    } else {
        st[w][lane * 4 + 0] = vx; st[w][lane * 4 + 1] = vy;
        st[w][lane * 4 + 2] = vz; st[w][lane * 4 + 3] = vw;
        __syncthreads();
        if (t < 128) {
            int c = t;
            float v0 = st[0][c], v1 = st[1][c], v2 = st[2][c], v3 = st[3][c];
            float v4 = st[4][c], v5 = st[5][c], v6 = st[6][c], v7 = st[7][c];
            long long o = (long long)c * NNODES + blockIdx.x * 8;
            uint4 hv, lv;
            hv.x = pack_hi(v0, v1); hv.y = pack_hi(v2, v3);
            hv.z = pack_hi(v4, v5); hv.w = pack_hi(v6, v7);
            lv.x = pack_lo(v0, v1); lv.y = pack_lo(v2, v3);
            lv.z = pack_lo(v4, v5); lv.w = pack_lo(v6, v7);
            *reinterpret_cast<uint4*>(oTh + o) = hv;
            *reinterpret_cast<uint4*>(oTl + o) = lv;
        }
    }
}

// agg of prescaled x (64 ch) -> row-major bf16 hi/lo (dual accumulators)
__global__ __launch_bounds__(256) void k_aggx() {
    int t = threadIdx.x, w = t >> 5, lane = t & 31;
    int i = blockIdx.x * 8 + w;
    int e0 = i * SLOTCAP;
    int n = g_deg[i];
    int npad = (n + 7) & ~7;
    if (npad > SLOTCAP) npad = SLOTCAP;
    float2 accA = {0.f, 0.f}, accB = {0.f, 0.f};
    for (int c0 = 0; c0 < npad; c0 += 32) {
        int m = npad - c0; if (m > 32) m = 32;
        int src = (lane < m) ? g_srcbuf[e0 + c0 + lane] : 0;
        for (int kk = 0; kk < m; kk += 8) {
#pragma unroll
            for (int u = 0; u < 8; u += 2) {
                int s0 = __shfl_sync(0xffffffffu, src, kk + u);
                int s1 = __shfl_sync(0xffffffffu, src, kk + u + 1);
                float2 h0 = *reinterpret_cast<const float2*>(g_xs + (long long)s0 * 64 + lane * 2);
                float2 h1 = *reinterpret_cast<const float2*>(g_xs + (long long)s1 * 64 + lane * 2);
                accA.x += h0.x; accA.y += h0.y;
                accB.x += h1.x; accB.y += h1.y;
            }
        }
    }
    float di = g_dinv[i];
    float2 hv = *reinterpret_cast<const float2*>(g_xs + (long long)i * 64 + lane * 2);
    float ax = di * (accA.x + accB.x + hv.x);
    float ay = di * (accA.y + accB.y + hv.y);
    long long o = (long long)i * 64 + lane * 2;
    *reinterpret_cast<uint32_t*>(g_axh + o) = pack_hi(ax, ay);
    *reinterpret_cast<uint32_t*>(g_axl + o) = pack_lo(ax, ay);
}

// ================= BN+SiLU(+res); fp32 h (opt), row bf16, trans bf16 (opt) =================
template<bool RES, bool WH, bool WT>
__global__ __launch_bounds__(256) void k_bn(
    const float* __restrict__ y, const float* __restrict__ res, float* __restrict__ h,
    __nv_bfloat16* __restrict__ rh, __nv_bfloat16* __restrict__ rl,
    __nv_bfloat16* __restrict__ th, __nv_bfloat16* __restrict__ tl,
    const float* __restrict__ gw, const float* __restrict__ be,
    const float* __restrict__ sumArr, const float* __restrict__ ssArr)
{
    __shared__ float tile[32][33];
    __shared__ float sc[32], sh[32];
    int t = threadIdx.x;
    int n0 = blockIdx.x * 32, c0 = blockIdx.y * 32;
    if (t < 32) {
        int c = c0 + t;
        float m = sumArr[c] * (1.f / NNODES);
        float var = ssArr[c] * (1.f / NNODES) - m * m;
        float s = gw[c] * rsqrtf(var + 1e-5f);
        sc[t] = s;
        sh[t] = be[c] - s * m;
    }
    __syncthreads();
    int nl = t >> 3, cg = t & 7;
    long long idx = (long long)(n0 + nl) * 128 + c0 + cg * 4;
    float4 v = *reinterpret_cast<const float4*>(y + idx);
    float o0, o1, o2, o3;
    {
        float a;
        a = sc[cg * 4 + 0] * v.x + sh[cg * 4 + 0]; o0 = a / (1.f + __expf(-a));
        a = sc[cg * 4 + 1] * v.y + sh[cg * 4 + 1]; o1 = a / (1.f + __expf(-a));
        a = sc[cg * 4 + 2] * v.z + sh[cg * 4 + 2]; o2 = a / (1.f + __expf(-a));
        a = sc[cg * 4 + 3] * v.w + sh[cg * 4 + 3]; o3 = a / (1.f + __expf(-a));
    }
    if (RES) {
        float4 r = *reinterpret_cast<const float4*>(res + idx);
        o0 += r.x; o1 += r.y; o2 += r.z; o3 += r.w;
    }
    if (WH) {
        float4 ov = { o0, o1, o2, o3 };
        *reinterpret_cast<float4*>(h + idx) = ov;
    }
    {
        uint2 hv, lv;
        hv.x = pack_hi(o0, o1); hv.y = pack_hi(o2, o3);
        lv.x = pack_lo(o0, o1); lv.y = pack_lo(o2, o3);
        *reinterpret_cast<uint2*>(rh + idx) = hv;
        *reinterpret_cast<uint2*>(rl + idx) = lv;
    }
    if (WT) {
        tile[nl][cg * 4 + 0] = o0; tile[nl][cg * 4 + 1] = o1;
        tile[nl][cg * 4 + 2] = o2; tile[nl][cg * 4 + 3] = o3;
        __syncthreads();
        int cc = t >> 3, g = t & 7;
        float w0 = tile[g * 4 + 0][cc], w1 = tile[g * 4 + 1][cc];
        float w2 = tile[g * 4 + 2][cc], w3 = tile[g * 4 + 3][cc];
        long long o = (long long)(c0 + cc) * NNODES + n0 + g * 4;
        uint2 hv, lv;
        hv.x = pack_hi(w0, w1); hv.y = pack_hi(w2, w3);
        lv.x = pack_lo(w0, w1); lv.y = pack_lo(w2, w3);
        *reinterpret_cast<uint2*>(th + o) = hv;
        *reinterpret_cast<uint2*>(tl + o) = lv;
    }
}

// ================= reduce partials + dinv2 + An; reset stack-2 state =================
__global__ __launch_bounds__(256) void k_reduce_an() {
    int b = blockIdx.x, t = threadIdx.x;
    if (b == 0 && t < 128) {
        g_s2a[t] = 0.f; g_q2a[t] = 0.f; g_s2b[t] = 0.f; g_q2b[t] = 0.f;
        if (t == 0) g_bar = 0;
    }
    const long long PS = (long long)NB * CH * CH;
    const long long BO = (long long)b * CH * CH;
    __shared__ float sd[128];
    for (int idx = t; idx < CH * CH; idx += 256) {
        float s = 0.f;
#pragma unroll
        for (int p = 0; p < 8; p++) s += g_xpart[p * PS + BO + idx];
        g_x2[BO + idx] = s;
    }
    int w = t >> 5, lane = t & 31;
    for (int r = w; r < 128; r += 8) {
        float rsum = 0.f;
#pragma unroll
        for (int q = 0; q < 4; q++) {
            int idx = r * 128 + lane + q * 32;
            float s = 0.f;
#pragma unroll
            for (int p = 0; p < 8; p++) s += g_apart[p * PS + BO + idx];
            g_A2[BO + idx] = s;
            rsum += s;
        }
#pragma unroll
        for (int o = 16; o; o >>= 1) rsum += __shfl_down_sync(0xffffffffu, rsum, o);
        if (lane == 0) sd[r] = rsqrtf(rsum + 1.0f);
    }
    __syncthreads();
    for (int idx = t; idx < CH * CH; idx += 256) {
        int i = idx >> 7, j = idx & 127;
        float v = g_A2[BO + idx] + (i == j ? 1.f : 0.f);
        g_An[BO + idx] = sd[i] * v * sd[j];
    }
}

// ================= fused stack-2 (FFMA2, 32 blocks, grid barrier) =================
__device__ __forceinline__ void gridbar(int target) {
    __syncthreads();
    __threadfence();
    if (threadIdx.x == 0) {
        atomicAdd(&g_bar, 1);
        while (*(volatile int*)&g_bar < target) __nanosleep(64);
    }
    __syncthreads();
    __threadfence();
}

__device__ __forceinline__ void gemm_sm128(const float* __restrict__ P, const float* __restrict__ Q,
                                           unsigned long long acc2[8][4], int tx, int ty)
{
#pragma unroll
    for (int i = 0; i < 8; i++)
#pragma unroll
        for (int j = 0; j < 4; j++) acc2[i][j] = 0ull;
#pragma unroll 2
    for (int k = 0; k < 128; k++) {
        float a[8];
#pragma unroll
        for (int i = 0; i < 8; i++) a[i] = P[(ty * 8 + i) * 128 + k];
        const unsigned long long* Qp =
            reinterpret_cast<const unsigned long long*>(&Q[k * 128 + tx * 8]);
        unsigned long long b0 = Qp[0], b1 = Qp[1], b2 = Qp[2], b3 = Qp[3];
#pragma unroll
        for (int i = 0; i < 8; i++) {
            unsigned long long ad = dup_f32(a[i]);
            ffma2(acc2[i][0], ad, b0);
            ffma2(acc2[i][1], ad, b1);
            ffma2(acc2[i][2], ad, b2);
            ffma2(acc2[i][3], ad, b3);
        }
    }
}

__global__ __launch_bounds__(256) void k_stack2(
    const float* __restrict__ w2a, const float* __restrict__ b2a,
    const float* __restrict__ g2a, const float* __restrict__ be2a,
    const float* __restrict__ w2b, const float* __restrict__ b2b,
    const float* __restrict__ g2b, const float* __restrict__ be2b,
    const float* __restrict__ wl, const float* __restrict__ bl,
    float* __restrict__ out, int out_size)
{
    extern __shared__ __align__(16) float sm2[];
    float* AN = sm2;
    float* XB = sm2 + 16384;
    float* WB = sm2 + 32768;
    __shared__ float red[2048];
    __shared__ float gv[128];
    __shared__ float lg[10];
    __shared__ float lse;
    int b = blockIdx.x, t = threadIdx.x, tx = t & 15, ty = t >> 4;
    const float INVN = 1.f / (NB * CH);

    {
        const float4* pAn = (const float4*)(g_An + (long long)b * 16384);
        const float4* pX2 = (const float4*)(g_x2 + (long long)b * 16384);
        const float4* pWa = (const float4*)w2a;
        float4* An4 = (float4*)AN; float4* X4 = (float4*)XB; float4* W4 = (float4*)WB;
        for (int i = t; i < 4096; i += 256) { An4[i] = pAn[i]; X4[i] = pX2[i]; W4[i] = pWa[i]; }
    }
    __syncthreads();

    unsigned long long acc2[8][4];
    float cs[8], cq[8];

    gemm_sm128(XB, WB, acc2, tx, ty);
    __syncthreads();
#pragma unroll
    for (int i = 0; i < 8; i++)
#pragma unroll
        for (int j = 0; j < 4; j++) {
            float2 p = u2f(acc2[i][j]);
            XB[(ty * 8 + i) * 128 + tx * 8 + 2 * j] = p.x;
            XB[(ty * 8 + i) * 128 + tx * 8 + 2 * j + 1] = p.y;
        }
    __syncthreads();

    gemm_sm128(AN, XB, acc2, tx, ty);
    __syncthreads();
#pragma unroll
    for (int j = 0; j < 8; j++) { cs[j] = 0.f; cq[j] = 0.f; }
#pragma unroll
    for (int i = 0; i < 8; i++)
#pragma unroll
        for (int j = 0; j < 4; j++) {
            float2 p = u2f(acc2[i][j]);
            float v0 = p.x + b2a[tx * 8 + 2 * j];
            float v1 = p.y + b2a[tx * 8 + 2 * j + 1];
            WB[(ty * 8 + i) * 128 + tx * 8 + 2 * j] = v0;
            WB[(ty * 8 + i) * 128 + tx * 8 + 2 * j + 1] = v1;
            cs[2 * j] += v0; cq[2 * j] += v0 * v0;
            cs[2 * j + 1] += v1; cq[2 * j + 1] += v1 * v1;
        }
#pragma unroll
    for (int j = 0; j < 8; j++) red[ty * 128 + tx * 8 + j] = cs[j];
    __syncthreads();
    if (t < 128) { float s = 0.f; for (int g = 0; g < 16; g++) s += red[g * 128 + t]; atomicAdd(&g_s2a[t], s); }
    __syncthreads();
#pragma unroll
    for (int j = 0; j < 8; j++) red[ty * 128 + tx * 8 + j] = cq[j];
    __syncthreads();
    if (t < 128) { float s = 0.f; for (int g = 0; g < 16; g++) s += red[g * 128 + t]; atomicAdd(&g_q2a[t], s); }

    gridbar(NB);

    float scv[8], shv[8];
#pragma unroll
    for (int j = 0; j < 8; j++) {
        int c = tx * 8 + j;
        float m = g_s2a[c] * INVN;
        float var = g_q2a[c] * INVN - m * m;
        float s = g2a[c] * rsqrtf(var + 1e-5f);
        scv[j] = s; shv[j] = be2a[c] - s * m;
    }
#pragma unroll
    for (int i = 0; i < 8; i++)
#pragma unroll
        for (int j = 0; j < 8; j++) {
            float v = WB[(ty * 8 + i) * 128 + tx * 8 + j];
            v = scv[j] * v + shv[j];
            v = v / (1.f + __expf(-v));
            XB[(ty * 8 + i) * 128 + tx * 8 + j] = v;
        }
    __syncthreads();

    {
        const float4* pWb = (const float4*)w2b;
        float4* W4 = (float4*)WB;
        for (int i = t; i < 4096; i += 256) W4[i] = pWb[i];
    }
    __syncthreads();

    gemm_sm128(XB, WB, acc2, tx, ty);
    __syncthreads();
#pragma unroll
    for (int i = 0; i < 8; i++)
#pragma unroll
        for (int j = 0; j < 4; j++) {
            float2 p = u2f(acc2[i][j]);
            WB[(ty * 8 + i) * 128 + tx * 8 + 2 * j] = p.x;
            WB[(ty * 8 + i) * 128 + tx * 8 + 2 * j + 1] = p.y;
        }
    __syncthreads();

    gemm_sm128(AN, WB, acc2, tx, ty);
#pragma unroll
    for (int j = 0; j < 8; j++) { cs[j] = 0.f; cq[j] = 0.f; }
#pragma unroll
    for (int i = 0; i < 8; i++)
#pragma unroll
        for (int j = 0; j < 4; j++) {
            float2 p = u2f(acc2[i][j]);
            float v0 = p.x + b2b[tx * 8 + 2 * j];
            float v1 = p.y + b2b[tx * 8 + 2 * j + 1];
            cs[2 * j] += v0; cq[2 * j] += v0 * v0;
            cs[2 * j + 1] += v1; cq[2 * j + 1] += v1 * v1;
        }
    __syncthreads();
#pragma unroll
    for (int j = 0; j < 8; j++) red[ty * 128 + tx * 8 + j] = cs[j];
    __syncthreads();
    if (t < 128) { float s = 0.f; for (int g = 0; g < 16; g++) s += red[g * 128 + t]; atomicAdd(&g_s2b[t], s); }
    __syncthreads();
#pragma unroll
    for (int j = 0; j < 8; j++) red[ty * 128 + tx * 8 + j] = cq[j];
    __syncthreads();
    if (t < 128) { float s = 0.f; for (int g = 0; g < 16; g++) s += red[g * 128 + t]; atomicAdd(&g_q2b[t], s); }

    gridbar(2 * NB);

#pragma unroll
    for (int j = 0; j < 8; j++) {
        int c = tx * 8 + j;
        float m = g_s2b[c] * INVN;
        float var = g_q2b[c] * INVN - m * m;
        float s = g2b[c] * rsqrtf(var + 1e-5f);
        scv[j] = s; shv[j] = be2b[c] - s * m;
    }
    float colsum[8];
#pragma unroll
    for (int j = 0; j < 8; j++) colsum[j] = 0.f;
#pragma unroll
    for (int i = 0; i < 8; i++)
#pragma unroll
        for (int j = 0; j < 4; j++) {
            float2 p = u2f(acc2[i][j]);
            float v0 = scv[2 * j] * (p.x + b2b[tx * 8 + 2 * j]) + shv[2 * j];
            float v1 = scv[2 * j + 1] * (p.y + b2b[tx * 8 + 2 * j + 1]) + shv[2 * j + 1];
            v0 = v0 / (1.f + __expf(-v0));
            v1 = v1 / (1.f + __expf(-v1));
            v0 += XB[(ty * 8 + i) * 128 + tx * 8 + 2 * j];
            v1 += XB[(ty * 8 + i) * 128 + tx * 8 + 2 * j + 1];
            colsum[2 * j] += v0;
            colsum[2 * j + 1] += v1;
        }
    __syncthreads();
#pragma unroll
    for (int j = 0; j < 8; j++) red[ty * 128 + tx * 8 + j] = colsum[j];
    __syncthreads();
    if (t < 128) {
        float s = 0.f;
        for (int g = 0; g < 16; g++) s += red[g * 128 + t];
        gv[t] = s * (1.f / 32.f);
    }
    __syncthreads();
    if (t < 10) {
        float a = bl[t];
        for (int k = 0; k < 128; k++) a += gv[k] * wl[k * 10 + t];
        lg[t] = a;
    }
    __syncthreads();
    if (t == 0) {
        float mx = -1e30f;
        for (int j = 0; j < 10; j++) mx = fmaxf(mx, lg[j]);
        float se = 0.f;
        for (int j = 0; j < 10; j++) se += expf(lg[j] - mx);
        lse = mx + logf(se);
    }
    __syncthreads();
    if (t < 10) {
        int o = b * 10 + t;
        if (o < out_size) out[o] = lg[t] - lse;
    }
    if (b == 0) {
        for (int idx = NB * 10 + t; idx < out_size; idx += 256) out[idx] = 0.f;
    }
}

// ================= host orchestration =================
extern "C" void kernel_launch(void* const* d_in, const int* in_sizes, int n_in,
                              void* d_out, int out_size) {
    const float* x    = (const float*)d_in[0];
    const int*   ei   = (const int*)  d_in[1];
    const float* w1a  = (const float*)d_in[4];
    const float* b1a  = (const float*)d_in[5];
    const float* g1a  = (const float*)d_in[6];
    const float* be1a = (const float*)d_in[7];
    const float* w1b  = (const float*)d_in[8];
    const float* b1b  = (const float*)d_in[9];
    const float* g1b  = (const float*)d_in[10];
    const float* be1b = (const float*)d_in[11];
    const float* wp1  = (const float*)d_in[12];
    const float* bp1  = (const float*)d_in[13];
    const float* w2a  = (const float*)d_in[14];
    const float* b2a  = (const float*)d_in[15];
    const float* g2a  = (const float*)d_in[16];
    const float* be2a = (const float*)d_in[17];
    const float* w2b  = (const float*)d_in[18];
    const float* b2b  = (const float*)d_in[19];
    const float* g2b  = (const float*)d_in[20];
    const float* be2b = (const float*)d_in[21];
    const float* wl   = (const float*)d_in[24];
    const float* bl   = (const float*)d_in[25];
    float* outp = (float*)d_out;
    (void)n_in; (void)in_sizes;

    float *p_lin, *p_y, *p_h, *p_s, *p_xpart, *p_apart;
    float *p_sumA, *p_ssA, *p_sumB, *p_ssB, *p_dinv;
    __nv_bfloat16 *p_axh, *p_axl, *p_hah, *p_hal, *p_hbh, *p_hbl;
    __nv_bfloat16 *p_hTh, *p_hTl, *p_sTh, *p_sTl, *p_tTh, *p_tTl;
    __nv_bfloat16 *p_w1ah, *p_w1al, *p_w1bh, *p_w1bl, *p_wp1h, *p_wp1l;
    cudaGetSymbolAddress((void**)&p_lin,   g_lin);
    cudaGetSymbolAddress((void**)&p_y,     g_y);
    cudaGetSymbolAddress((void**)&p_h,     g_h);
    cudaGetSymbolAddress((void**)&p_s,     g_s);
    cudaGetSymbolAddress((void**)&p_xpart, g_xpart);
    cudaGetSymbolAddress((void**)&p_apart, g_apart);
    cudaGetSymbolAddress((void**)&p_sumA,  g_sumA);
    cudaGetSymbolAddress((void**)&p_ssA,   g_ssA);
    cudaGetSymbolAddress((void**)&p_sumB,  g_sumB);
    cudaGetSymbolAddress((void**)&p_ssB,   g_ssB);
    cudaGetSymbolAddress((void**)&p_dinv,  g_dinv);
    cudaGetSymbolAddress((void**)&p_axh,   g_axh);
    cudaGetSymbolAddress((void**)&p_axl,   g_axl);
    cudaGetSymbolAddress((void**)&p_hah,   g_hah);
    cudaGetSymbolAddress((void**)&p_hal,   g_hal);
    cudaGetSymbolAddress((void**)&p_hbh,   g_hbh);
    cudaGetSymbolAddress((void**)&p_hbl,   g_hbl);
    cudaGetSymbolAddress((void**)&p_hTh,   g_hTh);
    cudaGetSymbolAddress((void**)&p_hTl,   g_hTl);
    cudaGetSymbolAddress((void**)&p_sTh,   g_sTh);
    cudaGetSymbolAddress((void**)&p_sTl,   g_sTl);
    cudaGetSymbolAddress((void**)&p_tTh,   g_tTh);
    cudaGetSymbolAddress((void**)&p_tTl,   g_tTl);
    cudaGetSymbolAddress((void**)&p_w1ah,  g_w1ah);
    cudaGetSymbolAddress((void**)&p_w1al,  g_w1al);
    cudaGetSymbolAddress((void**)&p_w1bh,  g_w1bh);
    cudaGetSymbolAddress((void**)&p_w1bl,  g_w1bl);
    cudaGetSymbolAddress((void**)&p_wp1h,  g_wp1h);
    cudaGetSymbolAddress((void**)&p_wp1l,  g_wp1l);

    static bool attrDone = false;
    if (!attrDone) {
        cudaFuncSetAttribute(k_stack2, cudaFuncAttributeMaxDynamicSharedMemorySize, 196608);
        cudaFuncSetAttribute(k_mma<false, true>,  cudaFuncAttributeMaxDynamicSharedMemorySize, 50176);
        cudaFuncSetAttribute(k_mma<false, false>, cudaFuncAttributeMaxDynamicSharedMemorySize, 50176);
        cudaFuncSetAttribute(k_mma<true, false>,  cudaFuncAttributeMaxDynamicSharedMemorySize, 50176);
        attrDone = true;
    }

    // graph structure (one-pass CSR) + pad + weight split + dinv + x prescale (fused)
    k_zero_deg<<<NNODES / 256, 256>>>();
    k_build<<<NEDGES / 256, 256>>>(ei);
    k_wsplit<<<160, 256>>>(w1a, w1b, wp1, x);

    // stack 1, layer a
    k_aggx<<<NNODES / 8, 256>>>();
    k_mma<false, true><<<256, 256, 50176>>>(p_axh, p_axl, 64,
                                            p_w1ah, p_w1al, nullptr, nullptr, 64,
                                            b1a, nullptr, p_y, nullptr, 64);
    k_bn<false, true, false><<<dim3(NNODES / 32, 4), 256>>>(
        p_y, nullptr, p_h, p_hah, p_hal, nullptr, nullptr, g1a, be1a, p_sumA, p_ssA);

    // stack 1, layer b (residual); GEMM output prescaled by dinv
    k_mma<false, false><<<256, 256, 50176>>>(p_hah, p_hal, 128,
                                             p_w1bh, p_w1bl, nullptr, nullptr, 128,
                                             nullptr, p_dinv, p_lin, nullptr, 128);
    k_aggw<0><<<NNODES / 8, 256>>>(p_lin, b1b, p_y, nullptr, nullptr);
    k_bn<true, false, true><<<dim3(NNODES / 32, 4), 256>>>(
        p_y, p_h, nullptr, p_hbh, p_hbl, p_hTh, p_hTl, g1b, be1b, p_sumB, p_ssB);

    // pooling 1; GEMM output prescaled by dinv
    k_mma<false, false><<<256, 256, 50176>>>(p_hbh, p_hbl, 128,
                                             p_wp1h, p_wp1l, nullptr, nullptr, 128,
                                             nullptr, p_dinv, p_lin, nullptr, 128);
    k_aggw<1><<<NNODES / 8, 256>>>(p_lin, bp1, p_s, p_sTh, p_sTl);
    k_aggw<2><<<NNODES / 8, 256>>>(p_s, nullptr, nullptr, p_tTh, p_tTl);

    // pooled einsums + reduce/An
    k_mma<true, false><<<dim3(1, 16, NB), 256, 50176>>>(p_sTh, p_sTl, NNODES,
                                                        p_hTh, p_hTl, p_tTh, p_tTl, NNODES,
                                                        nullptr, nullptr, p_xpart, p_apart, 128);
    k_reduce_an<<<NB, 256>>>();

    // fused stack 2 (FFMA2) + head
    k_stack2<<<NB, 256, 196608>>>(w2a, b2a, g2a, be2a, w2b, b2b, g2b, be2b, wl, bl, outp, out_size);
}

// round 12
// speedup vs baseline: 1.0334x; 1.0334x over previous
#include <cuda_runtime.h>
#include <cuda_bf16.h>
#include <math.h>
#include <stdint.h>

#define NNODES 32768
#define NEDGES 524288
#define NB     32
#define NPG    1024
#define CH     128
#define CIN    64
#define SLOTCAP 72

// ================= helpers =================
__device__ __forceinline__ uint32_t smem_u32(const void* p) {
    uint32_t a;
    asm("{ .reg .u64 t; cvta.to.shared.u64 t, %1; cvt.u32.u64 %0, t; }" : "=r"(a) : "l"(p));
    return a;
}
__device__ __forceinline__ void ffma2(unsigned long long& d, unsigned long long a, unsigned long long b) {
    asm("fma.rn.f32x2 %0, %1, %2, %0;" : "+l"(d) : "l"(a), "l"(b));
}
__device__ __forceinline__ unsigned long long dup_f32(float v) {
    unsigned long long r;
    asm("mov.b64 %0, {%1, %1};" : "=l"(r) : "f"(v));
    return r;
}
__device__ __forceinline__ float2 u2f(unsigned long long v) {
    float2 f;
    asm("mov.b64 {%0, %1}, %2;" : "=f"(f.x), "=f"(f.y) : "l"(v));
    return f;
}
#define CP_ASYNC16(dst, src) asm volatile("cp.async.ca.shared.global [%0], [%1], 16;" :: "r"(dst), "l"(src))
#define CP_COMMIT()          asm volatile("cp.async.commit_group;" ::: "memory")
#define CP_WAIT(n)           asm volatile("cp.async.wait_group %0;" :: "n"(n) : "memory")

#define MMA_BF16(cf, a0, a1, a2, a3, b0, b1) \
    asm volatile("mma.sync.aligned.m16n8k16.row.col.f32.bf16.bf16.f32 " \
        "{%0,%1,%2,%3},{%4,%5,%6,%7},{%8,%9},{%0,%1,%2,%3};" \
        : "+f"((cf)[0]), "+f"((cf)[1]), "+f"((cf)[2]), "+f"((cf)[3]) \
        : "r"(a0), "r"(a1), "r"(a2), "r"(a3), "r"(b0), "r"(b1))

__device__ __forceinline__ uint32_t pack_hi(float a, float b) {
    __nv_bfloat162 h;
    h.x = __float2bfloat16_rn(a); h.y = __float2bfloat16_rn(b);
    return *reinterpret_cast<uint32_t*>(&h);
}
__device__ __forceinline__ uint32_t pack_lo(float a, float b) {
    __nv_bfloat16 ha = __float2bfloat16_rn(a), hb = __float2bfloat16_rn(b);
    __nv_bfloat162 l;
    l.x = __float2bfloat16_rn(a - __bfloat162float(ha));
    l.y = __float2bfloat16_rn(b - __bfloat162float(hb));
    return *reinterpret_cast<uint32_t*>(&l);
}
__device__ __forceinline__ void split1(float v, __nv_bfloat16& h, __nv_bfloat16& l) {
    h = __float2bfloat16_rn(v);
    l = __float2bfloat16_rn(v - __bfloat162float(h));
}

// ================= device scratch =================
// Gather sources have 8 extra rows; row NNODES is never written => stays zero
// (sentinel target for padded CSR slots).
__device__ int   g_deg[NNODES];
__device__ int   g_srcbuf[NNODES * SLOTCAP];
__device__ float g_dinv[NNODES];

__device__ float g_xs [(NNODES + 8) * CIN];   // dinv-prescaled x
__device__ float g_lin[(NNODES + 8) * CH];    // dinv-prescaled GEMM out
__device__ float g_s  [(NNODES + 8) * CH];
__device__ float g_y  [NNODES * CH];
__device__ float g_h  [NNODES * CH];

__device__ __align__(16) __nv_bfloat16 g_axh[NNODES * CIN], g_axl[NNODES * CIN];
__device__ __align__(16) __nv_bfloat16 g_hah[NNODES * CH],  g_hal[NNODES * CH];
__device__ __align__(16) __nv_bfloat16 g_hbh[NNODES * CH],  g_hbl[NNODES * CH];
__device__ __align__(16) __nv_bfloat16 g_hTh[CH * NNODES],  g_hTl[CH * NNODES];
__device__ __align__(16) __nv_bfloat16 g_sTh[CH * NNODES],  g_sTl[CH * NNODES];
__device__ __align__(16) __nv_bfloat16 g_tTh[CH * NNODES],  g_tTl[CH * NNODES];
__device__ __align__(16) __nv_bfloat16 g_w1ah[CH * CIN], g_w1al[CH * CIN];
__device__ __align__(16) __nv_bfloat16 g_w1bh[CH * CH],  g_w1bl[CH * CH];
__device__ __align__(16) __nv_bfloat16 g_wp1h[CH * CH],  g_wp1l[CH * CH];

__device__ float g_xpart[8 * NB * CH * CH];
__device__ float g_apart[8 * NB * CH * CH];
__device__ float g_x2  [NB * CH * CH];
__device__ float g_A2  [NB * CH * CH];
__device__ float g_An  [NB * CH * CH];

__device__ float g_sumA[CH], g_ssA[CH], g_sumB[CH], g_ssB[CH];
__device__ float g_s2a[CH], g_q2a[CH], g_s2b[CH], g_q2b[CH];
__device__ int   g_bar;

// ================= graph structure (one-pass bucket CSR) =================
__global__ void k_zero_deg() {
    int i = blockIdx.x * 256 + threadIdx.x;
    g_deg[i] = 0;
    if (i < 128) { g_sumA[i] = 0.f; g_ssA[i] = 0.f; g_sumB[i] = 0.f; g_ssB[i] = 0.f; }
}
__global__ void k_build(const int* __restrict__ ei) {
    int e = blockIdx.x * 256 + threadIdx.x;
    if (e < NEDGES) {
        int d = ei[NEDGES + e];
        int p = atomicAdd(&g_deg[d], 1);
        g_srcbuf[d * SLOTCAP + p] = ei[e];
    }
}

// weights transpose + bf16 split; dinv; sentinel-pad (after k_build)
__global__ void k_wsplit(const float* __restrict__ w1a, const float* __restrict__ w1b,
                         const float* __restrict__ wp1) {
    int idx = blockIdx.x * 256 + threadIdx.x;      // 160 blocks = 40960
    if (idx < NNODES) {
        int deg = g_deg[idx];
        g_dinv[idx] = rsqrtf((float)deg + 1.0f);
        int npad = (deg + 7) & ~7;
        if (npad > SLOTCAP) npad = SLOTCAP;
        for (int p = deg; p < npad; p++) g_srcbuf[idx * SLOTCAP + p] = NNODES;
    }
    if (idx < 8192) {
        int n = idx >> 6, k = idx & 63;
        split1(w1a[k * 128 + n], g_w1ah[idx], g_w1al[idx]);
    } else if (idx < 24576) {
        int j = idx - 8192;
        int n = j >> 7, k = j & 127;
        split1(w1b[k * 128 + n], g_w1bh[j], g_w1bl[j]);
    } else if (idx < 40960) {
        int j = idx - 24576;
        int n = j >> 7, k = j & 127;
        split1(wp1[k * 128 + n], g_wp1h[j], g_wp1l[j]);
    }
}

// prescale x by dinv -> g_xs (dedicated wide launch; R10-proven)
__global__ __launch_bounds__(256) void k_xscale(const float* __restrict__ x) {
    int t = blockIdx.x * 256 + threadIdx.x;        // NNODES*32 threads
    int row = t >> 5, c2 = (t & 31) * 2;
    float d = g_dinv[row];
    float2 v = *reinterpret_cast<const float2*>(x + (long long)row * 64 + c2);
    v.x *= d; v.y *= d;
    *reinterpret_cast<float2*>(g_xs + (long long)row * 64 + c2) = v;
}

// ================= bf16-split mma.sync GEMM =================
template<bool POOLED, bool STATS>
__global__ __launch_bounds__(256) void k_mma(
    const __nv_bfloat16* __restrict__ Ah, const __nv_bfloat16* __restrict__ Al, long long pA,
    const __nv_bfloat16* __restrict__ B1h, const __nv_bfloat16* __restrict__ B1l,
    const __nv_bfloat16* __restrict__ B2h, const __nv_bfloat16* __restrict__ B2l, long long pB,
    const float* __restrict__ bias, const float* __restrict__ rowscale,
    float* __restrict__ C1, float* __restrict__ C2, int K)
{
    extern __shared__ __align__(16) char smem[];
    __nv_bfloat16* SB = reinterpret_cast<__nv_bfloat16*>(smem);
    float* sstat = reinterpret_cast<float*>(smem + 49152);
    int t = threadIdx.x, lane = t & 31;
    int warpm = ((t >> 5) & 3) * 32, warpn = (t >> 7) * 64;

    const __nv_bfloat16 *Ahb, *Alb, *Bhb, *Blb;
    float* Cb;
    long long m0 = 0;
    if (POOLED) {
        int g = blockIdx.z;
        int half = blockIdx.y >> 3, chunk = blockIdx.y & 7;
        long long ko = (long long)g * 1024 + (long long)chunk * 128;
        Ahb = Ah + ko; Alb = Al + ko;
        Bhb = (half ? B2h : B1h) + ko;
        Blb = (half ? B2l : B1l) + ko;
        Cb = (half ? C2 : C1) + (long long)(chunk * NB + g) * (CH * CH);
    } else {
        m0 = (long long)blockIdx.x * 128;
        Ahb = Ah + m0 * pA; Alb = Al + m0 * pA;
        Bhb = B1h; Blb = B1l;
        Cb = C1 + m0 * 128;
    }
    if (STATS) { sstat[t] = 0.f; }

    uint32_t sbase = smem_u32(SB);
    int sr = t >> 1, sc = t & 1;
    uint32_t dofs = sbase + sr * 48 + sc * 16;
    CP_ASYNC16(dofs,         Ahb + (long long)sr * pA + sc * 8);
    CP_ASYNC16(dofs + 6144,  Alb + (long long)sr * pA + sc * 8);
    CP_ASYNC16(dofs + 12288, Bhb + (long long)sr * pB + sc * 8);
    CP_ASYNC16(dofs + 18432, Blb + (long long)sr * pB + sc * 8);
    CP_COMMIT();

    float c[2][8][4];
#pragma unroll
    for (int i = 0; i < 2; i++)
#pragma unroll
        for (int j = 0; j < 8; j++)
#pragma unroll
            for (int q = 0; q < 4; q++) c[i][j][q] = 0.f;

    int g8 = lane >> 2, kc = (lane & 3) * 2;
    int NT = K >> 4;
    for (int kt = 0; kt < NT; kt++) {
        if (kt + 1 < NT) {
            int k0 = (kt + 1) << 4;
            uint32_t d2 = dofs + ((kt + 1) & 1) * 24576;
            CP_ASYNC16(d2,         Ahb + (long long)sr * pA + k0 + sc * 8);
            CP_ASYNC16(d2 + 6144,  Alb + (long long)sr * pA + k0 + sc * 8);
            CP_ASYNC16(d2 + 12288, Bhb + (long long)sr * pB + k0 + sc * 8);
            CP_ASYNC16(d2 + 18432, Blb + (long long)sr * pB + k0 + sc * 8);
            CP_COMMIT();
            CP_WAIT(1);
        } else {
            CP_WAIT(0);
        }
        __syncthreads();
        const __nv_bfloat16* P = SB + (kt & 1) * 12288;
        uint32_t ah[2][4], al[2][4];
#pragma unroll
        for (int mt = 0; mt < 2; mt++) {
            int mb = warpm + mt * 16 + g8;
            ah[mt][0] = *(const uint32_t*)(P + mb * 24 + kc);
            ah[mt][1] = *(const uint32_t*)(P + (mb + 8) * 24 + kc);
            ah[mt][2] = *(const uint32_t*)(P + mb * 24 + kc + 8);
            ah[mt][3] = *(const uint32_t*)(P + (mb + 8) * 24 + kc + 8);
            al[mt][0] = *(const uint32_t*)(P + 3072 + mb * 24 + kc);
            al[mt][1] = *(const uint32_t*)(P + 3072 + (mb + 8) * 24 + kc);
            al[mt][2] = *(const uint32_t*)(P + 3072 + mb * 24 + kc + 8);
            al[mt][3] = *(const uint32_t*)(P + 3072 + (mb + 8) * 24 + kc + 8);
        }
#pragma unroll
        for (int nt = 0; nt < 8; nt++) {
            int nb = warpn + nt * 8 + g8;
            uint32_t bh0 = *(const uint32_t*)(P + 6144 + nb * 24 + kc);
            uint32_t bh1 = *(const uint32_t*)(P + 6144 + nb * 24 + kc + 8);
            uint32_t bl0 = *(const uint32_t*)(P + 9216 + nb * 24 + kc);
            uint32_t bl1 = *(const uint32_t*)(P + 9216 + nb * 24 + kc + 8);
#pragma unroll
            for (int mt = 0; mt < 2; mt++) {
                MMA_BF16(c[mt][nt], ah[mt][0], ah[mt][1], ah[mt][2], ah[mt][3], bh0, bh1);
                MMA_BF16(c[mt][nt], ah[mt][0], ah[mt][1], ah[mt][2], ah[mt][3], bl0, bl1);
                MMA_BF16(c[mt][nt], al[mt][0], al[mt][1], al[mt][2], al[mt][3], bh0, bh1);
            }
        }
        __syncthreads();
    }

    float cs[8][2], cq[8][2];
    if (STATS) {
#pragma unroll
        for (int j = 0; j < 8; j++) { cs[j][0] = cs[j][1] = 0.f; cq[j][0] = cq[j][1] = 0.f; }
    }
#pragma unroll
    for (int mt = 0; mt < 2; mt++) {
        int row = warpm + mt * 16 + g8;
        float rs0 = rowscale ? rowscale[m0 + row] : 1.f;
        float rs1 = rowscale ? rowscale[m0 + row + 8] : 1.f;
#pragma unroll
        for (int nt = 0; nt < 8; nt++) {
            int col = warpn + nt * 8 + kc;
            float b0 = bias ? bias[col] : 0.f;
            float b1 = bias ? bias[col + 1] : 0.f;
            float v00 = (c[mt][nt][0] + b0) * rs0, v01 = (c[mt][nt][1] + b1) * rs0;
            float v10 = (c[mt][nt][2] + b0) * rs1, v11 = (c[mt][nt][3] + b1) * rs1;
            *reinterpret_cast<float2*>(Cb + (long long)row * 128 + col) = make_float2(v00, v01);
            *reinterpret_cast<float2*>(Cb + (long long)(row + 8) * 128 + col) = make_float2(v10, v11);
            if (STATS) {
                cs[nt][0] += v00 + v10; cq[nt][0] += v00 * v00 + v10 * v10;
                cs[nt][1] += v01 + v11; cq[nt][1] += v01 * v01 + v11 * v11;
            }
        }
    }
    if (STATS) {
        __syncthreads();
#pragma unroll
        for (int nt = 0; nt < 8; nt++) {
            int col = warpn + nt * 8 + kc;
            atomicAdd(&sstat[col], cs[nt][0]);
            atomicAdd(&sstat[col + 1], cs[nt][1]);
            atomicAdd(&sstat[128 + col], cq[nt][0]);
            atomicAdd(&sstat[128 + col + 1], cq[nt][1]);
        }
        __syncthreads();
        if (t < 128) {
            atomicAdd(&g_sumA[t], sstat[t]);
            atomicAdd(&g_ssA[t], sstat[128 + t]);
        }
    }
}

// ================= warp-per-node aggregation (dual accumulators) =================
// MODE 0: gcn+bias (+stats, fp32 out); 1: gcn+bias+softmax (fp32 + sT bf16); 2: plain sum (tT bf16)
template<int MODE>
__global__ __launch_bounds__(256) void k_aggw(
    const float* __restrict__ in, const float* __restrict__ bias, float* __restrict__ out,
    __nv_bfloat16* __restrict__ oTh, __nv_bfloat16* __restrict__ oTl)
{
    __shared__ float sred[8][128];
    __shared__ float st[8][132];
    int t = threadIdx.x, w = t >> 5, lane = t & 31;
    int i = blockIdx.x * 8 + w;
    int e0 = i * SLOTCAP;
    int n = g_deg[i];
    int npad = (n + 7) & ~7;
    if (npad > SLOTCAP) npad = SLOTCAP;
    float4 accA = {0.f, 0.f, 0.f, 0.f}, accB = {0.f, 0.f, 0.f, 0.f};
    for (int c0 = 0; c0 < npad; c0 += 32) {
        int m = npad - c0; if (m > 32) m = 32;
        int src = (lane < m) ? g_srcbuf[e0 + c0 + lane] : 0;
        for (int kk = 0; kk < m; kk += 8) {
#pragma unroll
            for (int u = 0; u < 8; u += 2) {
                int s0 = __shfl_sync(0xffffffffu, src, kk + u);
                int s1 = __shfl_sync(0xffffffffu, src, kk + u + 1);
                float4 h0 = *reinterpret_cast<const float4*>(in + (long long)s0 * 128 + lane * 4);
                float4 h1 = *reinterpret_cast<const float4*>(in + (long long)s1 * 128 + lane * 4);
                accA.x += h0.x; accA.y += h0.y; accA.z += h0.z; accA.w += h0.w;
                accB.x += h1.x; accB.y += h1.y; accB.z += h1.z; accB.w += h1.w;
            }
        }
    }
    float ax = accA.x + accB.x, ay = accA.y + accB.y;
    float az = accA.z + accB.z, aw = accA.w + accB.w;
    float di = g_dinv[i];
    float vx, vy, vz, vw;
    if (MODE != 2) {
        float4 hv = *reinterpret_cast<const float4*>(in + (long long)i * 128 + lane * 4);
        vx = di * (ax + hv.x) + bias[lane * 4 + 0];
        vy = di * (ay + hv.y) + bias[lane * 4 + 1];
        vz = di * (az + hv.z) + bias[lane * 4 + 2];
        vw = di * (aw + hv.w) + bias[lane * 4 + 3];
    } else {
        vx = ax; vy = ay; vz = az; vw = aw;
    }
    if (MODE == 1) {
        float mx = fmaxf(fmaxf(vx, vy), fmaxf(vz, vw));
#pragma unroll
        for (int o = 16; o; o >>= 1) mx = fmaxf(mx, __shfl_xor_sync(0xffffffffu, mx, o));
        vx = __expf(vx - mx); vy = __expf(vy - mx); vz = __expf(vz - mx); vw = __expf(vw - mx);
        float sm = vx + vy + vz + vw;
#pragma unroll
        for (int o = 16; o; o >>= 1) sm += __shfl_xor_sync(0xffffffffu, sm, o);
        float inv = 1.f / sm;
        vx *= inv; vy *= inv; vz *= inv; vw *= inv;
    }
    if (MODE != 2) {
        float4 o4 = { vx, vy, vz, vw };
        *reinterpret_cast<float4*>(out + (long long)i * 128 + lane * 4) = o4;
    }
    if (MODE == 0) {
        sred[w][lane * 4 + 0] = vx; sred[w][lane * 4 + 1] = vy;
        sred[w][lane * 4 + 2] = vz; sred[w][lane * 4 + 3] = vw;
        __syncthreads();
        if (t < 128) {
            float s = 0.f, q = 0.f;
#pragma unroll
            for (int ww = 0; ww < 8; ww++) { float v = sred[ww][t]; s += v; q += v * v; }
            atomicAdd(&g_sumB[t], s);
            atomicAdd(&g_ssB[t], q);
        }
    } else {
        st[w][lane * 4 + 0] = vx; st[w][lane * 4 + 1] = vy;
        st[w][lane * 4 + 2] = vz; st[w][lane * 4 + 3] = vw;
        __syncthreads();
        if (t < 128) {
            int c = t;
            float v0 = st[0][c], v1 = st[1][c], v2 = st[2][c], v3 = st[3][c];
            float v4 = st[4][c], v5 = st[5][c], v6 = st[6][c], v7 = st[7][c];
            long long o = (long long)c * NNODES + blockIdx.x * 8;
            uint4 hv, lv;
            hv.x = pack_hi(v0, v1); hv.y = pack_hi(v2, v3);
            hv.z = pack_hi(v4, v5); hv.w = pack_hi(v6, v7);
            lv.x = pack_lo(v0, v1); lv.y = pack_lo(v2, v3);
            lv.z = pack_lo(v4, v5); lv.w = pack_lo(v6, v7);
            *reinterpret_cast<uint4*>(oTh + o) = hv;
            *reinterpret_cast<uint4*>(oTl + o) = lv;
        }
    }
}

// agg of prescaled x (64 ch) -> row-major bf16 hi/lo (dual accumulators)
__global__ __launch_bounds__(256) void k_aggx() {
    int t = threadIdx.x, w = t >> 5, lane = t & 31;
    int i = blockIdx.x * 8 + w;
    int e0 = i * SLOTCAP;
    int n = g_deg[i];
    int npad = (n + 7) & ~7;
    if (npad > SLOTCAP) npad = SLOTCAP;
    float2 accA = {0.f, 0.f}, accB = {0.f, 0.f};
    for (int c0 = 0; c0 < npad; c0 += 32) {
        int m = npad - c0; if (m > 32) m = 32;
        int src = (lane < m) ? g_srcbuf[e0 + c0 + lane] : 0;
        for (int kk = 0; kk < m; kk += 8) {
#pragma unroll
            for (int u = 0; u < 8; u += 2) {
                int s0 = __shfl_sync(0xffffffffu, src, kk + u);
                int s1 = __shfl_sync(0xffffffffu, src, kk + u + 1);
                float2 h0 = *reinterpret_cast<const float2*>(g_xs + (long long)s0 * 64 + lane * 2);
                float2 h1 = *reinterpret_cast<const float2*>(g_xs + (long long)s1 * 64 + lane * 2);
                accA.x += h0.x; accA.y += h0.y;
                accB.x += h1.x; accB.y += h1.y;
            }
        }
    }
    float di = g_dinv[i];
    float2 hv = *reinterpret_cast<const float2*>(g_xs + (long long)i * 64 + lane * 2);
    float ax = di * (accA.x + accB.x + hv.x);
    float ay = di * (accA.y + accB.y + hv.y);
    long long o = (long long)i * 64 + lane * 2;
    *reinterpret_cast<uint32_t*>(g_axh + o) = pack_hi(ax, ay);
    *reinterpret_cast<uint32_t*>(g_axl + o) = pack_lo(ax, ay);
}

// ================= BN+SiLU(+res); fp32 h (opt), row bf16, trans bf16 (opt) =================
template<bool RES, bool WH, bool WT>
__global__ __launch_bounds__(256) void k_bn(
    const float* __restrict__ y, const float* __restrict__ res, float* __restrict__ h,
    __nv_bfloat16* __restrict__ rh, __nv_bfloat16* __restrict__ rl,
    __nv_bfloat16* __restrict__ th, __nv_bfloat16* __restrict__ tl,
    const float* __restrict__ gw, const float* __restrict__ be,
    const float* __restrict__ sumArr, const float* __restrict__ ssArr)
{
    __shared__ float tile[32][33];
    __shared__ float sc[32], sh[32];
    int t = threadIdx.x;
    int n0 = blockIdx.x * 32, c0 = blockIdx.y * 32;
    if (t < 32) {
        int c = c0 + t;
        float m = sumArr[c] * (1.f / NNODES);
        float var = ssArr[c] * (1.f / NNODES) - m * m;
        float s = gw[c] * rsqrtf(var + 1e-5f);
        sc[t] = s;
        sh[t] = be[c] - s * m;
    }
    __syncthreads();
    int nl = t >> 3, cg = t & 7;
    long long idx = (long long)(n0 + nl) * 128 + c0 + cg * 4;
    float4 v = *reinterpret_cast<const float4*>(y + idx);
    float o0, o1, o2, o3;
    {
        float a;
        a = sc[cg * 4 + 0] * v.x + sh[cg * 4 + 0]; o0 = a / (1.f + __expf(-a));
        a = sc[cg * 4 + 1] * v.y + sh[cg * 4 + 1]; o1 = a / (1.f + __expf(-a));
        a = sc[cg * 4 + 2] * v.z + sh[cg * 4 + 2]; o2 = a / (1.f + __expf(-a));
        a = sc[cg * 4 + 3] * v.w + sh[cg * 4 + 3]; o3 = a / (1.f + __expf(-a));
    }
    if (RES) {
        float4 r = *reinterpret_cast<const float4*>(res + idx);
        o0 += r.x; o1 += r.y; o2 += r.z; o3 += r.w;
    }
    if (WH) {
        float4 ov = { o0, o1, o2, o3 };
        *reinterpret_cast<float4*>(h + idx) = ov;
    }
    {
        uint2 hv, lv;
        hv.x = pack_hi(o0, o1); hv.y = pack_hi(o2, o3);
        lv.x = pack_lo(o0, o1); lv.y = pack_lo(o2, o3);
        *reinterpret_cast<uint2*>(rh + idx) = hv;
        *reinterpret_cast<uint2*>(rl + idx) = lv;
    }
    if (WT) {
        tile[nl][cg * 4 + 0] = o0; tile[nl][cg * 4 + 1] = o1;
        tile[nl][cg * 4 + 2] = o2; tile[nl][cg * 4 + 3] = o3;
        __syncthreads();
        int cc = t >> 3, g = t & 7;
        float w0 = tile[g * 4 + 0][cc], w1 = tile[g * 4 + 1][cc];
        float w2 = tile[g * 4 + 2][cc], w3 = tile[g * 4 + 3][cc];
        long long o = (long long)(c0 + cc) * NNODES + n0 + g * 4;
        uint2 hv, lv;
        hv.x = pack_hi(w0, w1); hv.y = pack_hi(w2, w3);
        lv.x = pack_lo(w0, w1); lv.y = pack_lo(w2, w3);
        *reinterpret_cast<uint2*>(th + o) = hv;
        *reinterpret_cast<uint2*>(tl + o) = lv;
    }
}

// ================= reduce partials + dinv2 + An; reset stack-2 state =================
__global__ __launch_bounds__(256) void k_reduce_an() {
    int b = blockIdx.x, t = threadIdx.x;
    if (b == 0 && t < 128) {
        g_s2a[t] = 0.f; g_q2a[t] = 0.f; g_s2b[t] = 0.f; g_q2b[t] = 0.f;
        if (t == 0) g_bar = 0;
    }
    const long long PS = (long long)NB * CH * CH;
    const long long BO = (long long)b * CH * CH;
    __shared__ float sd[128];
    for (int idx = t; idx < CH * CH; idx += 256) {
        float s = 0.f;
#pragma unroll
        for (int p = 0; p < 8; p++) s += g_xpart[p * PS + BO + idx];
        g_x2[BO + idx] = s;
    }
    int w = t >> 5, lane = t & 31;
    for (int r = w; r < 128; r += 8) {
        float rsum = 0.f;
#pragma unroll
        for (int q = 0; q < 4; q++) {
            int idx = r * 128 + lane + q * 32;
            float s = 0.f;
#pragma unroll
            for (int p = 0; p < 8; p++) s += g_apart[p * PS + BO + idx];
            g_A2[BO + idx] = s;
            rsum += s;
        }
#pragma unroll
        for (int o = 16; o; o >>= 1) rsum += __shfl_down_sync(0xffffffffu, rsum, o);
        if (lane == 0) sd[r] = rsqrtf(rsum + 1.0f);
    }
    __syncthreads();
    for (int idx = t; idx < CH * CH; idx += 256) {
        int i = idx >> 7, j = idx & 127;
        float v = g_A2[BO + idx] + (i == j ? 1.f : 0.f);
        g_An[BO + idx] = sd[i] * v * sd[j];
    }
}

// ================= fused stack-2 (FFMA2, 32 blocks, grid barrier) =================
__device__ __forceinline__ void gridbar(int target) {
    __syncthreads();
    __threadfence();
    if (threadIdx.x == 0) {
        atomicAdd(&g_bar, 1);
        while (*(volatile int*)&g_bar < target) __nanosleep(64);
    }
    __syncthreads();
    __threadfence();
}

__device__ __forceinline__ void gemm_sm128(const float* __restrict__ P, const float* __restrict__ Q,
                                           unsigned long long acc2[8][4], int tx, int ty)
{
#pragma unroll
    for (int i = 0; i < 8; i++)
#pragma unroll
        for (int j = 0; j < 4; j++) acc2[i][j] = 0ull;
#pragma unroll 2
    for (int k = 0; k < 128; k++) {
        float a[8];
#pragma unroll
        for (int i = 0; i < 8; i++) a[i] = P[(ty * 8 + i) * 128 + k];
        const unsigned long long* Qp =
            reinterpret_cast<const unsigned long long*>(&Q[k * 128 + tx * 8]);
        unsigned long long b0 = Qp[0], b1 = Qp[1], b2 = Qp[2], b3 = Qp[3];
#pragma unroll
        for (int i = 0; i < 8; i++) {
            unsigned long long ad = dup_f32(a[i]);
            ffma2(acc2[i][0], ad, b0);
            ffma2(acc2[i][1], ad, b1);
            ffma2(acc2[i][2], ad, b2);
            ffma2(acc2[i][3], ad, b3);
        }
    }
}

__global__ __launch_bounds__(256) void k_stack2(
    const float* __restrict__ w2a, const float* __restrict__ b2a,
    const float* __restrict__ g2a, const float* __restrict__ be2a,
    const float* __restrict__ w2b, const float* __restrict__ b2b,
    const float* __restrict__ g2b, const float* __restrict__ be2b,
    const float* __restrict__ wl, const float* __restrict__ bl,
    float* __restrict__ out, int out_size)
{
    extern __shared__ __align__(16) float sm2[];
    float* AN = sm2;
    float* XB = sm2 + 16384;
    float* WB = sm2 + 32768;
    __shared__ float red[2048];
    __shared__ float gv[128];
    __shared__ float lg[10];
    __shared__ float lse;
    int b = blockIdx.x, t = threadIdx.x, tx = t & 15, ty = t >> 4;
    const float INVN = 1.f / (NB * CH);

    {
        const float4* pAn = (const float4*)(g_An + (long long)b * 16384);
        const float4* pX2 = (const float4*)(g_x2 + (long long)b * 16384);
        const float4* pWa = (const float4*)w2a;
        float4* An4 = (float4*)AN; float4* X4 = (float4*)XB; float4* W4 = (float4*)WB;
        for (int i = t; i < 4096; i += 256) { An4[i] = pAn[i]; X4[i] = pX2[i]; W4[i] = pWa[i]; }
    }
    __syncthreads();

    unsigned long long acc2[8][4];
    float cs[8], cq[8];

    gemm_sm128(XB, WB, acc2, tx, ty);
    __syncthreads();
#pragma unroll
    for (int i = 0; i < 8; i++)
#pragma unroll
        for (int j = 0; j < 4; j++) {
            float2 p = u2f(acc2[i][j]);
            XB[(ty * 8 + i) * 128 + tx * 8 + 2 * j] = p.x;
            XB[(ty * 8 + i) * 128 + tx * 8 + 2 * j + 1] = p.y;
        }
    __syncthreads();

    gemm_sm128(AN, XB, acc2, tx, ty);
    __syncthreads();
#pragma unroll
    for (int j = 0; j < 8; j++) { cs[j] = 0.f; cq[j] = 0.f; }
#pragma unroll
    for (int i = 0; i < 8; i++)
#pragma unroll
        for (int j = 0; j < 4; j++) {
            float2 p = u2f(acc2[i][j]);
            float v0 = p.x + b2a[tx * 8 + 2 * j];
            float v1 = p.y + b2a[tx * 8 + 2 * j + 1];
            WB[(ty * 8 + i) * 128 + tx * 8 + 2 * j] = v0;
            WB[(ty * 8 + i) * 128 + tx * 8 + 2 * j + 1] = v1;
            cs[2 * j] += v0; cq[2 * j] += v0 * v0;
            cs[2 * j + 1] += v1; cq[2 * j + 1] += v1 * v1;
        }
#pragma unroll
    for (int j = 0; j < 8; j++) red[ty * 128 + tx * 8 + j] = cs[j];
    __syncthreads();
    if (t < 128) { float s = 0.f; for (int g = 0; g < 16; g++) s += red[g * 128 + t]; atomicAdd(&g_s2a[t], s); }
    __syncthreads();
#pragma unroll
    for (int j = 0; j < 8; j++) red[ty * 128 + tx * 8 + j] = cq[j];
    __syncthreads();
    if (t < 128) { float s = 0.f; for (int g = 0; g < 16; g++) s += red[g * 128 + t]; atomicAdd(&g_q2a[t], s); }

    gridbar(NB);

    float scv[8], shv[8];
#pragma unroll
    for (int j = 0; j < 8; j++) {
        int c = tx * 8 + j;
        float m = g_s2a[c] * INVN;
        float var = g_q2a[c] * INVN - m * m;
        float s = g2a[c] * rsqrtf(var + 1e-5f);
        scv[j] = s; shv[j] = be2a[c] - s * m;
    }
#pragma unroll
    for (int i = 0; i < 8; i++)
#pragma unroll
        for (int j = 0; j < 8; j++) {
            float v = WB[(ty * 8 + i) * 128 + tx * 8 + j];
            v = scv[j] * v + shv[j];
            v = v / (1.f + __expf(-v));
            XB[(ty * 8 + i) * 128 + tx * 8 + j] = v;
        }
    __syncthreads();

    {
        const float4* pWb = (const float4*)w2b;
        float4* W4 = (float4*)WB;
        for (int i = t; i < 4096; i += 256) W4[i] = pWb[i];
    }
    __syncthreads();

    gemm_sm128(XB, WB, acc2, tx, ty);
    __syncthreads();
#pragma unroll
    for (int i = 0; i < 8; i++)
#pragma unroll
        for (int j = 0; j < 4; j++) {
            float2 p = u2f(acc2[i][j]);
            WB[(ty * 8 + i) * 128 + tx * 8 + 2 * j] = p.x;
            WB[(ty * 8 + i) * 128 + tx * 8 + 2 * j + 1] = p.y;
        }
    __syncthreads();

    gemm_sm128(AN, WB, acc2, tx, ty);
#pragma unroll
    for (int j = 0; j < 8; j++) { cs[j] = 0.f; cq[j] = 0.f; }
#pragma unroll
    for (int i = 0; i < 8; i++)
#pragma unroll
        for (int j = 0; j < 4; j++) {
            float2 p = u2f(acc2[i][j]);
            float v0 = p.x + b2b[tx * 8 + 2 * j];
            float v1 = p.y + b2b[tx * 8 + 2 * j + 1];
            cs[2 * j] += v0; cq[2 * j] += v0 * v0;
            cs[2 * j + 1] += v1; cq[2 * j + 1] += v1 * v1;
        }
    __syncthreads();
#pragma unroll
    for (int j = 0; j < 8; j++) red[ty * 128 + tx * 8 + j] = cs[j];
    __syncthreads();
    if (t < 128) { float s = 0.f; for (int g = 0; g < 16; g++) s += red[g * 128 + t]; atomicAdd(&g_s2b[t], s); }
    __syncthreads();
#pragma unroll
    for (int j = 0; j < 8; j++) red[ty * 128 + tx * 8 + j] = cq[j];
    __syncthreads();
    if (t < 128) { float s = 0.f; for (int g = 0; g < 16; g++) s += red[g * 128 + t]; atomicAdd(&g_q2b[t], s); }

    gridbar(2 * NB);

#pragma unroll
    for (int j = 0; j < 8; j++) {
        int c = tx * 8 + j;
        float m = g_s2b[c] * INVN;
        float var = g_q2b[c] * INVN - m * m;
        float s = g2b[c] * rsqrtf(var + 1e-5f);
        scv[j] = s; shv[j] = be2b[c] - s * m;
    }
    float colsum[8];
#pragma unroll
    for (int j = 0; j < 8; j++) colsum[j] = 0.f;
#pragma unroll
    for (int i = 0; i < 8; i++)
#pragma unroll
        for (int j = 0; j < 4; j++) {
            float2 p = u2f(acc2[i][j]);
            float v0 = scv[2 * j] * (p.x + b2b[tx * 8 + 2 * j]) + shv[2 * j];
            float v1 = scv[2 * j + 1] * (p.y + b2b[tx * 8 + 2 * j + 1]) + shv[2 * j + 1];
            v0 = v0 / (1.f + __expf(-v0));
            v1 = v1 / (1.f + __expf(-v1));
            v0 += XB[(ty * 8 + i) * 128 + tx * 8 + 2 * j];
            v1 += XB[(ty * 8 + i) * 128 + tx * 8 + 2 * j + 1];
            colsum[2 * j] += v0;
            colsum[2 * j + 1] += v1;
        }
    __syncthreads();
#pragma unroll
    for (int j = 0; j < 8; j++) red[ty * 128 + tx * 8 + j] = colsum[j];
    __syncthreads();
    if (t < 128) {
        float s = 0.f;
        for (int g = 0; g < 16; g++) s += red[g * 128 + t];
        gv[t] = s * (1.f / 32.f);
    }
    __syncthreads();
    if (t < 10) {
        float a = bl[t];
        for (int k = 0; k < 128; k++) a += gv[k] * wl[k * 10 + t];
        lg[t] = a;
    }
    __syncthreads();
    if (t == 0) {
        float mx = -1e30f;
        for (int j = 0; j < 10; j++) mx = fmaxf(mx, lg[j]);
        float se = 0.f;
        for (int j = 0; j < 10; j++) se += expf(lg[j] - mx);
        lse = mx + logf(se);
    }
    __syncthreads();
    if (t < 10) {
        int o = b * 10 + t;
        if (o < out_size) out[o] = lg[t] - lse;
    }
    if (b == 0) {
        for (int idx = NB * 10 + t; idx < out_size; idx += 256) out[idx] = 0.f;
    }
}

// ================= host orchestration =================
extern "C" void kernel_launch(void* const* d_in, const int* in_sizes, int n_in,
                              void* d_out, int out_size) {
    const float* x    = (const float*)d_in[0];
    const int*   ei   = (const int*)  d_in[1];
    const float* w1a  = (const float*)d_in[4];
    const float* b1a  = (const float*)d_in[5];
    const float* g1a  = (const float*)d_in[6];
    const float* be1a = (const float*)d_in[7];
    const float* w1b  = (const float*)d_in[8];
    const float* b1b  = (const float*)d_in[9];
    const float* g1b  = (const float*)d_in[10];
    const float* be1b = (const float*)d_in[11];
    const float* wp1  = (const float*)d_in[12];
    const float* bp1  = (const float*)d_in[13];
    const float* w2a  = (const float*)d_in[14];
    const float* b2a  = (const float*)d_in[15];
    const float* g2a  = (const float*)d_in[16];
    const float* be2a = (const float*)d_in[17];
    const float* w2b  = (const float*)d_in[18];
    const float* b2b  = (const float*)d_in[19];
    const float* g2b  = (const float*)d_in[20];
    const float* be2b = (const float*)d_in[21];
    const float* wl   = (const float*)d_in[24];
    const float* bl   = (const float*)d_in[25];
    float* outp = (float*)d_out;
    (void)n_in; (void)in_sizes;

    float *p_lin, *p_y, *p_h, *p_s, *p_xpart, *p_apart;
    float *p_sumA, *p_ssA, *p_sumB, *p_ssB, *p_dinv;
    __nv_bfloat16 *p_axh, *p_axl, *p_hah, *p_hal, *p_hbh, *p_hbl;
    __nv_bfloat16 *p_hTh, *p_hTl, *p_sTh, *p_sTl, *p_tTh, *p_tTl;
    __nv_bfloat16 *p_w1ah, *p_w1al, *p_w1bh, *p_w1bl, *p_wp1h, *p_wp1l;
    cudaGetSymbolAddress((void**)&p_lin,   g_lin);
    cudaGetSymbolAddress((void**)&p_y,     g_y);
    cudaGetSymbolAddress((void**)&p_h,     g_h);
    cudaGetSymbolAddress((void**)&p_s,     g_s);
    cudaGetSymbolAddress((void**)&p_xpart, g_xpart);
    cudaGetSymbolAddress((void**)&p_apart, g_apart);
    cudaGetSymbolAddress((void**)&p_sumA,  g_sumA);
    cudaGetSymbolAddress((void**)&p_ssA,   g_ssA);
    cudaGetSymbolAddress((void**)&p_sumB,  g_sumB);
    cudaGetSymbolAddress((void**)&p_ssB,   g_ssB);
    cudaGetSymbolAddress((void**)&p_dinv,  g_dinv);
    cudaGetSymbolAddress((void**)&p_axh,   g_axh);
    cudaGetSymbolAddress((void**)&p_axl,   g_axl);
    cudaGetSymbolAddress((void**)&p_hah,   g_hah);
    cudaGetSymbolAddress((void**)&p_hal,   g_hal);
    cudaGetSymbolAddress((void**)&p_hbh,   g_hbh);
    cudaGetSymbolAddress((void**)&p_hbl,   g_hbl);
    cudaGetSymbolAddress((void**)&p_hTh,   g_hTh);
    cudaGetSymbolAddress((void**)&p_hTl,   g_hTl);
    cudaGetSymbolAddress((void**)&p_sTh,   g_sTh);
    cudaGetSymbolAddress((void**)&p_sTl,   g_sTl);
    cudaGetSymbolAddress((void**)&p_tTh,   g_tTh);
    cudaGetSymbolAddress((void**)&p_tTl,   g_tTl);
    cudaGetSymbolAddress((void**)&p_w1ah,  g_w1ah);
    cudaGetSymbolAddress((void**)&p_w1al,  g_w1al);
    cudaGetSymbolAddress((void**)&p_w1bh,  g_w1bh);
    cudaGetSymbolAddress((void**)&p_w1bl,  g_w1bl);
    cudaGetSymbolAddress((void**)&p_wp1h,  g_wp1h);
    cudaGetSymbolAddress((void**)&p_wp1l,  g_wp1l);

    static bool attrDone = false;
    if (!attrDone) {
        cudaFuncSetAttribute(k_stack2, cudaFuncAttributeMaxDynamicSharedMemorySize, 196608);
        cudaFuncSetAttribute(k_mma<false, true>,  cudaFuncAttributeMaxDynamicSharedMemorySize, 50176);
        cudaFuncSetAttribute(k_mma<false, false>, cudaFuncAttributeMaxDynamicSharedMemorySize, 50176);
        cudaFuncSetAttribute(k_mma<true, false>,  cudaFuncAttributeMaxDynamicSharedMemorySize, 50176);
        attrDone = true;
    }

    // graph structure (one-pass CSR) + pad + weight split + dinv + x prescale (separate)
    k_zero_deg<<<NNODES / 256, 256>>>();
    k_build<<<NEDGES / 256, 256>>>(ei);
    k_wsplit<<<160, 256>>>(w1a, w1b, wp1);
    k_xscale<<<NNODES / 8, 256>>>(x);

    // stack 1, layer a
    k_aggx<<<NNODES / 8, 256>>>();
    k_mma<false, true><<<256, 256, 50176>>>(p_axh, p_axl, 64,
                                            p_w1ah, p_w1al, nullptr, nullptr, 64,
                                            b1a, nullptr, p_y, nullptr, 64);
    k_bn<false, true, false><<<dim3(NNODES / 32, 4), 256>>>(
        p_y, nullptr, p_h, p_hah, p_hal, nullptr, nullptr, g1a, be1a, p_sumA, p_ssA);

    // stack 1, layer b (residual); GEMM output prescaled by dinv
    k_mma<false, false><<<256, 256, 50176>>>(p_hah, p_hal, 128,
                                             p_w1bh, p_w1bl, nullptr, nullptr, 128,
                                             nullptr, p_dinv, p_lin, nullptr, 128);
    k_aggw<0><<<NNODES / 8, 256>>>(p_lin, b1b, p_y, nullptr, nullptr);
    k_bn<true, false, true><<<dim3(NNODES / 32, 4), 256>>>(
        p_y, p_h, nullptr, p_hbh, p_hbl, p_hTh, p_hTl, g1b, be1b, p_sumB, p_ssB);

    // pooling 1; GEMM output prescaled by dinv
    k_mma<false, false><<<256, 256, 50176>>>(p_hbh, p_hbl, 128,
                                             p_wp1h, p_wp1l, nullptr, nullptr, 128,
                                             nullptr, p_dinv, p_lin, nullptr, 128);
    k_aggw<1><<<NNODES / 8, 256>>>(p_lin, bp1, p_s, p_sTh, p_sTl);
    k_aggw<2><<<NNODES / 8, 256>>>(p_s, nullptr, nullptr, p_tTh, p_tTl);

    // pooled einsums + reduce/An
    k_mma<true, false><<<dim3(1, 16, NB), 256, 50176>>>(p_sTh, p_sTl, NNODES,
                                                        p_hTh, p_hTl, p_tTh, p_tTl, NNODES,
                                                        nullptr, nullptr, p_xpart, p_apart, 128);
    k_reduce_an<<<NB, 256>>>();

    // fused stack 2 (FFMA2) + head
    k_stack2<<<NB, 256, 196608>>>(w2a, b2a, g2a, be2a, w2b, b2b, g2b, be2b, wl, bl, outp, out_size);
}

// round 13
// speedup vs baseline: 1.0396x; 1.0059x over previous
#include <cuda_runtime.h>
#include <cuda_bf16.h>
#include <math.h>
#include <stdint.h>

#define NNODES 32768
#define NEDGES 524288
#define NB     32
#define NPG    1024
#define CH     128
#define CIN    64
#define SLOTCAP 72

// PDL entry: allow successor to spin up, then wait for predecessor's data.
#define PDL_ENTRY() do { \
    cudaTriggerProgrammaticLaunchCompletion(); \
    cudaGridDependencySynchronize(); \
} while (0)

// ================= helpers =================
__device__ __forceinline__ uint32_t smem_u32(const void* p) {
    uint32_t a;
    asm("{ .reg .u64 t; cvta.to.shared.u64 t, %1; cvt.u32.u64 %0, t; }" : "=r"(a) : "l"(p));
    return a;
}
__device__ __forceinline__ void ffma2(unsigned long long& d, unsigned long long a, unsigned long long b) {
    asm("fma.rn.f32x2 %0, %1, %2, %0;" : "+l"(d) : "l"(a), "l"(b));
}
__device__ __forceinline__ unsigned long long dup_f32(float v) {
    unsigned long long r;
    asm("mov.b64 %0, {%1, %1};" : "=l"(r) : "f"(v));
    return r;
}
__device__ __forceinline__ float2 u2f(unsigned long long v) {
    float2 f;
    asm("mov.b64 {%0, %1}, %2;" : "=f"(f.x), "=f"(f.y) : "l"(v));
    return f;
}
#define CP_ASYNC16(dst, src) asm volatile("cp.async.ca.shared.global [%0], [%1], 16;" :: "r"(dst), "l"(src))
#define CP_COMMIT()          asm volatile("cp.async.commit_group;" ::: "memory")
#define CP_WAIT(n)           asm volatile("cp.async.wait_group %0;" :: "n"(n) : "memory")

#define MMA_BF16(cf, a0, a1, a2, a3, b0, b1) \
    asm volatile("mma.sync.aligned.m16n8k16.row.col.f32.bf16.bf16.f32 " \
        "{%0,%1,%2,%3},{%4,%5,%6,%7},{%8,%9},{%0,%1,%2,%3};" \
        : "+f"((cf)[0]), "+f"((cf)[1]), "+f"((cf)[2]), "+f"((cf)[3]) \
        : "r"(a0), "r"(a1), "r"(a2), "r"(a3), "r"(b0), "r"(b1))

__device__ __forceinline__ uint32_t pack_hi(float a, float b) {
    __nv_bfloat162 h;
    h.x = __float2bfloat16_rn(a); h.y = __float2bfloat16_rn(b);
    return *reinterpret_cast<uint32_t*>(&h);
}
__device__ __forceinline__ uint32_t pack_lo(float a, float b) {
    __nv_bfloat16 ha = __float2bfloat16_rn(a), hb = __float2bfloat16_rn(b);
    __nv_bfloat162 l;
    l.x = __float2bfloat16_rn(a - __bfloat162float(ha));
    l.y = __float2bfloat16_rn(b - __bfloat162float(hb));
    return *reinterpret_cast<uint32_t*>(&l);
}
__device__ __forceinline__ void split1(float v, __nv_bfloat16& h, __nv_bfloat16& l) {
    h = __float2bfloat16_rn(v);
    l = __float2bfloat16_rn(v - __bfloat162float(h));
}

// ================= device scratch =================
__device__ int   g_deg[NNODES];
__device__ int   g_srcbuf[NNODES * SLOTCAP];
__device__ float g_dinv[NNODES];

__device__ float g_xs [(NNODES + 8) * CIN];
__device__ float g_lin[(NNODES + 8) * CH];
__device__ float g_s  [(NNODES + 8) * CH];
__device__ float g_y  [NNODES * CH];
__device__ float g_h  [NNODES * CH];

__device__ __align__(16) __nv_bfloat16 g_axh[NNODES * CIN], g_axl[NNODES * CIN];
__device__ __align__(16) __nv_bfloat16 g_hah[NNODES * CH],  g_hal[NNODES * CH];
__device__ __align__(16) __nv_bfloat16 g_hbh[NNODES * CH],  g_hbl[NNODES * CH];
__device__ __align__(16) __nv_bfloat16 g_hTh[CH * NNODES],  g_hTl[CH * NNODES];
__device__ __align__(16) __nv_bfloat16 g_sTh[CH * NNODES],  g_sTl[CH * NNODES];
__device__ __align__(16) __nv_bfloat16 g_tTh[CH * NNODES],  g_tTl[CH * NNODES];
__device__ __align__(16) __nv_bfloat16 g_w1ah[CH * CIN], g_w1al[CH * CIN];
__device__ __align__(16) __nv_bfloat16 g_w1bh[CH * CH],  g_w1bl[CH * CH];
__device__ __align__(16) __nv_bfloat16 g_wp1h[CH * CH],  g_wp1l[CH * CH];

__device__ float g_xpart[8 * NB * CH * CH];
__device__ float g_apart[8 * NB * CH * CH];
__device__ float g_x2  [NB * CH * CH];
__device__ float g_A2  [NB * CH * CH];
__device__ float g_An  [NB * CH * CH];

__device__ float g_sumA[CH], g_ssA[CH], g_sumB[CH], g_ssB[CH];
__device__ float g_s2a[CH], g_q2a[CH], g_s2b[CH], g_q2b[CH];
__device__ int   g_bar;

// ================= graph structure (one-pass bucket CSR) =================
__global__ void k_zero_deg() {
    int i = blockIdx.x * 256 + threadIdx.x;
    cudaTriggerProgrammaticLaunchCompletion();
    g_deg[i] = 0;
    if (i < 128) { g_sumA[i] = 0.f; g_ssA[i] = 0.f; g_sumB[i] = 0.f; g_ssB[i] = 0.f; }
}
__global__ void k_build(const int* __restrict__ ei) {
    int e = blockIdx.x * 256 + threadIdx.x;
    PDL_ENTRY();
    if (e < NEDGES) {
        int d = ei[NEDGES + e];
        int p = atomicAdd(&g_deg[d], 1);
        g_srcbuf[d * SLOTCAP + p] = ei[e];
    }
}

__global__ void k_wsplit(const float* __restrict__ w1a, const float* __restrict__ w1b,
                         const float* __restrict__ wp1) {
    int idx = blockIdx.x * 256 + threadIdx.x;
    PDL_ENTRY();
    if (idx < NNODES) {
        int deg = g_deg[idx];
        g_dinv[idx] = rsqrtf((float)deg + 1.0f);
        int npad = (deg + 7) & ~7;
        if (npad > SLOTCAP) npad = SLOTCAP;
        for (int p = deg; p < npad; p++) g_srcbuf[idx * SLOTCAP + p] = NNODES;
    }
    if (idx < 8192) {
        int n = idx >> 6, k = idx & 63;
        split1(w1a[k * 128 + n], g_w1ah[idx], g_w1al[idx]);
    } else if (idx < 24576) {
        int j = idx - 8192;
        int n = j >> 7, k = j & 127;
        split1(w1b[k * 128 + n], g_w1bh[j], g_w1bl[j]);
    } else if (idx < 40960) {
        int j = idx - 24576;
        int n = j >> 7, k = j & 127;
        split1(wp1[k * 128 + n], g_wp1h[j], g_wp1l[j]);
    }
}

__global__ __launch_bounds__(256) void k_xscale(const float* __restrict__ x) {
    int t = blockIdx.x * 256 + threadIdx.x;
    PDL_ENTRY();
    int row = t >> 5, c2 = (t & 31) * 2;
    float d = g_dinv[row];
    float2 v = *reinterpret_cast<const float2*>(x + (long long)row * 64 + c2);
    v.x *= d; v.y *= d;
    *reinterpret_cast<float2*>(g_xs + (long long)row * 64 + c2) = v;
}

// ================= bf16-split mma.sync GEMM =================
template<bool POOLED, bool STATS>
__global__ __launch_bounds__(256) void k_mma(
    const __nv_bfloat16* __restrict__ Ah, const __nv_bfloat16* __restrict__ Al, long long pA,
    const __nv_bfloat16* __restrict__ B1h, const __nv_bfloat16* __restrict__ B1l,
    const __nv_bfloat16* __restrict__ B2h, const __nv_bfloat16* __restrict__ B2l, long long pB,
    const float* __restrict__ bias, const float* __restrict__ rowscale,
    float* __restrict__ C1, float* __restrict__ C2, int K)
{
    extern __shared__ __align__(16) char smem[];
    __nv_bfloat16* SB = reinterpret_cast<__nv_bfloat16*>(smem);
    float* sstat = reinterpret_cast<float*>(smem + 49152);
    int t = threadIdx.x, lane = t & 31;
    int warpm = ((t >> 5) & 3) * 32, warpn = (t >> 7) * 64;

    const __nv_bfloat16 *Ahb, *Alb, *Bhb, *Blb;
    float* Cb;
    long long m0 = 0;
    if (POOLED) {
        int g = blockIdx.z;
        int half = blockIdx.y >> 3, chunk = blockIdx.y & 7;
        long long ko = (long long)g * 1024 + (long long)chunk * 128;
        Ahb = Ah + ko; Alb = Al + ko;
        Bhb = (half ? B2h : B1h) + ko;
        Blb = (half ? B2l : B1l) + ko;
        Cb = (half ? C2 : C1) + (long long)(chunk * NB + g) * (CH * CH);
    } else {
        m0 = (long long)blockIdx.x * 128;
        Ahb = Ah + m0 * pA; Alb = Al + m0 * pA;
        Bhb = B1h; Blb = B1l;
        Cb = C1 + m0 * 128;
    }
    PDL_ENTRY();
    if (STATS) { sstat[t] = 0.f; }

    uint32_t sbase = smem_u32(SB);
    int sr = t >> 1, sc = t & 1;
    uint32_t dofs = sbase + sr * 48 + sc * 16;
    CP_ASYNC16(dofs,         Ahb + (long long)sr * pA + sc * 8);
    CP_ASYNC16(dofs + 6144,  Alb + (long long)sr * pA + sc * 8);
    CP_ASYNC16(dofs + 12288, Bhb + (long long)sr * pB + sc * 8);
    CP_ASYNC16(dofs + 18432, Blb + (long long)sr * pB + sc * 8);
    CP_COMMIT();

    float c[2][8][4];
#pragma unroll
    for (int i = 0; i < 2; i++)
#pragma unroll
        for (int j = 0; j < 8; j++)
#pragma unroll
            for (int q = 0; q < 4; q++) c[i][j][q] = 0.f;

    int g8 = lane >> 2, kc = (lane & 3) * 2;
    int NT = K >> 4;
    for (int kt = 0; kt < NT; kt++) {
        if (kt + 1 < NT) {
            int k0 = (kt + 1) << 4;
            uint32_t d2 = dofs + ((kt + 1) & 1) * 24576;
            CP_ASYNC16(d2,         Ahb + (long long)sr * pA + k0 + sc * 8);
            CP_ASYNC16(d2 + 6144,  Alb + (long long)sr * pA + k0 + sc * 8);
            CP_ASYNC16(d2 + 12288, Bhb + (long long)sr * pB + k0 + sc * 8);
            CP_ASYNC16(d2 + 18432, Blb + (long long)sr * pB + k0 + sc * 8);
            CP_COMMIT();
            CP_WAIT(1);
        } else {
            CP_WAIT(0);
        }
        __syncthreads();
        const __nv_bfloat16* P = SB + (kt & 1) * 12288;
        uint32_t ah[2][4], al[2][4];
#pragma unroll
        for (int mt = 0; mt < 2; mt++) {
            int mb = warpm + mt * 16 + g8;
            ah[mt][0] = *(const uint32_t*)(P + mb * 24 + kc);
            ah[mt][1] = *(const uint32_t*)(P + (mb + 8) * 24 + kc);
            ah[mt][2] = *(const uint32_t*)(P + mb * 24 + kc + 8);
            ah[mt][3] = *(const uint32_t*)(P + (mb + 8) * 24 + kc + 8);
            al[mt][0] = *(const uint32_t*)(P + 3072 + mb * 24 + kc);
            al[mt][1] = *(const uint32_t*)(P + 3072 + (mb + 8) * 24 + kc);
            al[mt][2] = *(const uint32_t*)(P + 3072 + mb * 24 + kc + 8);
            al[mt][3] = *(const uint32_t*)(P + 3072 + (mb + 8) * 24 + kc + 8);
        }
#pragma unroll
        for (int nt = 0; nt < 8; nt++) {
            int nb = warpn + nt * 8 + g8;
            uint32_t bh0 = *(const uint32_t*)(P + 6144 + nb * 24 + kc);
            uint32_t bh1 = *(const uint32_t*)(P + 6144 + nb * 24 + kc + 8);
            uint32_t bl0 = *(const uint32_t*)(P + 9216 + nb * 24 + kc);
            uint32_t bl1 = *(const uint32_t*)(P + 9216 + nb * 24 + kc + 8);
#pragma unroll
            for (int mt = 0; mt < 2; mt++) {
                MMA_BF16(c[mt][nt], ah[mt][0], ah[mt][1], ah[mt][2], ah[mt][3], bh0, bh1);
                MMA_BF16(c[mt][nt], ah[mt][0], ah[mt][1], ah[mt][2], ah[mt][3], bl0, bl1);
                MMA_BF16(c[mt][nt], al[mt][0], al[mt][1], al[mt][2], al[mt][3], bh0, bh1);
            }
        }
        __syncthreads();
    }

    float cs[8][2], cq[8][2];
    if (STATS) {
#pragma unroll
        for (int j = 0; j < 8; j++) { cs[j][0] = cs[j][1] = 0.f; cq[j][0] = cq[j][1] = 0.f; }
    }
#pragma unroll
    for (int mt = 0; mt < 2; mt++) {
        int row = warpm + mt * 16 + g8;
        float rs0 = rowscale ? rowscale[m0 + row] : 1.f;
        float rs1 = rowscale ? rowscale[m0 + row + 8] : 1.f;
#pragma unroll
        for (int nt = 0; nt < 8; nt++) {
            int col = warpn + nt * 8 + kc;
            float b0 = bias ? bias[col] : 0.f;
            float b1 = bias ? bias[col + 1] : 0.f;
            float v00 = (c[mt][nt][0] + b0) * rs0, v01 = (c[mt][nt][1] + b1) * rs0;
            float v10 = (c[mt][nt][2] + b0) * rs1, v11 = (c[mt][nt][3] + b1) * rs1;
            *reinterpret_cast<float2*>(Cb + (long long)row * 128 + col) = make_float2(v00, v01);
            *reinterpret_cast<float2*>(Cb + (long long)(row + 8) * 128 + col) = make_float2(v10, v11);
            if (STATS) {
                cs[nt][0] += v00 + v10; cq[nt][0] += v00 * v00 + v10 * v10;
                cs[nt][1] += v01 + v11; cq[nt][1] += v01 * v01 + v11 * v11;
            }
        }
    }
    if (STATS) {
        __syncthreads();
#pragma unroll
        for (int nt = 0; nt < 8; nt++) {
            int col = warpn + nt * 8 + kc;
            atomicAdd(&sstat[col], cs[nt][0]);
            atomicAdd(&sstat[col + 1], cs[nt][1]);
            atomicAdd(&sstat[128 + col], cq[nt][0]);
            atomicAdd(&sstat[128 + col + 1], cq[nt][1]);
        }
        __syncthreads();
        if (t < 128) {
            atomicAdd(&g_sumA[t], sstat[t]);
            atomicAdd(&g_ssA[t], sstat[128 + t]);
        }
    }
}

// ================= warp-per-node aggregation (dual accumulators) =================
template<int MODE>
__global__ __launch_bounds__(256) void k_aggw(
    const float* __restrict__ in, const float* __restrict__ bias, float* __restrict__ out,
    __nv_bfloat16* __restrict__ oTh, __nv_bfloat16* __restrict__ oTl)
{
    __shared__ float sred[8][128];
    __shared__ float st[8][132];
    int t = threadIdx.x, w = t >> 5, lane = t & 31;
    int i = blockIdx.x * 8 + w;
    int e0 = i * SLOTCAP;
    PDL_ENTRY();
    int n = g_deg[i];
    int npad = (n + 7) & ~7;
    if (npad > SLOTCAP) npad = SLOTCAP;
    float4 accA = {0.f, 0.f, 0.f, 0.f}, accB = {0.f, 0.f, 0.f, 0.f};
    for (int c0 = 0; c0 < npad; c0 += 32) {
        int m = npad - c0; if (m > 32) m = 32;
        int src = (lane < m) ? g_srcbuf[e0 + c0 + lane] : 0;
        for (int kk = 0; kk < m; kk += 8) {
#pragma unroll
            for (int u = 0; u < 8; u += 2) {
                int s0 = __shfl_sync(0xffffffffu, src, kk + u);
                int s1 = __shfl_sync(0xffffffffu, src, kk + u + 1);
                float4 h0 = *reinterpret_cast<const float4*>(in + (long long)s0 * 128 + lane * 4);
                float4 h1 = *reinterpret_cast<const float4*>(in + (long long)s1 * 128 + lane * 4);
                accA.x += h0.x; accA.y += h0.y; accA.z += h0.z; accA.w += h0.w;
                accB.x += h1.x; accB.y += h1.y; accB.z += h1.z; accB.w += h1.w;
            }
        }
    }
    float ax = accA.x + accB.x, ay = accA.y + accB.y;
    float az = accA.z + accB.z, aw = accA.w + accB.w;
    float di = g_dinv[i];
    float vx, vy, vz, vw;
    if (MODE != 2) {
        float4 hv = *reinterpret_cast<const float4*>(in + (long long)i * 128 + lane * 4);
        vx = di * (ax + hv.x) + bias[lane * 4 + 0];
        vy = di * (ay + hv.y) + bias[lane * 4 + 1];
        vz = di * (az + hv.z) + bias[lane * 4 + 2];
        vw = di * (aw + hv.w) + bias[lane * 4 + 3];
    } else {
        vx = ax; vy = ay; vz = az; vw = aw;
    }
    if (MODE == 1) {
        float mx = fmaxf(fmaxf(vx, vy), fmaxf(vz, vw));
#pragma unroll
        for (int o = 16; o; o >>= 1) mx = fmaxf(mx, __shfl_xor_sync(0xffffffffu, mx, o));
        vx = __expf(vx - mx); vy = __expf(vy - mx); vz = __expf(vz - mx); vw = __expf(vw - mx);
        float sm = vx + vy + vz + vw;
#pragma unroll
        for (int o = 16; o; o >>= 1) sm += __shfl_xor_sync(0xffffffffu, sm, o);
        float inv = 1.f / sm;
        vx *= inv; vy *= inv; vz *= inv; vw *= inv;
    }
    if (MODE != 2) {
        float4 o4 = { vx, vy, vz, vw };
        *reinterpret_cast<float4*>(out + (long long)i * 128 + lane * 4) = o4;
    }
    if (MODE == 0) {
        sred[w][lane * 4 + 0] = vx; sred[w][lane * 4 + 1] = vy;
        sred[w][lane * 4 + 2] = vz; sred[w][lane * 4 + 3] = vw;
        __syncthreads();
        if (t < 128) {
            float s = 0.f, q = 0.f;
#pragma unroll
            for (int ww = 0; ww < 8; ww++) { float v = sred[ww][t]; s += v; q += v * v; }
            atomicAdd(&g_sumB[t], s);
            atomicAdd(&g_ssB[t], q);
        }
    } else {
        st[w][lane * 4 + 0] = vx; st[w][lane * 4 + 1] = vy;
        st[w][lane * 4 + 2] = vz; st[w][lane * 4 + 3] = vw;
        __syncthreads();
        if (t < 128) {
            int c = t;
            float v0 = st[0][c], v1 = st[1][c], v2 = st[2][c], v3 = st[3][c];
            float v4 = st[4][c], v5 = st[5][c], v6 = st[6][c], v7 = st[7][c];
            long long o = (long long)c * NNODES + blockIdx.x * 8;
            uint4 hv, lv;
            hv.x = pack_hi(v0, v1); hv.y = pack_hi(v2, v3);
            hv.z = pack_hi(v4, v5); hv.w = pack_hi(v6, v7);
            lv.x = pack_lo(v0, v1); lv.y = pack_lo(v2, v3);
            lv.z = pack_lo(v4, v5); lv.w = pack_lo(v6, v7);
            *reinterpret_cast<uint4*>(oTh + o) = hv;
            *reinterpret_cast<uint4*>(oTl + o) = lv;
        }
    }
}

__global__ __launch_bounds__(256) void k_aggx() {
    int t = threadIdx.x, w = t >> 5, lane = t & 31;
    int i = blockIdx.x * 8 + w;
    int e0 = i * SLOTCAP;
    PDL_ENTRY();
    int n = g_deg[i];
    int npad = (n + 7) & ~7;
    if (npad > SLOTCAP) npad = SLOTCAP;
    float2 accA = {0.f, 0.f}, accB = {0.f, 0.f};
    for (int c0 = 0; c0 < npad; c0 += 32) {
        int m = npad - c0; if (m > 32) m = 32;
        int src = (lane < m) ? g_srcbuf[e0 + c0 + lane] : 0;
        for (int kk = 0; kk < m; kk += 8) {
#pragma unroll
            for (int u = 0; u < 8; u += 2) {
                int s0 = __shfl_sync(0xffffffffu, src, kk + u);
                int s1 = __shfl_sync(0xffffffffu, src, kk + u + 1);
                float2 h0 = *reinterpret_cast<const float2*>(g_xs + (long long)s0 * 64 + lane * 2);
                float2 h1 = *reinterpret_cast<const float2*>(g_xs + (long long)s1 * 64 + lane * 2);
                accA.x += h0.x; accA.y += h0.y;
                accB.x += h1.x; accB.y += h1.y;
            }
        }
    }
    float di = g_dinv[i];
    float2 hv = *reinterpret_cast<const float2*>(g_xs + (long long)i * 64 + lane * 2);
    float ax = di * (accA.x + accB.x + hv.x);
    float ay = di * (accA.y + accB.y + hv.y);
    long long o = (long long)i * 64 + lane * 2;
    *reinterpret_cast<uint32_t*>(g_axh + o) = pack_hi(ax, ay);
    *reinterpret_cast<uint32_t*>(g_axl + o) = pack_lo(ax, ay);
}

// ================= BN+SiLU(+res) =================
template<bool RES, bool WH, bool WT>
__global__ __launch_bounds__(256) void k_bn(
    const float* __restrict__ y, const float* __restrict__ res, float* __restrict__ h,
    __nv_bfloat16* __restrict__ rh, __nv_bfloat16* __restrict__ rl,
    __nv_bfloat16* __restrict__ th, __nv_bfloat16* __restrict__ tl,
    const float* __restrict__ gw, const float* __restrict__ be,
    const float* __restrict__ sumArr, const float* __restrict__ ssArr)
{
    __shared__ float tile[32][33];
    __shared__ float sc[32], sh[32];
    int t = threadIdx.x;
    int n0 = blockIdx.x * 32, c0 = blockIdx.y * 32;
    PDL_ENTRY();
    if (t < 32) {
        int c = c0 + t;
        float m = sumArr[c] * (1.f / NNODES);
        float var = ssArr[c] * (1.f / NNODES) - m * m;
        float s = gw[c] * rsqrtf(var + 1e-5f);
        sc[t] = s;
        sh[t] = be[c] - s * m;
    }
    __syncthreads();
    int nl = t >> 3, cg = t & 7;
    long long idx = (long long)(n0 + nl) * 128 + c0 + cg * 4;
    float4 v = *reinterpret_cast<const float4*>(y + idx);
    float o0, o1, o2, o3;
    {
        float a;
        a = sc[cg * 4 + 0] * v.x + sh[cg * 4 + 0]; o0 = a / (1.f + __expf(-a));
        a = sc[cg * 4 + 1] * v.y + sh[cg * 4 + 1]; o1 = a / (1.f + __expf(-a));
        a = sc[cg * 4 + 2] * v.z + sh[cg * 4 + 2]; o2 = a / (1.f + __expf(-a));
        a = sc[cg * 4 + 3] * v.w + sh[cg * 4 + 3]; o3 = a / (1.f + __expf(-a));
    }
    if (RES) {
        float4 r = *reinterpret_cast<const float4*>(res + idx);
        o0 += r.x; o1 += r.y; o2 += r.z; o3 += r.w;
    }
    if (WH) {
        float4 ov = { o0, o1, o2, o3 };
        *reinterpret_cast<float4*>(h + idx) = ov;
    }
    {
        uint2 hv, lv;
        hv.x = pack_hi(o0, o1); hv.y = pack_hi(o2, o3);
        lv.x = pack_lo(o0, o1); lv.y = pack_lo(o2, o3);
        *reinterpret_cast<uint2*>(rh + idx) = hv;
        *reinterpret_cast<uint2*>(rl + idx) = lv;
    }
    if (WT) {
        tile[nl][cg * 4 + 0] = o0; tile[nl][cg * 4 + 1] = o1;
        tile[nl][cg * 4 + 2] = o2; tile[nl][cg * 4 + 3] = o3;
        __syncthreads();
        int cc = t >> 3, g = t & 7;
        float w0 = tile[g * 4 + 0][cc], w1 = tile[g * 4 + 1][cc];
        float w2 = tile[g * 4 + 2][cc], w3 = tile[g * 4 + 3][cc];
        long long o = (long long)(c0 + cc) * NNODES + n0 + g * 4;
        uint2 hv, lv;
        hv.x = pack_hi(w0, w1); hv.y = pack_hi(w2, w3);
        lv.x = pack_lo(w0, w1); lv.y = pack_lo(w2, w3);
        *reinterpret_cast<uint2*>(th + o) = hv;
        *reinterpret_cast<uint2*>(tl + o) = lv;
    }
}

// ================= reduce partials + dinv2 + An =================
__global__ __launch_bounds__(256) void k_reduce_an() {
    int b = blockIdx.x, t = threadIdx.x;
    PDL_ENTRY();
    if (b == 0 && t < 128) {
        g_s2a[t] = 0.f; g_q2a[t] = 0.f; g_s2b[t] = 0.f; g_q2b[t] = 0.f;
        if (t == 0) g_bar = 0;
    }
    const long long PS = (long long)NB * CH * CH;
    const long long BO = (long long)b * CH * CH;
    __shared__ float sd[128];
    for (int idx = t; idx < CH * CH; idx += 256) {
        float s = 0.f;
#pragma unroll
        for (int p = 0; p < 8; p++) s += g_xpart[p * PS + BO + idx];
        g_x2[BO + idx] = s;
    }
    int w = t >> 5, lane = t & 31;
    for (int r = w; r < 128; r += 8) {
        float rsum = 0.f;
#pragma unroll
        for (int q = 0; q < 4; q++) {
            int idx = r * 128 + lane + q * 32;
            float s = 0.f;
#pragma unroll
            for (int p = 0; p < 8; p++) s += g_apart[p * PS + BO + idx];
            g_A2[BO + idx] = s;
            rsum += s;
        }
#pragma unroll
        for (int o = 16; o; o >>= 1) rsum += __shfl_down_sync(0xffffffffu, rsum, o);
        if (lane == 0) sd[r] = rsqrtf(rsum + 1.0f);
    }
    __syncthreads();
    for (int idx = t; idx < CH * CH; idx += 256) {
        int i = idx >> 7, j = idx & 127;
        float v = g_A2[BO + idx] + (i == j ? 1.f : 0.f);
        g_An[BO + idx] = sd[i] * v * sd[j];
    }
}

// ================= fused stack-2 (FFMA2, 32 blocks, grid barrier) =================
__device__ __forceinline__ void gridbar(int target) {
    __syncthreads();
    __threadfence();
    if (threadIdx.x == 0) {
        atomicAdd(&g_bar, 1);
        while (*(volatile int*)&g_bar < target) __nanosleep(64);
    }
    __syncthreads();
    __threadfence();
}

__device__ __forceinline__ void gemm_sm128(const float* __restrict__ P, const float* __restrict__ Q,
                                           unsigned long long acc2[8][4], int tx, int ty)
{
#pragma unroll
    for (int i = 0; i < 8; i++)
#pragma unroll
        for (int j = 0; j < 4; j++) acc2[i][j] = 0ull;
#pragma unroll 2
    for (int k = 0; k < 128; k++) {
        float a[8];
#pragma unroll
        for (int i = 0; i < 8; i++) a[i] = P[(ty * 8 + i) * 128 + k];
        const unsigned long long* Qp =
            reinterpret_cast<const unsigned long long*>(&Q[k * 128 + tx * 8]);
        unsigned long long b0 = Qp[0], b1 = Qp[1], b2 = Qp[2], b3 = Qp[3];
#pragma unroll
        for (int i = 0; i < 8; i++) {
            unsigned long long ad = dup_f32(a[i]);
            ffma2(acc2[i][0], ad, b0);
            ffma2(acc2[i][1], ad, b1);
            ffma2(acc2[i][2], ad, b2);
            ffma2(acc2[i][3], ad, b3);
        }
    }
}

__global__ __launch_bounds__(256) void k_stack2(
    const float* __restrict__ w2a, const float* __restrict__ b2a,
    const float* __restrict__ g2a, const float* __restrict__ be2a,
    const float* __restrict__ w2b, const float* __restrict__ b2b,
    const float* __restrict__ g2b, const float* __restrict__ be2b,
    const float* __restrict__ wl, const float* __restrict__ bl,
    float* __restrict__ out, int out_size)
{
    extern __shared__ __align__(16) float sm2[];
    float* AN = sm2;
    float* XB = sm2 + 16384;
    float* WB = sm2 + 32768;
    __shared__ float red[2048];
    __shared__ float gv[128];
    __shared__ float lg[10];
    __shared__ float lse;
    int b = blockIdx.x, t = threadIdx.x, tx = t & 15, ty = t >> 4;
    const float INVN = 1.f / (NB * CH);
    PDL_ENTRY();

    {
        const float4* pAn = (const float4*)(g_An + (long long)b * 16384);
        const float4* pX2 = (const float4*)(g_x2 + (long long)b * 16384);
        const float4* pWa = (const float4*)w2a;
        float4* An4 = (float4*)AN; float4* X4 = (float4*)XB; float4* W4 = (float4*)WB;
        for (int i = t; i < 4096; i += 256) { An4[i] = pAn[i]; X4[i] = pX2[i]; W4[i] = pWa[i]; }
    }
    __syncthreads();

    unsigned long long acc2[8][4];
    float cs[8], cq[8];

    gemm_sm128(XB, WB, acc2, tx, ty);
    __syncthreads();
#pragma unroll
    for (int i = 0; i < 8; i++)
#pragma unroll
        for (int j = 0; j < 4; j++) {
            float2 p = u2f(acc2[i][j]);
            XB[(ty * 8 + i) * 128 + tx * 8 + 2 * j] = p.x;
            XB[(ty * 8 + i) * 128 + tx * 8 + 2 * j + 1] = p.y;
        }
    __syncthreads();

    gemm_sm128(AN, XB, acc2, tx, ty);
    __syncthreads();
#pragma unroll
    for (int j = 0; j < 8; j++) { cs[j] = 0.f; cq[j] = 0.f; }
#pragma unroll
    for (int i = 0; i < 8; i++)
#pragma unroll
        for (int j = 0; j < 4; j++) {
            float2 p = u2f(acc2[i][j]);
            float v0 = p.x + b2a[tx * 8 + 2 * j];
            float v1 = p.y + b2a[tx * 8 + 2 * j + 1];
            WB[(ty * 8 + i) * 128 + tx * 8 + 2 * j] = v0;
            WB[(ty * 8 + i) * 128 + tx * 8 + 2 * j + 1] = v1;
            cs[2 * j] += v0; cq[2 * j] += v0 * v0;
            cs[2 * j + 1] += v1; cq[2 * j + 1] += v1 * v1;
        }
#pragma unroll
    for (int j = 0; j < 8; j++) red[ty * 128 + tx * 8 + j] = cs[j];
    __syncthreads();
    if (t < 128) { float s = 0.f; for (int g = 0; g < 16; g++) s += red[g * 128 + t]; atomicAdd(&g_s2a[t], s); }
    __syncthreads();
#pragma unroll
    for (int j = 0; j < 8; j++) red[ty * 128 + tx * 8 + j] = cq[j];
    __syncthreads();
    if (t < 128) { float s = 0.f; for (int g = 0; g < 16; g++) s += red[g * 128 + t]; atomicAdd(&g_q2a[t], s); }

    gridbar(NB);

    float scv[8], shv[8];
#pragma unroll
    for (int j = 0; j < 8; j++) {
        int c = tx * 8 + j;
        float m = g_s2a[c] * INVN;
        float var = g_q2a[c] * INVN - m * m;
        float s = g2a[c] * rsqrtf(var + 1e-5f);
        scv[j] = s; shv[j] = be2a[c] - s * m;
    }
#pragma unroll
    for (int i = 0; i < 8; i++)
#pragma unroll
        for (int j = 0; j < 8; j++) {
            float v = WB[(ty * 8 + i) * 128 + tx * 8 + j];
            v = scv[j] * v + shv[j];
            v = v / (1.f + __expf(-v));
            XB[(ty * 8 + i) * 128 + tx * 8 + j] = v;
        }
    __syncthreads();

    {
        const float4* pWb = (const float4*)w2b;
        float4* W4 = (float4*)WB;
        for (int i = t; i < 4096; i += 256) W4[i] = pWb[i];
    }
    __syncthreads();

    gemm_sm128(XB, WB, acc2, tx, ty);
    __syncthreads();
#pragma unroll
    for (int i = 0; i < 8; i++)
#pragma unroll
        for (int j = 0; j < 4; j++) {
            float2 p = u2f(acc2[i][j]);
            WB[(ty * 8 + i) * 128 + tx * 8 + 2 * j] = p.x;
            WB[(ty * 8 + i) * 128 + tx * 8 + 2 * j + 1] = p.y;
        }
    __syncthreads();

    gemm_sm128(AN, WB, acc2, tx, ty);
#pragma unroll
    for (int j = 0; j < 8; j++) { cs[j] = 0.f; cq[j] = 0.f; }
#pragma unroll
    for (int i = 0; i < 8; i++)
#pragma unroll
        for (int j = 0; j < 4; j++) {
            float2 p = u2f(acc2[i][j]);
            float v0 = p.x + b2b[tx * 8 + 2 * j];
            float v1 = p.y + b2b[tx * 8 + 2 * j + 1];
            cs[2 * j] += v0; cq[2 * j] += v0 * v0;
            cs[2 * j + 1] += v1; cq[2 * j + 1] += v1 * v1;
        }
    __syncthreads();
#pragma unroll
    for (int j = 0; j < 8; j++) red[ty * 128 + tx * 8 + j] = cs[j];
    __syncthreads();
    if (t < 128) { float s = 0.f; for (int g = 0; g < 16; g++) s += red[g * 128 + t]; atomicAdd(&g_s2b[t], s); }
    __syncthreads();
#pragma unroll
    for (int j = 0; j < 8; j++) red[ty * 128 + tx * 8 + j] = cq[j];
    __syncthreads();
    if (t < 128) { float s = 0.f; for (int g = 0; g < 16; g++) s += red[g * 128 + t]; atomicAdd(&g_q2b[t], s); }

    gridbar(2 * NB);

#pragma unroll
    for (int j = 0; j < 8; j++) {
        int c = tx * 8 + j;
        float m = g_s2b[c] * INVN;
        float var = g_q2b[c] * INVN - m * m;
        float s = g2b[c] * rsqrtf(var + 1e-5f);
        scv[j] = s; shv[j] = be2b[c] - s * m;
    }
    float colsum[8];
#pragma unroll
    for (int j = 0; j < 8; j++) colsum[j] = 0.f;
#pragma unroll
    for (int i = 0; i < 8; i++)
#pragma unroll
        for (int j = 0; j < 4; j++) {
            float2 p = u2f(acc2[i][j]);
            float v0 = scv[2 * j] * (p.x + b2b[tx * 8 + 2 * j]) + shv[2 * j];
            float v1 = scv[2 * j + 1] * (p.y + b2b[tx * 8 + 2 * j + 1]) + shv[2 * j + 1];
            v0 = v0 / (1.f + __expf(-v0));
            v1 = v1 / (1.f + __expf(-v1));
            v0 += XB[(ty * 8 + i) * 128 + tx * 8 + 2 * j];
            v1 += XB[(ty * 8 + i) * 128 + tx * 8 + 2 * j + 1];
            colsum[2 * j] += v0;
            colsum[2 * j + 1] += v1;
        }
    __syncthreads();
#pragma unroll
    for (int j = 0; j < 8; j++) red[ty * 128 + tx * 8 + j] = colsum[j];
    __syncthreads();
    if (t < 128) {
        float s = 0.f;
        for (int g = 0; g < 16; g++) s += red[g * 128 + t];
        gv[t] = s * (1.f / 32.f);
    }
    __syncthreads();
    if (t < 10) {
        float a = bl[t];
        for (int k = 0; k < 128; k++) a += gv[k] * wl[k * 10 + t];
        lg[t] = a;
    }
    __syncthreads();
    if (t == 0) {
        float mx = -1e30f;
        for (int j = 0; j < 10; j++) mx = fmaxf(mx, lg[j]);
        float se = 0.f;
        for (int j = 0; j < 10; j++) se += expf(lg[j] - mx);
        lse = mx + logf(se);
    }
    __syncthreads();
    if (t < 10) {
        int o = b * 10 + t;
        if (o < out_size) out[o] = lg[t] - lse;
    }
    if (b == 0) {
        for (int idx = NB * 10 + t; idx < out_size; idx += 256) out[idx] = 0.f;
    }
}

// ================= host orchestration =================
extern "C" void kernel_launch(void* const* d_in, const int* in_sizes, int n_in,
                              void* d_out, int out_size) {
    const float* x    = (const float*)d_in[0];
    const int*   ei   = (const int*)  d_in[1];
    const float* w1a  = (const float*)d_in[4];
    const float* b1a  = (const float*)d_in[5];
    const float* g1a  = (const float*)d_in[6];
    const float* be1a = (const float*)d_in[7];
    const float* w1b  = (const float*)d_in[8];
    const float* b1b  = (const float*)d_in[9];
    const float* g1b  = (const float*)d_in[10];
    const float* be1b = (const float*)d_in[11];
    const float* wp1  = (const float*)d_in[12];
    const float* bp1  = (const float*)d_in[13];
    const float* w2a  = (const float*)d_in[14];
    const float* b2a  = (const float*)d_in[15];
    const float* g2a  = (const float*)d_in[16];
    const float* be2a = (const float*)d_in[17];
    const float* w2b  = (const float*)d_in[18];
    const float* b2b  = (const float*)d_in[19];
    const float* g2b  = (const float*)d_in[20];
    const float* be2b = (const float*)d_in[21];
    const float* wl   = (const float*)d_in[24];
    const float* bl   = (const float*)d_in[25];
    float* outp = (float*)d_out;
    (void)n_in; (void)in_sizes;

    float *p_lin, *p_y, *p_h, *p_s, *p_xpart, *p_apart;
    float *p_sumA, *p_ssA, *p_sumB, *p_ssB, *p_dinv;
    __nv_bfloat16 *p_axh, *p_axl, *p_hah, *p_hal, *p_hbh, *p_hbl;
    __nv_bfloat16 *p_hTh, *p_hTl, *p_sTh, *p_sTl, *p_tTh, *p_tTl;
    __nv_bfloat16 *p_w1ah, *p_w1al, *p_w1bh, *p_w1bl, *p_wp1h, *p_wp1l;
    cudaGetSymbolAddress((void**)&p_lin,   g_lin);
    cudaGetSymbolAddress((void**)&p_y,     g_y);
    cudaGetSymbolAddress((void**)&p_h,     g_h);
    cudaGetSymbolAddress((void**)&p_s,     g_s);
    cudaGetSymbolAddress((void**)&p_xpart, g_xpart);
    cudaGetSymbolAddress((void**)&p_apart, g_apart);
    cudaGetSymbolAddress((void**)&p_sumA,  g_sumA);
    cudaGetSymbolAddress((void**)&p_ssA,   g_ssA);
    cudaGetSymbolAddress((void**)&p_sumB,  g_sumB);
    cudaGetSymbolAddress((void**)&p_ssB,   g_ssB);
    cudaGetSymbolAddress((void**)&p_dinv,  g_dinv);
    cudaGetSymbolAddress((void**)&p_axh,   g_axh);
    cudaGetSymbolAddress((void**)&p_axl,   g_axl);
    cudaGetSymbolAddress((void**)&p_hah,   g_hah);
    cudaGetSymbolAddress((void**)&p_hal,   g_hal);
    cudaGetSymbolAddress((void**)&p_hbh,   g_hbh);
    cudaGetSymbolAddress((void**)&p_hbl,   g_hbl);
    cudaGetSymbolAddress((void**)&p_hTh,   g_hTh);
    cudaGetSymbolAddress((void**)&p_hTl,   g_hTl);
    cudaGetSymbolAddress((void**)&p_sTh,   g_sTh);
    cudaGetSymbolAddress((void**)&p_sTl,   g_sTl);
    cudaGetSymbolAddress((void**)&p_tTh,   g_tTh);
    cudaGetSymbolAddress((void**)&p_tTl,   g_tTl);
    cudaGetSymbolAddress((void**)&p_w1ah,  g_w1ah);
    cudaGetSymbolAddress((void**)&p_w1al,  g_w1al);
    cudaGetSymbolAddress((void**)&p_w1bh,  g_w1bh);
    cudaGetSymbolAddress((void**)&p_w1bl,  g_w1bl);
    cudaGetSymbolAddress((void**)&p_wp1h,  g_wp1h);
    cudaGetSymbolAddress((void**)&p_wp1l,  g_wp1l);

    static bool attrDone = false;
    if (!attrDone) {
        cudaFuncSetAttribute(k_stack2, cudaFuncAttributeMaxDynamicSharedMemorySize, 196608);
        cudaFuncSetAttribute(k_mma<false, true>,  cudaFuncAttributeMaxDynamicSharedMemorySize, 50176);
        cudaFuncSetAttribute(k_mma<false, false>, cudaFuncAttributeMaxDynamicSharedMemorySize, 50176);
        cudaFuncSetAttribute(k_mma<true, false>,  cudaFuncAttributeMaxDynamicSharedMemorySize, 50176);
        attrDone = true;
    }

    cudaLaunchAttribute pdl[1];
    pdl[0].id = cudaLaunchAttributeProgrammaticStreamSerialization;
    pdl[0].val.programmaticStreamSerializationAllowed = 1;
    auto cfg = [&](dim3 g, dim3 b, size_t smem) {
        cudaLaunchConfig_t c = {};
        c.gridDim = g; c.blockDim = b; c.dynamicSmemBytes = smem;
        c.stream = 0; c.attrs = pdl; c.numAttrs = 1;
        return c;
    };

    // graph structure + weight split + x prescale
    { auto c = cfg(dim3(NNODES / 256), dim3(256), 0); cudaLaunchKernelEx(&c, k_zero_deg); }
    { auto c = cfg(dim3(NEDGES / 256), dim3(256), 0); cudaLaunchKernelEx(&c, k_build, ei); }
    { auto c = cfg(dim3(160), dim3(256), 0); cudaLaunchKernelEx(&c, k_wsplit, w1a, w1b, wp1); }
    { auto c = cfg(dim3(NNODES / 8), dim3(256), 0); cudaLaunchKernelEx(&c, k_xscale, x); }

    // stack 1, layer a
    { auto c = cfg(dim3(NNODES / 8), dim3(256), 0); cudaLaunchKernelEx(&c, k_aggx); }
    { auto c = cfg(dim3(256), dim3(256), 50176);
      cudaLaunchKernelEx(&c, k_mma<false, true>,
          (const __nv_bfloat16*)p_axh, (const __nv_bfloat16*)p_axl, (long long)64,
          (const __nv_bfloat16*)p_w1ah, (const __nv_bfloat16*)p_w1al,
          (const __nv_bfloat16*)nullptr, (const __nv_bfloat16*)nullptr, (long long)64,
          b1a, (const float*)nullptr, p_y, (float*)nullptr, 64); }
    { auto c = cfg(dim3(NNODES / 32, 4), dim3(256), 0);
      cudaLaunchKernelEx(&c, k_bn<false, true, false>,
          (const float*)p_y, (const float*)nullptr, p_h, p_hah, p_hal,
          (__nv_bfloat16*)nullptr, (__nv_bfloat16*)nullptr, g1a, be1a,
          (const float*)p_sumA, (const float*)p_ssA); }

    // stack 1, layer b (residual)
    { auto c = cfg(dim3(256), dim3(256), 50176);
      cudaLaunchKernelEx(&c, k_mma<false, false>,
          (const __nv_bfloat16*)p_hah, (const __nv_bfloat16*)p_hal, (long long)128,
          (const __nv_bfloat16*)p_w1bh, (const __nv_bfloat16*)p_w1bl,
          (const __nv_bfloat16*)nullptr, (const __nv_bfloat16*)nullptr, (long long)128,
          (const float*)nullptr, (const float*)p_dinv, p_lin, (float*)nullptr, 128); }
    { auto c = cfg(dim3(NNODES / 8), dim3(256), 0);
      cudaLaunchKernelEx(&c, k_aggw<0>, (const float*)p_lin, b1b, p_y,
          (__nv_bfloat16*)nullptr, (__nv_bfloat16*)nullptr); }
    { auto c = cfg(dim3(NNODES / 32, 4), dim3(256), 0);
      cudaLaunchKernelEx(&c, k_bn<true, false, true>,
          (const float*)p_y, (const float*)p_h, (float*)nullptr, p_hbh, p_hbl,
          p_hTh, p_hTl, g1b, be1b, (const float*)p_sumB, (const float*)p_ssB); }

    // pooling 1
    { auto c = cfg(dim3(256), dim3(256), 50176);
      cudaLaunchKernelEx(&c, k_mma<false, false>,
          (const __nv_bfloat16*)p_hbh, (const __nv_bfloat16*)p_hbl, (long long)128,
          (const __nv_bfloat16*)p_wp1h, (const __nv_bfloat16*)p_wp1l,
          (const __nv_bfloat16*)nullptr, (const __nv_bfloat16*)nullptr, (long long)128,
          (const float*)nullptr, (const float*)p_dinv, p_lin, (float*)nullptr, 128); }
    { auto c = cfg(dim3(NNODES / 8), dim3(256), 0);
      cudaLaunchKernelEx(&c, k_aggw<1>, (const float*)p_lin, bp1, p_s, p_sTh, p_sTl); }
    { auto c = cfg(dim3(NNODES / 8), dim3(256), 0);
      cudaLaunchKernelEx(&c, k_aggw<2>, (const float*)p_s, (const float*)nullptr,
          (float*)nullptr, p_tTh, p_tTl); }

    // pooled einsums + reduce/An
    { auto c = cfg(dim3(1, 16, NB), dim3(256), 50176);
      cudaLaunchKernelEx(&c, k_mma<true, false>,
          (const __nv_bfloat16*)p_sTh, (const __nv_bfloat16*)p_sTl, (long long)NNODES,
          (const __nv_bfloat16*)p_hTh, (const __nv_bfloat16*)p_hTl,
          (const __nv_bfloat16*)p_tTh, (const __nv_bfloat16*)p_tTl, (long long)NNODES,
          (const float*)nullptr, (const float*)nullptr, p_xpart, p_apart, 128); }
    { auto c = cfg(dim3(NB), dim3(256), 0); cudaLaunchKernelEx(&c, k_reduce_an); }

    // fused stack 2 (FFMA2) + head
    { auto c = cfg(dim3(NB), dim3(256), 196608);
      cudaLaunchKernelEx(&c, k_stack2, w2a, b2a, g2a, be2a, w2b, b2b, g2b, be2b,
          wl, bl, outp, out_size); }
}

// round 14
// speedup vs baseline: 1.0399x; 1.0003x over previous
#include <cuda_runtime.h>
#include <cuda_bf16.h>
#include <math.h>
#include <stdint.h>

#define NNODES 32768
#define NEDGES 524288
#define NB     32
#define NPG    1024
#define CH     128
#define CIN    64
#define SLOTCAP 72

// PDL entry: allow successor to spin up, then wait for predecessor's data.
#define PDL_ENTRY() do { \
    cudaTriggerProgrammaticLaunchCompletion(); \
    cudaGridDependencySynchronize(); \
} while (0)

// ================= helpers =================
__device__ __forceinline__ uint32_t smem_u32(const void* p) {
    uint32_t a;
    asm("{ .reg .u64 t; cvta.to.shared.u64 t, %1; cvt.u32.u64 %0, t; }" : "=r"(a) : "l"(p));
    return a;
}
__device__ __forceinline__ void ffma2(unsigned long long& d, unsigned long long a, unsigned long long b) {
    asm("fma.rn.f32x2 %0, %1, %2, %0;" : "+l"(d) : "l"(a), "l"(b));
}
__device__ __forceinline__ unsigned long long dup_f32(float v) {
    unsigned long long r;
    asm("mov.b64 %0, {%1, %1};" : "=l"(r) : "f"(v));
    return r;
}
__device__ __forceinline__ float2 u2f(unsigned long long v) {
    float2 f;
    asm("mov.b64 {%0, %1}, %2;" : "=f"(f.x), "=f"(f.y) : "l"(v));
    return f;
}
#define CP_ASYNC16(dst, src) asm volatile("cp.async.ca.shared.global [%0], [%1], 16;" :: "r"(dst), "l"(src))
#define CP_COMMIT()          asm volatile("cp.async.commit_group;" ::: "memory")
#define CP_WAIT(n)           asm volatile("cp.async.wait_group %0;" :: "n"(n) : "memory")

#define MMA_BF16(cf, a0, a1, a2, a3, b0, b1) \
    asm volatile("mma.sync.aligned.m16n8k16.row.col.f32.bf16.bf16.f32 " \
        "{%0,%1,%2,%3},{%4,%5,%6,%7},{%8,%9},{%0,%1,%2,%3};" \
        : "+f"((cf)[0]), "+f"((cf)[1]), "+f"((cf)[2]), "+f"((cf)[3]) \
        : "r"(a0), "r"(a1), "r"(a2), "r"(a3), "r"(b0), "r"(b1))

__device__ __forceinline__ uint32_t pack_hi(float a, float b) {
    __nv_bfloat162 h;
    h.x = __float2bfloat16_rn(a); h.y = __float2bfloat16_rn(b);
    return *reinterpret_cast<uint32_t*>(&h);
}
__device__ __forceinline__ uint32_t pack_lo(float a, float b) {
    __nv_bfloat16 ha = __float2bfloat16_rn(a), hb = __float2bfloat16_rn(b);
    __nv_bfloat162 l;
    l.x = __float2bfloat16_rn(a - __bfloat162float(ha));
    l.y = __float2bfloat16_rn(b - __bfloat162float(hb));
    return *reinterpret_cast<uint32_t*>(&l);
}
__device__ __forceinline__ void split1(float v, __nv_bfloat16& h, __nv_bfloat16& l) {
    h = __float2bfloat16_rn(v);
    l = __float2bfloat16_rn(v - __bfloat162float(h));
}

// ================= device scratch =================
// Gather targets (g_lin, g_s) have 8 extra rows; row NNODES is never written
// => stays zero (sentinel target for padded CSR slots).
__device__ int   g_deg[NNODES];
__device__ int   g_srcbuf[NNODES * SLOTCAP];
__device__ float g_dinv[NNODES];

__device__ float g_lin[(NNODES + 8) * CH];
__device__ float g_s  [(NNODES + 8) * CH];
__device__ float g_y  [NNODES * CH];
__device__ float g_h  [NNODES * CH];

__device__ __align__(16) __nv_bfloat16 g_axh[NNODES * CIN], g_axl[NNODES * CIN];
__device__ __align__(16) __nv_bfloat16 g_hah[NNODES * CH],  g_hal[NNODES * CH];
__device__ __align__(16) __nv_bfloat16 g_hbh[NNODES * CH],  g_hbl[NNODES * CH];
__device__ __align__(16) __nv_bfloat16 g_hTh[CH * NNODES],  g_hTl[CH * NNODES];
__device__ __align__(16) __nv_bfloat16 g_sTh[CH * NNODES],  g_sTl[CH * NNODES];
__device__ __align__(16) __nv_bfloat16 g_tTh[CH * NNODES],  g_tTl[CH * NNODES];
__device__ __align__(16) __nv_bfloat16 g_w1ah[CH * CIN], g_w1al[CH * CIN];
__device__ __align__(16) __nv_bfloat16 g_w1bh[CH * CH],  g_w1bl[CH * CH];
__device__ __align__(16) __nv_bfloat16 g_wp1h[CH * CH],  g_wp1l[CH * CH];

__device__ float g_xpart[8 * NB * CH * CH];
__device__ float g_apart[8 * NB * CH * CH];
__device__ float g_x2  [NB * CH * CH];
__device__ float g_A2  [NB * CH * CH];
__device__ float g_An  [NB * CH * CH];

__device__ float g_sumA[CH], g_ssA[CH], g_sumB[CH], g_ssB[CH];
__device__ float g_s2a[CH], g_q2a[CH], g_s2b[CH], g_q2b[CH];
__device__ int   g_bar;

// ================= graph structure (one-pass bucket CSR) =================
__global__ void k_zero_deg() {
    int i = blockIdx.x * 256 + threadIdx.x;
    cudaTriggerProgrammaticLaunchCompletion();
    g_deg[i] = 0;
    if (i < 128) { g_sumA[i] = 0.f; g_ssA[i] = 0.f; g_sumB[i] = 0.f; g_ssB[i] = 0.f; }
}
// 2 edges per thread (independent atomics -> higher MLP on the ATOMG path)
__global__ void k_build(const int* __restrict__ ei) {
    int e = (blockIdx.x * 256 + threadIdx.x) * 2;
    PDL_ENTRY();
    if (e < NEDGES) {
        int s0 = ei[e], s1 = ei[e + 1];
        int d0 = ei[NEDGES + e], d1 = ei[NEDGES + e + 1];
        int p0 = atomicAdd(&g_deg[d0], 1);
        int p1 = atomicAdd(&g_deg[d1], 1);
        g_srcbuf[d0 * SLOTCAP + p0] = s0;
        g_srcbuf[d1 * SLOTCAP + p1] = s1;
    }
}

// weights transpose + bf16 split; dinv; sentinel-pad buckets
__global__ void k_wsplit(const float* __restrict__ w1a, const float* __restrict__ w1b,
                         const float* __restrict__ wp1) {
    int idx = blockIdx.x * 256 + threadIdx.x;      // 160 blocks = 40960
    PDL_ENTRY();
    if (idx < NNODES) {
        int deg = g_deg[idx];
        g_dinv[idx] = rsqrtf((float)deg + 1.0f);
        int npad = (deg + 7) & ~7;
        if (npad > SLOTCAP) npad = SLOTCAP;
        for (int p = deg; p < npad; p++) g_srcbuf[idx * SLOTCAP + p] = NNODES;
    }
    if (idx < 8192) {
        int n = idx >> 6, k = idx & 63;
        split1(w1a[k * 128 + n], g_w1ah[idx], g_w1al[idx]);
    } else if (idx < 24576) {
        int j = idx - 8192;
        int n = j >> 7, k = j & 127;
        split1(w1b[k * 128 + n], g_w1bh[j], g_w1bl[j]);
    } else if (idx < 40960) {
        int j = idx - 24576;
        int n = j >> 7, k = j & 127;
        split1(wp1[k * 128 + n], g_wp1h[j], g_wp1l[j]);
    }
}

// ================= bf16-split mma.sync GEMM =================
template<bool POOLED, bool STATS>
__global__ __launch_bounds__(256) void k_mma(
    const __nv_bfloat16* __restrict__ Ah, const __nv_bfloat16* __restrict__ Al, long long pA,
    const __nv_bfloat16* __restrict__ B1h, const __nv_bfloat16* __restrict__ B1l,
    const __nv_bfloat16* __restrict__ B2h, const __nv_bfloat16* __restrict__ B2l, long long pB,
    const float* __restrict__ bias, const float* __restrict__ rowscale,
    float* __restrict__ C1, float* __restrict__ C2, int K)
{
    extern __shared__ __align__(16) char smem[];
    __nv_bfloat16* SB = reinterpret_cast<__nv_bfloat16*>(smem);
    float* sstat = reinterpret_cast<float*>(smem + 49152);
    int t = threadIdx.x, lane = t & 31;
    int warpm = ((t >> 5) & 3) * 32, warpn = (t >> 7) * 64;

    const __nv_bfloat16 *Ahb, *Alb, *Bhb, *Blb;
    float* Cb;
    long long m0 = 0;
    if (POOLED) {
        int g = blockIdx.z;
        int half = blockIdx.y >> 3, chunk = blockIdx.y & 7;
        long long ko = (long long)g * 1024 + (long long)chunk * 128;
        Ahb = Ah + ko; Alb = Al + ko;
        Bhb = (half ? B2h : B1h) + ko;
        Blb = (half ? B2l : B1l) + ko;
        Cb = (half ? C2 : C1) + (long long)(chunk * NB + g) * (CH * CH);
    } else {
        m0 = (long long)blockIdx.x * 128;
        Ahb = Ah + m0 * pA; Alb = Al + m0 * pA;
        Bhb = B1h; Blb = B1l;
        Cb = C1 + m0 * 128;
    }
    PDL_ENTRY();
    if (STATS) { sstat[t] = 0.f; }

    uint32_t sbase = smem_u32(SB);
    int sr = t >> 1, sc = t & 1;
    uint32_t dofs = sbase + sr * 48 + sc * 16;
    CP_ASYNC16(dofs,         Ahb + (long long)sr * pA + sc * 8);
    CP_ASYNC16(dofs + 6144,  Alb + (long long)sr * pA + sc * 8);
    CP_ASYNC16(dofs + 12288, Bhb + (long long)sr * pB + sc * 8);
    CP_ASYNC16(dofs + 18432, Blb + (long long)sr * pB + sc * 8);
    CP_COMMIT();

    float c[2][8][4];
#pragma unroll
    for (int i = 0; i < 2; i++)
#pragma unroll
        for (int j = 0; j < 8; j++)
#pragma unroll
            for (int q = 0; q < 4; q++) c[i][j][q] = 0.f;

    int g8 = lane >> 2, kc = (lane & 3) * 2;
    int NT = K >> 4;
    for (int kt = 0; kt < NT; kt++) {
        if (kt + 1 < NT) {
            int k0 = (kt + 1) << 4;
            uint32_t d2 = dofs + ((kt + 1) & 1) * 24576;
            CP_ASYNC16(d2,         Ahb + (long long)sr * pA + k0 + sc * 8);
            CP_ASYNC16(d2 + 6144,  Alb + (long long)sr * pA + k0 + sc * 8);
            CP_ASYNC16(d2 + 12288, Bhb + (long long)sr * pB + k0 + sc * 8);
            CP_ASYNC16(d2 + 18432, Blb + (long long)sr * pB + k0 + sc * 8);
            CP_COMMIT();
            CP_WAIT(1);
        } else {
            CP_WAIT(0);
        }
        __syncthreads();
        const __nv_bfloat16* P = SB + (kt & 1) * 12288;
        uint32_t ah[2][4], al[2][4];
#pragma unroll
        for (int mt = 0; mt < 2; mt++) {
            int mb = warpm + mt * 16 + g8;
            ah[mt][0] = *(const uint32_t*)(P + mb * 24 + kc);
            ah[mt][1] = *(const uint32_t*)(P + (mb + 8) * 24 + kc);
            ah[mt][2] = *(const uint32_t*)(P + mb * 24 + kc + 8);
            ah[mt][3] = *(const uint32_t*)(P + (mb + 8) * 24 + kc + 8);
            al[mt][0] = *(const uint32_t*)(P + 3072 + mb * 24 + kc);
            al[mt][1] = *(const uint32_t*)(P + 3072 + (mb + 8) * 24 + kc);
            al[mt][2] = *(const uint32_t*)(P + 3072 + mb * 24 + kc + 8);
            al[mt][3] = *(const uint32_t*)(P + 3072 + (mb + 8) * 24 + kc + 8);
        }
#pragma unroll
        for (int nt = 0; nt < 8; nt++) {
            int nb = warpn + nt * 8 + g8;
            uint32_t bh0 = *(const uint32_t*)(P + 6144 + nb * 24 + kc);
            uint32_t bh1 = *(const uint32_t*)(P + 6144 + nb * 24 + kc + 8);
            uint32_t bl0 = *(const uint32_t*)(P + 9216 + nb * 24 + kc);
            uint32_t bl1 = *(const uint32_t*)(P + 9216 + nb * 24 + kc + 8);
#pragma unroll
            for (int mt = 0; mt < 2; mt++) {
                MMA_BF16(c[mt][nt], ah[mt][0], ah[mt][1], ah[mt][2], ah[mt][3], bh0, bh1);
                MMA_BF16(c[mt][nt], ah[mt][0], ah[mt][1], ah[mt][2], ah[mt][3], bl0, bl1);
                MMA_BF16(c[mt][nt], al[mt][0], al[mt][1], al[mt][2], al[mt][3], bh0, bh1);
            }
        }
        __syncthreads();
    }

    float cs[8][2], cq[8][2];
    if (STATS) {
#pragma unroll
        for (int j = 0; j < 8; j++) { cs[j][0] = cs[j][1] = 0.f; cq[j][0] = cq[j][1] = 0.f; }
    }
#pragma unroll
    for (int mt = 0; mt < 2; mt++) {
        int row = warpm + mt * 16 + g8;
        float rs0 = rowscale ? rowscale[m0 + row] : 1.f;
        float rs1 = rowscale ? rowscale[m0 + row + 8] : 1.f;
#pragma unroll
        for (int nt = 0; nt < 8; nt++) {
            int col = warpn + nt * 8 + kc;
            float b0 = bias ? bias[col] : 0.f;
            float b1 = bias ? bias[col + 1] : 0.f;
            float v00 = (c[mt][nt][0] + b0) * rs0, v01 = (c[mt][nt][1] + b1) * rs0;
            float v10 = (c[mt][nt][2] + b0) * rs1, v11 = (c[mt][nt][3] + b1) * rs1;
            *reinterpret_cast<float2*>(Cb + (long long)row * 128 + col) = make_float2(v00, v01);
            *reinterpret_cast<float2*>(Cb + (long long)(row + 8) * 128 + col) = make_float2(v10, v11);
            if (STATS) {
                cs[nt][0] += v00 + v10; cq[nt][0] += v00 * v00 + v10 * v10;
                cs[nt][1] += v01 + v11; cq[nt][1] += v01 * v01 + v11 * v11;
            }
        }
    }
    if (STATS) {
        __syncthreads();
#pragma unroll
        for (int nt = 0; nt < 8; nt++) {
            int col = warpn + nt * 8 + kc;
            atomicAdd(&sstat[col], cs[nt][0]);
            atomicAdd(&sstat[col + 1], cs[nt][1]);
            atomicAdd(&sstat[128 + col], cq[nt][0]);
            atomicAdd(&sstat[128 + col + 1], cq[nt][1]);
        }
        __syncthreads();
        if (t < 128) {
            atomicAdd(&g_sumA[t], sstat[t]);
            atomicAdd(&g_ssA[t], sstat[128 + t]);
        }
    }
}

// ================= warp-per-node aggregation (dual accumulators, sentinel pad) =================
template<int MODE>
__global__ __launch_bounds__(256) void k_aggw(
    const float* __restrict__ in, const float* __restrict__ bias, float* __restrict__ out,
    __nv_bfloat16* __restrict__ oTh, __nv_bfloat16* __restrict__ oTl)
{
    __shared__ float sred[8][128];
    __shared__ float st[8][132];
    int t = threadIdx.x, w = t >> 5, lane = t & 31;
    int i = blockIdx.x * 8 + w;
    int e0 = i * SLOTCAP;
    PDL_ENTRY();
    int n = g_deg[i];
    int npad = (n + 7) & ~7;
    if (npad > SLOTCAP) npad = SLOTCAP;
    float4 accA = {0.f, 0.f, 0.f, 0.f}, accB = {0.f, 0.f, 0.f, 0.f};
    for (int c0 = 0; c0 < npad; c0 += 32) {
        int m = npad - c0; if (m > 32) m = 32;
        int src = (lane < m) ? g_srcbuf[e0 + c0 + lane] : 0;
        for (int kk = 0; kk < m; kk += 8) {
#pragma unroll
            for (int u = 0; u < 8; u += 2) {
                int s0 = __shfl_sync(0xffffffffu, src, kk + u);
                int s1 = __shfl_sync(0xffffffffu, src, kk + u + 1);
                float4 h0 = *reinterpret_cast<const float4*>(in + (long long)s0 * 128 + lane * 4);
                float4 h1 = *reinterpret_cast<const float4*>(in + (long long)s1 * 128 + lane * 4);
                accA.x += h0.x; accA.y += h0.y; accA.z += h0.z; accA.w += h0.w;
                accB.x += h1.x; accB.y += h1.y; accB.z += h1.z; accB.w += h1.w;
            }
        }
    }
    float ax = accA.x + accB.x, ay = accA.y + accB.y;
    float az = accA.z + accB.z, aw = accA.w + accB.w;
    float di = g_dinv[i];
    float vx, vy, vz, vw;
    if (MODE != 2) {
        float4 hv = *reinterpret_cast<const float4*>(in + (long long)i * 128 + lane * 4);
        vx = di * (ax + hv.x) + bias[lane * 4 + 0];
        vy = di * (ay + hv.y) + bias[lane * 4 + 1];
        vz = di * (az + hv.z) + bias[lane * 4 + 2];
        vw = di * (aw + hv.w) + bias[lane * 4 + 3];
    } else {
        vx = ax; vy = ay; vz = az; vw = aw;
    }
    if (MODE == 1) {
        float mx = fmaxf(fmaxf(vx, vy), fmaxf(vz, vw));
#pragma unroll
        for (int o = 16; o; o >>= 1) mx = fmaxf(mx, __shfl_xor_sync(0xffffffffu, mx, o));
        vx = __expf(vx - mx); vy = __expf(vy - mx); vz = __expf(vz - mx); vw = __expf(vw - mx);
        float sm = vx + vy + vz + vw;
#pragma unroll
        for (int o = 16; o; o >>= 1) sm += __shfl_xor_sync(0xffffffffu, sm, o);
        float inv = 1.f / sm;
        vx *= inv; vy *= inv; vz *= inv; vw *= inv;
    }
    if (MODE != 2) {
        float4 o4 = { vx, vy, vz, vw };
        *reinterpret_cast<float4*>(out + (long long)i * 128 + lane * 4) = o4;
    }
    if (MODE == 0) {
        sred[w][lane * 4 + 0] = vx; sred[w][lane * 4 + 1] = vy;
        sred[w][lane * 4 + 2] = vz; sred[w][lane * 4 + 3] = vw;
        __syncthreads();
        if (t < 128) {
            float s = 0.f, q = 0.f;
#pragma unroll
            for (int ww = 0; ww < 8; ww++) { float v = sred[ww][t]; s += v; q += v * v; }
            atomicAdd(&g_sumB[t], s);
            atomicAdd(&g_ssB[t], q);
        }
    } else {
        st[w][lane * 4 + 0] = vx; st[w][lane * 4 + 1] = vy;
        st[w][lane * 4 + 2] = vz; st[w][lane * 4 + 3] = vw;
        __syncthreads();
        if (t < 128) {
            int c = t;
            float v0 = st[0][c], v1 = st[1][c], v2 = st[2][c], v3 = st[3][c];
            float v4 = st[4][c], v5 = st[5][c], v6 = st[6][c], v7 = st[7][c];
            long long o = (long long)c * NNODES + blockIdx.x * 8;
            uint4 hv, lv;
            hv.x = pack_hi(v0, v1); hv.y = pack_hi(v2, v3);
            hv.z = pack_hi(v4, v5); hv.w = pack_hi(v6, v7);
            lv.x = pack_lo(v0, v1); lv.y = pack_lo(v2, v3);
            lv.z = pack_lo(v4, v5); lv.w = pack_lo(v6, v7);
            *reinterpret_cast<uint4*>(oTh + o) = hv;
            *reinterpret_cast<uint4*>(oTl + o) = lv;
        }
    }
}

// agg of RAW x (64 ch) with shuffled dinv; warp-uniform tail (no sentinel, no prescale pass)
__global__ __launch_bounds__(256) void k_aggx(const float* __restrict__ x) {
    int t = threadIdx.x, w = t >> 5, lane = t & 31;
    int i = blockIdx.x * 8 + w;
    int e0 = i * SLOTCAP;
    PDL_ENTRY();
    int n = g_deg[i];
    float2 accA = {0.f, 0.f}, accB = {0.f, 0.f};
    int n8 = n & ~7;
    for (int c0 = 0; c0 < n8; c0 += 32) {
        int m = n8 - c0; if (m > 32) m = 32;
        int src = 0; float dv = 0.f;
        if (lane < m) { src = g_srcbuf[e0 + c0 + lane]; dv = g_dinv[src]; }
        for (int kk = 0; kk < m; kk += 8) {
#pragma unroll
            for (int u = 0; u < 8; u += 2) {
                int s0 = __shfl_sync(0xffffffffu, src, kk + u);
                int s1 = __shfl_sync(0xffffffffu, src, kk + u + 1);
                float d0 = __shfl_sync(0xffffffffu, dv, kk + u);
                float d1 = __shfl_sync(0xffffffffu, dv, kk + u + 1);
                float2 h0 = *reinterpret_cast<const float2*>(x + (long long)s0 * 64 + lane * 2);
                float2 h1 = *reinterpret_cast<const float2*>(x + (long long)s1 * 64 + lane * 2);
                accA.x += d0 * h0.x; accA.y += d0 * h0.y;
                accB.x += d1 * h1.x; accB.y += d1 * h1.y;
            }
        }
    }
    // warp-uniform tail (n - n8 < 8 edges)
    for (int e = n8; e < n; e++) {
        int s = g_srcbuf[e0 + e];           // uniform load per warp
        float d = g_dinv[s];
        float2 hv = *reinterpret_cast<const float2*>(x + (long long)s * 64 + lane * 2);
        accA.x += d * hv.x; accA.y += d * hv.y;
    }
    float di = g_dinv[i];
    float2 hv = *reinterpret_cast<const float2*>(x + (long long)i * 64 + lane * 2);
    float ax = di * (accA.x + accB.x + di * hv.x);
    float ay = di * (accA.y + accB.y + di * hv.y);
    long long o = (long long)i * 64 + lane * 2;
    *reinterpret_cast<uint32_t*>(g_axh + o) = pack_hi(ax, ay);
    *reinterpret_cast<uint32_t*>(g_axl + o) = pack_lo(ax, ay);
}

// ================= BN+SiLU(+res) =================
template<bool RES, bool WH, bool WT>
__global__ __launch_bounds__(256) void k_bn(
    const float* __restrict__ y, const float* __restrict__ res, float* __restrict__ h,
    __nv_bfloat16* __restrict__ rh, __nv_bfloat16* __restrict__ rl,
    __nv_bfloat16* __restrict__ th, __nv_bfloat16* __restrict__ tl,
    const float* __restrict__ gw, const float* __restrict__ be,
    const float* __restrict__ sumArr, const float* __restrict__ ssArr)
{
    __shared__ float tile[32][33];
    __shared__ float sc[32], sh[32];
    int t = threadIdx.x;
    int n0 = blockIdx.x * 32, c0 = blockIdx.y * 32;
    PDL_ENTRY();
    if (t < 32) {
        int c = c0 + t;
        float m = sumArr[c] * (1.f / NNODES);
        float var = ssArr[c] * (1.f / NNODES) - m * m;
        float s = gw[c] * rsqrtf(var + 1e-5f);
        sc[t] = s;
        sh[t] = be[c] - s * m;
    }
    __syncthreads();
    int nl = t >> 3, cg = t & 7;
    long long idx = (long long)(n0 + nl) * 128 + c0 + cg * 4;
    float4 v = *reinterpret_cast<const float4*>(y + idx);
    float o0, o1, o2, o3;
    {
        float a;
        a = sc[cg * 4 + 0] * v.x + sh[cg * 4 + 0]; o0 = a / (1.f + __expf(-a));
        a = sc[cg * 4 + 1] * v.y + sh[cg * 4 + 1]; o1 = a / (1.f + __expf(-a));
        a = sc[cg * 4 + 2] * v.z + sh[cg * 4 + 2]; o2 = a / (1.f + __expf(-a));
        a = sc[cg * 4 + 3] * v.w + sh[cg * 4 + 3]; o3 = a / (1.f + __expf(-a));
    }
    if (RES) {
        float4 r = *reinterpret_cast<const float4*>(res + idx);
        o0 += r.x; o1 += r.y; o2 += r.z; o3 += r.w;
    }
    if (WH) {
        float4 ov = { o0, o1, o2, o3 };
        *reinterpret_cast<float4*>(h + idx) = ov;
    }
    {
        uint2 hv, lv;
        hv.x = pack_hi(o0, o1); hv.y = pack_hi(o2, o3);
        lv.x = pack_lo(o0, o1); lv.y = pack_lo(o2, o3);
        *reinterpret_cast<uint2*>(rh + idx) = hv;
        *reinterpret_cast<uint2*>(rl + idx) = lv;
    }
    if (WT) {
        tile[nl][cg * 4 + 0] = o0; tile[nl][cg * 4 + 1] = o1;
        tile[nl][cg * 4 + 2] = o2; tile[nl][cg * 4 + 3] = o3;
        __syncthreads();
        int cc = t >> 3, g = t & 7;
        float w0 = tile[g * 4 + 0][cc], w1 = tile[g * 4 + 1][cc];
        float w2 = tile[g * 4 + 2][cc], w3 = tile[g * 4 + 3][cc];
        long long o = (long long)(c0 + cc) * NNODES + n0 + g * 4;
        uint2 hv, lv;
        hv.x = pack_hi(w0, w1); hv.y = pack_hi(w2, w3);
        lv.x = pack_lo(w0, w1); lv.y = pack_lo(w2, w3);
        *reinterpret_cast<uint2*>(th + o) = hv;
        *reinterpret_cast<uint2*>(tl + o) = lv;
    }
}

// ================= reduce partials + dinv2 + An =================
__global__ __launch_bounds__(256) void k_reduce_an() {
    int b = blockIdx.x, t = threadIdx.x;
    PDL_ENTRY();
    if (b == 0 && t < 128) {
        g_s2a[t] = 0.f; g_q2a[t] = 0.f; g_s2b[t] = 0.f; g_q2b[t] = 0.f;
        if (t == 0) g_bar = 0;
    }
    const long long PS = (long long)NB * CH * CH;
    const long long BO = (long long)b * CH * CH;
    __shared__ float sd[128];
    for (int idx = t; idx < CH * CH; idx += 256) {
        float s = 0.f;
#pragma unroll
        for (int p = 0; p < 8; p++) s += g_xpart[p * PS + BO + idx];
        g_x2[BO + idx] = s;
    }
    int w = t >> 5, lane = t & 31;
    for (int r = w; r < 128; r += 8) {
        float rsum = 0.f;
#pragma unroll
        for (int q = 0; q < 4; q++) {
            int idx = r * 128 + lane + q * 32;
            float s = 0.f;
#pragma unroll
            for (int p = 0; p < 8; p++) s += g_apart[p * PS + BO + idx];
            g_A2[BO + idx] = s;
            rsum += s;
        }
#pragma unroll
        for (int o = 16; o; o >>= 1) rsum += __shfl_down_sync(0xffffffffu, rsum, o);
        if (lane == 0) sd[r] = rsqrtf(rsum + 1.0f);
    }
    __syncthreads();
    for (int idx = t; idx < CH * CH; idx += 256) {
        int i = idx >> 7, j = idx & 127;
        float v = g_A2[BO + idx] + (i == j ? 1.f : 0.f);
        g_An[BO + idx] = sd[i] * v * sd[j];
    }
}

// ================= fused stack-2 (FFMA2, 32 blocks, grid barrier) =================
__device__ __forceinline__ void gridbar(int target) {
    __syncthreads();
    __threadfence();
    if (threadIdx.x == 0) {
        atomicAdd(&g_bar, 1);
        while (*(volatile int*)&g_bar < target) __nanosleep(64);
    }
    __syncthreads();
    __threadfence();
}

__device__ __forceinline__ void gemm_sm128(const float* __restrict__ P, const float* __restrict__ Q,
                                           unsigned long long acc2[8][4], int tx, int ty)
{
#pragma unroll
    for (int i = 0; i < 8; i++)
#pragma unroll
        for (int j = 0; j < 4; j++) acc2[i][j] = 0ull;
#pragma unroll 2
    for (int k = 0; k < 128; k++) {
        float a[8];
#pragma unroll
        for (int i = 0; i < 8; i++) a[i] = P[(ty * 8 + i) * 128 + k];
        const unsigned long long* Qp =
            reinterpret_cast<const unsigned long long*>(&Q[k * 128 + tx * 8]);
        unsigned long long b0 = Qp[0], b1 = Qp[1], b2 = Qp[2], b3 = Qp[3];
#pragma unroll
        for (int i = 0; i < 8; i++) {
            unsigned long long ad = dup_f32(a[i]);
            ffma2(acc2[i][0], ad, b0);
            ffma2(acc2[i][1], ad, b1);
            ffma2(acc2[i][2], ad, b2);
            ffma2(acc2[i][3], ad, b3);
        }
    }
}

__global__ __launch_bounds__(256) void k_stack2(
    const float* __restrict__ w2a, const float* __restrict__ b2a,
    const float* __restrict__ g2a, const float* __restrict__ be2a,
    const float* __restrict__ w2b, const float* __restrict__ b2b,
    const float* __restrict__ g2b, const float* __restrict__ be2b,
    const float* __restrict__ wl, const float* __restrict__ bl,
    float* __restrict__ out, int out_size)
{
    extern __shared__ __align__(16) float sm2[];
    float* AN = sm2;
    float* XB = sm2 + 16384;
    float* WB = sm2 + 32768;
    __shared__ float red[2048];
    __shared__ float gv[128];
    __shared__ float lg[10];
    __shared__ float lse;
    int b = blockIdx.x, t = threadIdx.x, tx = t & 15, ty = t >> 4;
    const float INVN = 1.f / (NB * CH);
    PDL_ENTRY();

    {
        const float4* pAn = (const float4*)(g_An + (long long)b * 16384);
        const float4* pX2 = (const float4*)(g_x2 + (long long)b * 16384);
        const float4* pWa = (const float4*)w2a;
        float4* An4 = (float4*)AN; float4* X4 = (float4*)XB; float4* W4 = (float4*)WB;
        for (int i = t; i < 4096; i += 256) { An4[i] = pAn[i]; X4[i] = pX2[i]; W4[i] = pWa[i]; }
    }
    __syncthreads();

    unsigned long long acc2[8][4];
    float cs[8], cq[8];

    gemm_sm128(XB, WB, acc2, tx, ty);
    __syncthreads();
#pragma unroll
    for (int i = 0; i < 8; i++)
#pragma unroll
        for (int j = 0; j < 4; j++) {
            float2 p = u2f(acc2[i][j]);
            XB[(ty * 8 + i) * 128 + tx * 8 + 2 * j] = p.x;
            XB[(ty * 8 + i) * 128 + tx * 8 + 2 * j + 1] = p.y;
        }
    __syncthreads();

    gemm_sm128(AN, XB, acc2, tx, ty);
    __syncthreads();
#pragma unroll
    for (int j = 0; j < 8; j++) { cs[j] = 0.f; cq[j] = 0.f; }
#pragma unroll
    for (int i = 0; i < 8; i++)
#pragma unroll
        for (int j = 0; j < 4; j++) {
            float2 p = u2f(acc2[i][j]);
            float v0 = p.x + b2a[tx * 8 + 2 * j];
            float v1 = p.y + b2a[tx * 8 + 2 * j + 1];
            WB[(ty * 8 + i) * 128 + tx * 8 + 2 * j] = v0;
            WB[(ty * 8 + i) * 128 + tx * 8 + 2 * j + 1] = v1;
            cs[2 * j] += v0; cq[2 * j] += v0 * v0;
            cs[2 * j + 1] += v1; cq[2 * j + 1] += v1 * v1;
        }
#pragma unroll
    for (int j = 0; j < 8; j++) red[ty * 128 + tx * 8 + j] = cs[j];
    __syncthreads();
    if (t < 128) { float s = 0.f; for (int g = 0; g < 16; g++) s += red[g * 128 + t]; atomicAdd(&g_s2a[t], s); }
    __syncthreads();
#pragma unroll
    for (int j = 0; j < 8; j++) red[ty * 128 + tx * 8 + j] = cq[j];
    __syncthreads();
    if (t < 128) { float s = 0.f; for (int g = 0; g < 16; g++) s += red[g * 128 + t]; atomicAdd(&g_q2a[t], s); }

    gridbar(NB);

    float scv[8], shv[8];
#pragma unroll
    for (int j = 0; j < 8; j++) {
        int c = tx * 8 + j;
        float m = g_s2a[c] * INVN;
        float var = g_q2a[c] * INVN - m * m;
        float s = g2a[c] * rsqrtf(var + 1e-5f);
        scv[j] = s; shv[j] = be2a[c] - s * m;
    }
#pragma unroll
    for (int i = 0; i < 8; i++)
#pragma unroll
        for (int j = 0; j < 8; j++) {
            float v = WB[(ty * 8 + i) * 128 + tx * 8 + j];
            v = scv[j] * v + shv[j];
            v = v / (1.f + __expf(-v));
            XB[(ty * 8 + i) * 128 + tx * 8 + j] = v;
        }
    __syncthreads();

    {
        const float4* pWb = (const float4*)w2b;
        float4* W4 = (float4*)WB;
        for (int i = t; i < 4096; i += 256) W4[i] = pWb[i];
    }
    __syncthreads();

    gemm_sm128(XB, WB, acc2, tx, ty);
    __syncthreads();
#pragma unroll
    for (int i = 0; i < 8; i++)
#pragma unroll
        for (int j = 0; j < 4; j++) {
            float2 p = u2f(acc2[i][j]);
            WB[(ty * 8 + i) * 128 + tx * 8 + 2 * j] = p.x;
            WB[(ty * 8 + i) * 128 + tx * 8 + 2 * j + 1] = p.y;
        }
    __syncthreads();

    gemm_sm128(AN, WB, acc2, tx, ty);
#pragma unroll
    for (int j = 0; j < 8; j++) { cs[j] = 0.f; cq[j] = 0.f; }
#pragma unroll
    for (int i = 0; i < 8; i++)
#pragma unroll
        for (int j = 0; j < 4; j++) {
            float2 p = u2f(acc2[i][j]);
            float v0 = p.x + b2b[tx * 8 + 2 * j];
            float v1 = p.y + b2b[tx * 8 + 2 * j + 1];
            cs[2 * j] += v0; cq[2 * j] += v0 * v0;
            cs[2 * j + 1] += v1; cq[2 * j + 1] += v1 * v1;
        }
    __syncthreads();
#pragma unroll
    for (int j = 0; j < 8; j++) red[ty * 128 + tx * 8 + j] = cs[j];
    __syncthreads();
    if (t < 128) { float s = 0.f; for (int g = 0; g < 16; g++) s += red[g * 128 + t]; atomicAdd(&g_s2b[t], s); }
    __syncthreads();
#pragma unroll
    for (int j = 0; j < 8; j++) red[ty * 128 + tx * 8 + j] = cq[j];
    __syncthreads();
    if (t < 128) { float s = 0.f; for (int g = 0; g < 16; g++) s += red[g * 128 + t]; atomicAdd(&g_q2b[t], s); }

    gridbar(2 * NB);

#pragma unroll
    for (int j = 0; j < 8; j++) {
        int c = tx * 8 + j;
        float m = g_s2b[c] * INVN;
        float var = g_q2b[c] * INVN - m * m;
        float s = g2b[c] * rsqrtf(var + 1e-5f);
        scv[j] = s; shv[j] = be2b[c] - s * m;
    }
    float colsum[8];
#pragma unroll
    for (int j = 0; j < 8; j++) colsum[j] = 0.f;
#pragma unroll
    for (int i = 0; i < 8; i++)
#pragma unroll
        for (int j = 0; j < 4; j++) {
            float2 p = u2f(acc2[i][j]);
            float v0 = scv[2 * j] * (p.x + b2b[tx * 8 + 2 * j]) + shv[2 * j];
            float v1 = scv[2 * j + 1] * (p.y + b2b[tx * 8 + 2 * j + 1]) + shv[2 * j + 1];
            v0 = v0 / (1.f + __expf(-v0));
            v1 = v1 / (1.f + __expf(-v1));
            v0 += XB[(ty * 8 + i) * 128 + tx * 8 + 2 * j];
            v1 += XB[(ty * 8 + i) * 128 + tx * 8 + 2 * j + 1];
            colsum[2 * j] += v0;
            colsum[2 * j + 1] += v1;
        }
    __syncthreads();
#pragma unroll
    for (int j = 0; j < 8; j++) red[ty * 128 + tx * 8 + j] = colsum[j];
    __syncthreads();
    if (t < 128) {
        float s = 0.f;
        for (int g = 0; g < 16; g++) s += red[g * 128 + t];
        gv[t] = s * (1.f / 32.f);
    }
    __syncthreads();
    if (t < 10) {
        float a = bl[t];
        for (int k = 0; k < 128; k++) a += gv[k] * wl[k * 10 + t];
        lg[t] = a;
    }
    __syncthreads();
    if (t == 0) {
        float mx = -1e30f;
        for (int j = 0; j < 10; j++) mx = fmaxf(mx, lg[j]);
        float se = 0.f;
        for (int j = 0; j < 10; j++) se += expf(lg[j] - mx);
        lse = mx + logf(se);
    }
    __syncthreads();
    if (t < 10) {
        int o = b * 10 + t;
        if (o < out_size) out[o] = lg[t] - lse;
    }
    if (b == 0) {
        for (int idx = NB * 10 + t; idx < out_size; idx += 256) out[idx] = 0.f;
    }
}

// ================= host orchestration =================
extern "C" void kernel_launch(void* const* d_in, const int* in_sizes, int n_in,
                              void* d_out, int out_size) {
    const float* x    = (const float*)d_in[0];
    const int*   ei   = (const int*)  d_in[1];
    const float* w1a  = (const float*)d_in[4];
    const float* b1a  = (const float*)d_in[5];
    const float* g1a  = (const float*)d_in[6];
    const float* be1a = (const float*)d_in[7];
    const float* w1b  = (const float*)d_in[8];
    const float* b1b  = (const float*)d_in[9];
    const float* g1b  = (const float*)d_in[10];
    const float* be1b = (const float*)d_in[11];
    const float* wp1  = (const float*)d_in[12];
    const float* bp1  = (const float*)d_in[13];
    const float* w2a  = (const float*)d_in[14];
    const float* b2a  = (const float*)d_in[15];
    const float* g2a  = (const float*)d_in[16];
    const float* be2a = (const float*)d_in[17];
    const float* w2b  = (const float*)d_in[18];
    const float* b2b  = (const float*)d_in[19];
    const float* g2b  = (const float*)d_in[20];
    const float* be2b = (const float*)d_in[21];
    const float* wl   = (const float*)d_in[24];
    const float* bl   = (const float*)d_in[25];
    float* outp = (float*)d_out;
    (void)n_in; (void)in_sizes;

    float *p_lin, *p_y, *p_h, *p_s, *p_xpart, *p_apart;
    float *p_sumA, *p_ssA, *p_sumB, *p_ssB, *p_dinv;
    __nv_bfloat16 *p_axh, *p_axl, *p_hah, *p_hal, *p_hbh, *p_hbl;
    __nv_bfloat16 *p_hTh, *p_hTl, *p_sTh, *p_sTl, *p_tTh, *p_tTl;
    __nv_bfloat16 *p_w1ah, *p_w1al, *p_w1bh, *p_w1bl, *p_wp1h, *p_wp1l;
    cudaGetSymbolAddress((void**)&p_lin,   g_lin);
    cudaGetSymbolAddress((void**)&p_y,     g_y);
    cudaGetSymbolAddress((void**)&p_h,     g_h);
    cudaGetSymbolAddress((void**)&p_s,     g_s);
    cudaGetSymbolAddress((void**)&p_xpart, g_xpart);
    cudaGetSymbolAddress((void**)&p_apart, g_apart);
    cudaGetSymbolAddress((void**)&p_sumA,  g_sumA);
    cudaGetSymbolAddress((void**)&p_ssA,   g_ssA);
    cudaGetSymbolAddress((void**)&p_sumB,  g_sumB);
    cudaGetSymbolAddress((void**)&p_ssB,   g_ssB);
    cudaGetSymbolAddress((void**)&p_dinv,  g_dinv);
    cudaGetSymbolAddress((void**)&p_axh,   g_axh);
    cudaGetSymbolAddress((void**)&p_axl,   g_axl);
    cudaGetSymbolAddress((void**)&p_hah,   g_hah);
    cudaGetSymbolAddress((void**)&p_hal,   g_hal);
    cudaGetSymbolAddress((void**)&p_hbh,   g_hbh);
    cudaGetSymbolAddress((void**)&p_hbl,   g_hbl);
    cudaGetSymbolAddress((void**)&p_hTh,   g_hTh);
    cudaGetSymbolAddress((void**)&p_hTl,   g_hTl);
    cudaGetSymbolAddress((void**)&p_sTh,   g_sTh);
    cudaGetSymbolAddress((void**)&p_sTl,   g_sTl);
    cudaGetSymbolAddress((void**)&p_tTh,   g_tTh);
    cudaGetSymbolAddress((void**)&p_tTl,   g_tTl);
    cudaGetSymbolAddress((void**)&p_w1ah,  g_w1ah);
    cudaGetSymbolAddress((void**)&p_w1al,  g_w1al);
    cudaGetSymbolAddress((void**)&p_w1bh,  g_w1bh);
    cudaGetSymbolAddress((void**)&p_w1bl,  g_w1bl);
    cudaGetSymbolAddress((void**)&p_wp1h,  g_wp1h);
    cudaGetSymbolAddress((void**)&p_wp1l,  g_wp1l);

    static bool attrDone = false;
    if (!attrDone) {
        cudaFuncSetAttribute(k_stack2, cudaFuncAttributeMaxDynamicSharedMemorySize, 196608);
        cudaFuncSetAttribute(k_mma<false, true>,  cudaFuncAttributeMaxDynamicSharedMemorySize, 50176);
        cudaFuncSetAttribute(k_mma<false, false>, cudaFuncAttributeMaxDynamicSharedMemorySize, 50176);
        cudaFuncSetAttribute(k_mma<true, false>,  cudaFuncAttributeMaxDynamicSharedMemorySize, 50176);
        attrDone = true;
    }

    cudaLaunchAttribute pdl[1];
    pdl[0].id = cudaLaunchAttributeProgrammaticStreamSerialization;
    pdl[0].val.programmaticStreamSerializationAllowed = 1;
    auto cfg = [&](dim3 g, dim3 b, size_t smem) {
        cudaLaunchConfig_t c = {};
        c.gridDim = g; c.blockDim = b; c.dynamicSmemBytes = smem;
        c.stream = 0; c.attrs = pdl; c.numAttrs = 1;
        return c;
    };

    // graph structure + weight split (no x prescale pass)
    { auto c = cfg(dim3(NNODES / 256), dim3(256), 0); cudaLaunchKernelEx(&c, k_zero_deg); }
    { auto c = cfg(dim3(NEDGES / 512), dim3(256), 0); cudaLaunchKernelEx(&c, k_build, ei); }
    { auto c = cfg(dim3(160), dim3(256), 0); cudaLaunchKernelEx(&c, k_wsplit, w1a, w1b, wp1); }

    // stack 1, layer a (aggx gathers raw x with shuffled dinv)
    { auto c = cfg(dim3(NNODES / 8), dim3(256), 0); cudaLaunchKernelEx(&c, k_aggx, x); }
    { auto c = cfg(dim3(256), dim3(256), 50176);
      cudaLaunchKernelEx(&c, k_mma<false, true>,
          (const __nv_bfloat16*)p_axh, (const __nv_bfloat16*)p_axl, (long long)64,
          (const __nv_bfloat16*)p_w1ah, (const __nv_bfloat16*)p_w1al,
          (const __nv_bfloat16*)nullptr, (const __nv_bfloat16*)nullptr, (long long)64,
          b1a, (const float*)nullptr, p_y, (float*)nullptr, 64); }
    { auto c = cfg(dim3(NNODES / 32, 4), dim3(256), 0);
      cudaLaunchKernelEx(&c, k_bn<false, true, false>,
          (const float*)p_y, (const float*)nullptr, p_h, p_hah, p_hal,
          (__nv_bfloat16*)nullptr, (__nv_bfloat16*)nullptr, g1a, be1a,
          (const float*)p_sumA, (const float*)p_ssA); }

    // stack 1, layer b (residual); GEMM output prescaled by dinv
    { auto c = cfg(dim3(256), dim3(256), 50176);
      cudaLaunchKernelEx(&c, k_mma<false, false>,
          (const __nv_bfloat16*)p_hah, (const __nv_bfloat16*)p_hal, (long long)128,
          (const __nv_bfloat16*)p_w1bh, (const __nv_bfloat16*)p_w1bl,
          (const __nv_bfloat16*)nullptr, (const __nv_bfloat16*)nullptr, (long long)128,
          (const float*)nullptr, (const float*)p_dinv, p_lin, (float*)nullptr, 128); }
    { auto c = cfg(dim3(NNODES / 8), dim3(256), 0);
      cudaLaunchKernelEx(&c, k_aggw<0>, (const float*)p_lin, b1b, p_y,
          (__nv_bfloat16*)nullptr, (__nv_bfloat16*)nullptr); }
    { auto c = cfg(dim3(NNODES / 32, 4), dim3(256), 0);
      cudaLaunchKernelEx(&c, k_bn<true, false, true>,
          (const float*)p_y, (const float*)p_h, (float*)nullptr, p_hbh, p_hbl,
          p_hTh, p_hTl, g1b, be1b, (const float*)p_sumB, (const float*)p_ssB); }

    // pooling 1
    { auto c = cfg(dim3(256), dim3(256), 50176);
      cudaLaunchKernelEx(&c, k_mma<false, false>,
          (const __nv_bfloat16*)p_hbh, (const __nv_bfloat16*)p_hbl, (long long)128,
          (const __nv_bfloat16*)p_wp1h, (const __nv_bfloat16*)p_wp1l,
          (const __nv_bfloat16*)nullptr, (const __nv_bfloat16*)nullptr, (long long)128,
          (const float*)nullptr, (const float*)p_dinv, p_lin, (float*)nullptr, 128); }
    { auto c = cfg(dim3(NNODES / 8), dim3(256), 0);
      cudaLaunchKernelEx(&c, k_aggw<1>, (const float*)p_lin, bp1, p_s, p_sTh, p_sTl); }
    { auto c = cfg(dim3(NNODES / 8), dim3(256), 0);
      cudaLaunchKernelEx(&c, k_aggw<2>, (const float*)p_s, (const float*)nullptr,
          (float*)nullptr, p_tTh, p_tTl); }

    // pooled einsums + reduce/An
    { auto c = cfg(dim3(1, 16, NB), dim3(256), 50176);
      cudaLaunchKernelEx(&c, k_mma<true, false>,
          (const __nv_bfloat16*)p_sTh, (const __nv_bfloat16*)p_sTl, (long long)NNODES,
          (const __nv_bfloat16*)p_hTh, (const __nv_bfloat16*)p_hTl,
          (const __nv_bfloat16*)p_tTh, (const __nv_bfloat16*)p_tTl, (long long)NNODES,
          (const float*)nullptr, (const float*)nullptr, p_xpart, p_apart, 128); }
    { auto c = cfg(dim3(NB), dim3(256), 0); cudaLaunchKernelEx(&c, k_reduce_an); }

    // fused stack 2 (FFMA2) + head
    { auto c = cfg(dim3(NB), dim3(256), 196608);
      cudaLaunchKernelEx(&c, k_stack2, w2a, b2a, g2a, be2a, w2b, b2b, g2b, be2b,
          wl, bl, outp, out_size); }
}

// round 15
// speedup vs baseline: 1.0435x; 1.0035x over previous
#include <cuda_runtime.h>
#include <cuda_bf16.h>
#include <math.h>
#include <stdint.h>

#define NNODES 32768
#define NEDGES 524288
#define NB     32
#define NPG    1024
#define CH     128
#define CIN    64
#define SLOTCAP 72
#define P2     132   // stack2 smem pitch (floats): 132%4==0 (alignment), 132%32==4 (bank spread)

// PDL entry: allow successor to spin up, then wait for predecessor's data.
#define PDL_ENTRY() do { \
    cudaTriggerProgrammaticLaunchCompletion(); \
    cudaGridDependencySynchronize(); \
} while (0)

// ================= helpers =================
__device__ __forceinline__ uint32_t smem_u32(const void* p) {
    uint32_t a;
    asm("{ .reg .u64 t; cvta.to.shared.u64 t, %1; cvt.u32.u64 %0, t; }" : "=r"(a) : "l"(p));
    return a;
}
__device__ __forceinline__ void ffma2(unsigned long long& d, unsigned long long a, unsigned long long b) {
    asm("fma.rn.f32x2 %0, %1, %2, %0;" : "+l"(d) : "l"(a), "l"(b));
}
__device__ __forceinline__ unsigned long long dup_f32(float v) {
    unsigned long long r;
    asm("mov.b64 %0, {%1, %1};" : "=l"(r) : "f"(v));
    return r;
}
__device__ __forceinline__ float2 u2f(unsigned long long v) {
    float2 f;
    asm("mov.b64 {%0, %1}, %2;" : "=f"(f.x), "=f"(f.y) : "l"(v));
    return f;
}
#define CP_ASYNC16(dst, src) asm volatile("cp.async.ca.shared.global [%0], [%1], 16;" :: "r"(dst), "l"(src))
#define CP_COMMIT()          asm volatile("cp.async.commit_group;" ::: "memory")
#define CP_WAIT(n)           asm volatile("cp.async.wait_group %0;" :: "n"(n) : "memory")

#define MMA_BF16(cf, a0, a1, a2, a3, b0, b1) \
    asm volatile("mma.sync.aligned.m16n8k16.row.col.f32.bf16.bf16.f32 " \
        "{%0,%1,%2,%3},{%4,%5,%6,%7},{%8,%9},{%0,%1,%2,%3};" \
        : "+f"((cf)[0]), "+f"((cf)[1]), "+f"((cf)[2]), "+f"((cf)[3]) \
        : "r"(a0), "r"(a1), "r"(a2), "r"(a3), "r"(b0), "r"(b1))

__device__ __forceinline__ uint32_t pack_hi(float a, float b) {
    __nv_bfloat162 h;
    h.x = __float2bfloat16_rn(a); h.y = __float2bfloat16_rn(b);
    return *reinterpret_cast<uint32_t*>(&h);
}
__device__ __forceinline__ uint32_t pack_lo(float a, float b) {
    __nv_bfloat16 ha = __float2bfloat16_rn(a), hb = __float2bfloat16_rn(b);
    __nv_bfloat162 l;
    l.x = __float2bfloat16_rn(a - __bfloat162float(ha));
    l.y = __float2bfloat16_rn(b - __bfloat162float(hb));
    return *reinterpret_cast<uint32_t*>(&l);
}
__device__ __forceinline__ void split1(float v, __nv_bfloat16& h, __nv_bfloat16& l) {
    h = __float2bfloat16_rn(v);
    l = __float2bfloat16_rn(v - __bfloat162float(h));
}

// ================= device scratch =================
__device__ int   g_deg[NNODES];
__device__ int   g_srcbuf[NNODES * SLOTCAP];
__device__ float g_dinv[NNODES];

__device__ float g_lin[(NNODES + 8) * CH];
__device__ float g_s  [(NNODES + 8) * CH];
__device__ float g_y  [NNODES * CH];
__device__ float g_h  [NNODES * CH];

__device__ __align__(16) __nv_bfloat16 g_axh[NNODES * CIN], g_axl[NNODES * CIN];
__device__ __align__(16) __nv_bfloat16 g_hah[NNODES * CH],  g_hal[NNODES * CH];
__device__ __align__(16) __nv_bfloat16 g_hbh[NNODES * CH],  g_hbl[NNODES * CH];
__device__ __align__(16) __nv_bfloat16 g_hTh[CH * NNODES],  g_hTl[CH * NNODES];
__device__ __align__(16) __nv_bfloat16 g_sTh[CH * NNODES],  g_sTl[CH * NNODES];
__device__ __align__(16) __nv_bfloat16 g_tTh[CH * NNODES],  g_tTl[CH * NNODES];
__device__ __align__(16) __nv_bfloat16 g_w1ah[CH * CIN], g_w1al[CH * CIN];
__device__ __align__(16) __nv_bfloat16 g_w1bh[CH * CH],  g_w1bl[CH * CH];
__device__ __align__(16) __nv_bfloat16 g_wp1h[CH * CH],  g_wp1l[CH * CH];

__device__ float g_xpart[8 * NB * CH * CH];
__device__ float g_apart[8 * NB * CH * CH];
__device__ float g_x2  [NB * CH * CH];
__device__ float g_A2  [NB * CH * CH];
__device__ float g_An  [NB * CH * CH];

__device__ float g_sumA[CH], g_ssA[CH], g_sumB[CH], g_ssB[CH];
__device__ float g_s2a[CH], g_q2a[CH], g_s2b[CH], g_q2b[CH];
__device__ int   g_bar;

// ================= graph structure (one-pass bucket CSR) =================
__global__ void k_zero_deg() {
    int i = blockIdx.x * 256 + threadIdx.x;
    cudaTriggerProgrammaticLaunchCompletion();
    g_deg[i] = 0;
    if (i < 128) { g_sumA[i] = 0.f; g_ssA[i] = 0.f; g_sumB[i] = 0.f; g_ssB[i] = 0.f; }
}
__global__ void k_build(const int* __restrict__ ei) {
    int e = (blockIdx.x * 256 + threadIdx.x) * 2;
    PDL_ENTRY();
    if (e < NEDGES) {
        int s0 = ei[e], s1 = ei[e + 1];
        int d0 = ei[NEDGES + e], d1 = ei[NEDGES + e + 1];
        int p0 = atomicAdd(&g_deg[d0], 1);
        int p1 = atomicAdd(&g_deg[d1], 1);
        g_srcbuf[d0 * SLOTCAP + p0] = s0;
        g_srcbuf[d1 * SLOTCAP + p1] = s1;
    }
}

__global__ void k_wsplit(const float* __restrict__ w1a, const float* __restrict__ w1b,
                         const float* __restrict__ wp1) {
    int idx = blockIdx.x * 256 + threadIdx.x;
    PDL_ENTRY();
    if (idx < NNODES) {
        int deg = g_deg[idx];
        g_dinv[idx] = rsqrtf((float)deg + 1.0f);
        int npad = (deg + 7) & ~7;
        if (npad > SLOTCAP) npad = SLOTCAP;
        for (int p = deg; p < npad; p++) g_srcbuf[idx * SLOTCAP + p] = NNODES;
    }
    if (idx < 8192) {
        int n = idx >> 6, k = idx & 63;
        split1(w1a[k * 128 + n], g_w1ah[idx], g_w1al[idx]);
    } else if (idx < 24576) {
        int j = idx - 8192;
        int n = j >> 7, k = j & 127;
        split1(w1b[k * 128 + n], g_w1bh[j], g_w1bl[j]);
    } else if (idx < 40960) {
        int j = idx - 24576;
        int n = j >> 7, k = j & 127;
        split1(wp1[k * 128 + n], g_wp1h[j], g_wp1l[j]);
    }
}

// ================= bf16-split mma.sync GEMM =================
template<bool POOLED, bool STATS>
__global__ __launch_bounds__(256) void k_mma(
    const __nv_bfloat16* __restrict__ Ah, const __nv_bfloat16* __restrict__ Al, long long pA,
    const __nv_bfloat16* __restrict__ B1h, const __nv_bfloat16* __restrict__ B1l,
    const __nv_bfloat16* __restrict__ B2h, const __nv_bfloat16* __restrict__ B2l, long long pB,
    const float* __restrict__ bias, const float* __restrict__ rowscale,
    float* __restrict__ C1, float* __restrict__ C2, int K)
{
    extern __shared__ __align__(16) char smem[];
    __nv_bfloat16* SB = reinterpret_cast<__nv_bfloat16*>(smem);
    float* sstat = reinterpret_cast<float*>(smem + 49152);
    int t = threadIdx.x, lane = t & 31;
    int warpm = ((t >> 5) & 3) * 32, warpn = (t >> 7) * 64;

    const __nv_bfloat16 *Ahb, *Alb, *Bhb, *Blb;
    float* Cb;
    long long m0 = 0;
    if (POOLED) {
        int g = blockIdx.z;
        int half = blockIdx.y >> 3, chunk = blockIdx.y & 7;
        long long ko = (long long)g * 1024 + (long long)chunk * 128;
        Ahb = Ah + ko; Alb = Al + ko;
        Bhb = (half ? B2h : B1h) + ko;
        Blb = (half ? B2l : B1l) + ko;
        Cb = (half ? C2 : C1) + (long long)(chunk * NB + g) * (CH * CH);
    } else {
        m0 = (long long)blockIdx.x * 128;
        Ahb = Ah + m0 * pA; Alb = Al + m0 * pA;
        Bhb = B1h; Blb = B1l;
        Cb = C1 + m0 * 128;
    }
    PDL_ENTRY();
    if (STATS) { sstat[t] = 0.f; }

    uint32_t sbase = smem_u32(SB);
    int sr = t >> 1, sc = t & 1;
    uint32_t dofs = sbase + sr * 48 + sc * 16;
    CP_ASYNC16(dofs,         Ahb + (long long)sr * pA + sc * 8);
    CP_ASYNC16(dofs + 6144,  Alb + (long long)sr * pA + sc * 8);
    CP_ASYNC16(dofs + 12288, Bhb + (long long)sr * pB + sc * 8);
    CP_ASYNC16(dofs + 18432, Blb + (long long)sr * pB + sc * 8);
    CP_COMMIT();

    float c[2][8][4];
#pragma unroll
    for (int i = 0; i < 2; i++)
#pragma unroll
        for (int j = 0; j < 8; j++)
#pragma unroll
            for (int q = 0; q < 4; q++) c[i][j][q] = 0.f;

    int g8 = lane >> 2, kc = (lane & 3) * 2;
    int NT = K >> 4;
    for (int kt = 0; kt < NT; kt++) {
        if (kt + 1 < NT) {
            int k0 = (kt + 1) << 4;
            uint32_t d2 = dofs + ((kt + 1) & 1) * 24576;
            CP_ASYNC16(d2,         Ahb + (long long)sr * pA + k0 + sc * 8);
            CP_ASYNC16(d2 + 6144,  Alb + (long long)sr * pA + k0 + sc * 8);
            CP_ASYNC16(d2 + 12288, Bhb + (long long)sr * pB + k0 + sc * 8);
            CP_ASYNC16(d2 + 18432, Blb + (long long)sr * pB + k0 + sc * 8);
            CP_COMMIT();
            CP_WAIT(1);
        } else {
            CP_WAIT(0);
        }
        __syncthreads();
        const __nv_bfloat16* P = SB + (kt & 1) * 12288;
        uint32_t ah[2][4], al[2][4];
#pragma unroll
        for (int mt = 0; mt < 2; mt++) {
            int mb = warpm + mt * 16 + g8;
            ah[mt][0] = *(const uint32_t*)(P + mb * 24 + kc);
            ah[mt][1] = *(const uint32_t*)(P + (mb + 8) * 24 + kc);
            ah[mt][2] = *(const uint32_t*)(P + mb * 24 + kc + 8);
            ah[mt][3] = *(const uint32_t*)(P + (mb + 8) * 24 + kc + 8);
            al[mt][0] = *(const uint32_t*)(P + 3072 + mb * 24 + kc);
            al[mt][1] = *(const uint32_t*)(P + 3072 + (mb + 8) * 24 + kc);
            al[mt][2] = *(const uint32_t*)(P + 3072 + mb * 24 + kc + 8);
            al[mt][3] = *(const uint32_t*)(P + 3072 + (mb + 8) * 24 + kc + 8);
        }
#pragma unroll
        for (int nt = 0; nt < 8; nt++) {
            int nb = warpn + nt * 8 + g8;
            uint32_t bh0 = *(const uint32_t*)(P + 6144 + nb * 24 + kc);
            uint32_t bh1 = *(const uint32_t*)(P + 6144 + nb * 24 + kc + 8);
            uint32_t bl0 = *(const uint32_t*)(P + 9216 + nb * 24 + kc);
            uint32_t bl1 = *(const uint32_t*)(P + 9216 + nb * 24 + kc + 8);
#pragma unroll
            for (int mt = 0; mt < 2; mt++) {
                MMA_BF16(c[mt][nt], ah[mt][0], ah[mt][1], ah[mt][2], ah[mt][3], bh0, bh1);
                MMA_BF16(c[mt][nt], ah[mt][0], ah[mt][1], ah[mt][2], ah[mt][3], bl0, bl1);
                MMA_BF16(c[mt][nt], al[mt][0], al[mt][1], al[mt][2], al[mt][3], bh0, bh1);
            }
        }
        __syncthreads();
    }

    float cs[8][2], cq[8][2];
    if (STATS) {
#pragma unroll
        for (int j = 0; j < 8; j++) { cs[j][0] = cs[j][1] = 0.f; cq[j][0] = cq[j][1] = 0.f; }
    }
#pragma unroll
    for (int mt = 0; mt < 2; mt++) {
        int row = warpm + mt * 16 + g8;
        float rs0 = rowscale ? rowscale[m0 + row] : 1.f;
        float rs1 = rowscale ? rowscale[m0 + row + 8] : 1.f;
#pragma unroll
        for (int nt = 0; nt < 8; nt++) {
            int col = warpn + nt * 8 + kc;
            float b0 = bias ? bias[col] : 0.f;
            float b1 = bias ? bias[col + 1] : 0.f;
            float v00 = (c[mt][nt][0] + b0) * rs0, v01 = (c[mt][nt][1] + b1) * rs0;
            float v10 = (c[mt][nt][2] + b0) * rs1, v11 = (c[mt][nt][3] + b1) * rs1;
            *reinterpret_cast<float2*>(Cb + (long long)row * 128 + col) = make_float2(v00, v01);
            *reinterpret_cast<float2*>(Cb + (long long)(row + 8) * 128 + col) = make_float2(v10, v11);
            if (STATS) {
                cs[nt][0] += v00 + v10; cq[nt][0] += v00 * v00 + v10 * v10;
                cs[nt][1] += v01 + v11; cq[nt][1] += v01 * v01 + v11 * v11;
            }
        }
    }
    if (STATS) {
        __syncthreads();
#pragma unroll
        for (int nt = 0; nt < 8; nt++) {
            int col = warpn + nt * 8 + kc;
            atomicAdd(&sstat[col], cs[nt][0]);
            atomicAdd(&sstat[col + 1], cs[nt][1]);
            atomicAdd(&sstat[128 + col], cq[nt][0]);
            atomicAdd(&sstat[128 + col + 1], cq[nt][1]);
        }
        __syncthreads();
        if (t < 128) {
            atomicAdd(&g_sumA[t], sstat[t]);
            atomicAdd(&g_ssA[t], sstat[128 + t]);
        }
    }
}

// ================= warp-per-node aggregation (dual accumulators, sentinel pad) =================
template<int MODE>
__global__ __launch_bounds__(256) void k_aggw(
    const float* __restrict__ in, const float* __restrict__ bias, float* __restrict__ out,
    __nv_bfloat16* __restrict__ oTh, __nv_bfloat16* __restrict__ oTl)
{
    __shared__ float sred[8][128];
    __shared__ float st[8][132];
    int t = threadIdx.x, w = t >> 5, lane = t & 31;
    int i = blockIdx.x * 8 + w;
    int e0 = i * SLOTCAP;
    PDL_ENTRY();
    int n = g_deg[i];
    int npad = (n + 7) & ~7;
    if (npad > SLOTCAP) npad = SLOTCAP;
    float4 accA = {0.f, 0.f, 0.f, 0.f}, accB = {0.f, 0.f, 0.f, 0.f};
    for (int c0 = 0; c0 < npad; c0 += 32) {
        int m = npad - c0; if (m > 32) m = 32;
        int src = (lane < m) ? g_srcbuf[e0 + c0 + lane] : 0;
        for (int kk = 0; kk < m; kk += 8) {
#pragma unroll
            for (int u = 0; u < 8; u += 2) {
                int s0 = __shfl_sync(0xffffffffu, src, kk + u);
                int s1 = __shfl_sync(0xffffffffu, src, kk + u + 1);
                float4 h0 = *reinterpret_cast<const float4*>(in + (long long)s0 * 128 + lane * 4);
                float4 h1 = *reinterpret_cast<const float4*>(in + (long long)s1 * 128 + lane * 4);
                accA.x += h0.x; accA.y += h0.y; accA.z += h0.z; accA.w += h0.w;
                accB.x += h1.x; accB.y += h1.y; accB.z += h1.z; accB.w += h1.w;
            }
        }
    }
    float ax = accA.x + accB.x, ay = accA.y + accB.y;
    float az = accA.z + accB.z, aw = accA.w + accB.w;
    float di = g_dinv[i];
    float vx, vy, vz, vw;
    if (MODE != 2) {
        float4 hv = *reinterpret_cast<const float4*>(in + (long long)i * 128 + lane * 4);
        vx = di * (ax + hv.x) + bias[lane * 4 + 0];
        vy = di * (ay + hv.y) + bias[lane * 4 + 1];
        vz = di * (az + hv.z) + bias[lane * 4 + 2];
        vw = di * (aw + hv.w) + bias[lane * 4 + 3];
    } else {
        vx = ax; vy = ay; vz = az; vw = aw;
    }
    if (MODE == 1) {
        float mx = fmaxf(fmaxf(vx, vy), fmaxf(vz, vw));
#pragma unroll
        for (int o = 16; o; o >>= 1) mx = fmaxf(mx, __shfl_xor_sync(0xffffffffu, mx, o));
        vx = __expf(vx - mx); vy = __expf(vy - mx); vz = __expf(vz - mx); vw = __expf(vw - mx);
        float sm = vx + vy + vz + vw;
#pragma unroll
        for (int o = 16; o; o >>= 1) sm += __shfl_xor_sync(0xffffffffu, sm, o);
        float inv = 1.f / sm;
        vx *= inv; vy *= inv; vz *= inv; vw *= inv;
    }
    if (MODE != 2) {
        float4 o4 = { vx, vy, vz, vw };
        *reinterpret_cast<float4*>(out + (long long)i * 128 + lane * 4) = o4;
    }
    if (MODE == 0) {
        sred[w][lane * 4 + 0] = vx; sred[w][lane * 4 + 1] = vy;
        sred[w][lane * 4 + 2] = vz; sred[w][lane * 4 + 3] = vw;
        __syncthreads();
        if (t < 128) {
            float s = 0.f, q = 0.f;
#pragma unroll
            for (int ww = 0; ww < 8; ww++) { float v = sred[ww][t]; s += v; q += v * v; }
            atomicAdd(&g_sumB[t], s);
            atomicAdd(&g_ssB[t], q);
        }
    } else {
        st[w][lane * 4 + 0] = vx; st[w][lane * 4 + 1] = vy;
        st[w][lane * 4 + 2] = vz; st[w][lane * 4 + 3] = vw;
        __syncthreads();
        if (t < 128) {
            int c = t;
            float v0 = st[0][c], v1 = st[1][c], v2 = st[2][c], v3 = st[3][c];
            float v4 = st[4][c], v5 = st[5][c], v6 = st[6][c], v7 = st[7][c];
            long long o = (long long)c * NNODES + blockIdx.x * 8;
            uint4 hv, lv;
            hv.x = pack_hi(v0, v1); hv.y = pack_hi(v2, v3);
            hv.z = pack_hi(v4, v5); hv.w = pack_hi(v6, v7);
            lv.x = pack_lo(v0, v1); lv.y = pack_lo(v2, v3);
            lv.z = pack_lo(v4, v5); lv.w = pack_lo(v6, v7);
            *reinterpret_cast<uint4*>(oTh + o) = hv;
            *reinterpret_cast<uint4*>(oTl + o) = lv;
        }
    }
}

// agg of RAW x (64 ch) with shuffled dinv; warp-uniform tail
__global__ __launch_bounds__(256) void k_aggx(const float* __restrict__ x) {
    int t = threadIdx.x, w = t >> 5, lane = t & 31;
    int i = blockIdx.x * 8 + w;
    int e0 = i * SLOTCAP;
    PDL_ENTRY();
    int n = g_deg[i];
    float2 accA = {0.f, 0.f}, accB = {0.f, 0.f};
    int n8 = n & ~7;
    for (int c0 = 0; c0 < n8; c0 += 32) {
        int m = n8 - c0; if (m > 32) m = 32;
        int src = 0; float dv = 0.f;
        if (lane < m) { src = g_srcbuf[e0 + c0 + lane]; dv = g_dinv[src]; }
        for (int kk = 0; kk < m; kk += 8) {
#pragma unroll
            for (int u = 0; u < 8; u += 2) {
                int s0 = __shfl_sync(0xffffffffu, src, kk + u);
                int s1 = __shfl_sync(0xffffffffu, src, kk + u + 1);
                float d0 = __shfl_sync(0xffffffffu, dv, kk + u);
                float d1 = __shfl_sync(0xffffffffu, dv, kk + u + 1);
                float2 h0 = *reinterpret_cast<const float2*>(x + (long long)s0 * 64 + lane * 2);
                float2 h1 = *reinterpret_cast<const float2*>(x + (long long)s1 * 64 + lane * 2);
                accA.x += d0 * h0.x; accA.y += d0 * h0.y;
                accB.x += d1 * h1.x; accB.y += d1 * h1.y;
            }
        }
    }
    for (int e = n8; e < n; e++) {
        int s = g_srcbuf[e0 + e];
        float d = g_dinv[s];
        float2 hv = *reinterpret_cast<const float2*>(x + (long long)s * 64 + lane * 2);
        accA.x += d * hv.x; accA.y += d * hv.y;
    }
    float di = g_dinv[i];
    float2 hv = *reinterpret_cast<const float2*>(x + (long long)i * 64 + lane * 2);
    float ax = di * (accA.x + accB.x + di * hv.x);
    float ay = di * (accA.y + accB.y + di * hv.y);
    long long o = (long long)i * 64 + lane * 2;
    *reinterpret_cast<uint32_t*>(g_axh + o) = pack_hi(ax, ay);
    *reinterpret_cast<uint32_t*>(g_axl + o) = pack_lo(ax, ay);
}

// ================= BN+SiLU(+res) =================
template<bool RES, bool WH, bool WT>
__global__ __launch_bounds__(256) void k_bn(
    const float* __restrict__ y, const float* __restrict__ res, float* __restrict__ h,
    __nv_bfloat16* __restrict__ rh, __nv_bfloat16* __restrict__ rl,
    __nv_bfloat16* __restrict__ th, __nv_bfloat16* __restrict__ tl,
    const float* __restrict__ gw, const float* __restrict__ be,
    const float* __restrict__ sumArr, const float* __restrict__ ssArr)
{
    __shared__ float tile[32][33];
    __shared__ float sc[32], sh[32];
    int t = threadIdx.x;
    int n0 = blockIdx.x * 32, c0 = blockIdx.y * 32;
    PDL_ENTRY();
    if (t < 32) {
        int c = c0 + t;
        float m = sumArr[c] * (1.f / NNODES);
        float var = ssArr[c] * (1.f / NNODES) - m * m;
        float s = gw[c] * rsqrtf(var + 1e-5f);
        sc[t] = s;
        sh[t] = be[c] - s * m;
    }
    __syncthreads();
    int nl = t >> 3, cg = t & 7;
    long long idx = (long long)(n0 + nl) * 128 + c0 + cg * 4;
    float4 v = *reinterpret_cast<const float4*>(y + idx);
    float o0, o1, o2, o3;
    {
        float a;
        a = sc[cg * 4 + 0] * v.x + sh[cg * 4 + 0]; o0 = a / (1.f + __expf(-a));
        a = sc[cg * 4 + 1] * v.y + sh[cg * 4 + 1]; o1 = a / (1.f + __expf(-a));
        a = sc[cg * 4 + 2] * v.z + sh[cg * 4 + 2]; o2 = a / (1.f + __expf(-a));
        a = sc[cg * 4 + 3] * v.w + sh[cg * 4 + 3]; o3 = a / (1.f + __expf(-a));
    }
    if (RES) {
        float4 r = *reinterpret_cast<const float4*>(res + idx);
        o0 += r.x; o1 += r.y; o2 += r.z; o3 += r.w;
    }
    if (WH) {
        float4 ov = { o0, o1, o2, o3 };
        *reinterpret_cast<float4*>(h + idx) = ov;
    }
    {
        uint2 hv, lv;
        hv.x = pack_hi(o0, o1); hv.y = pack_hi(o2, o3);
        lv.x = pack_lo(o0, o1); lv.y = pack_lo(o2, o3);
        *reinterpret_cast<uint2*>(rh + idx) = hv;
        *reinterpret_cast<uint2*>(rl + idx) = lv;
    }
    if (WT) {
        tile[nl][cg * 4 + 0] = o0; tile[nl][cg * 4 + 1] = o1;
        tile[nl][cg * 4 + 2] = o2; tile[nl][cg * 4 + 3] = o3;
        __syncthreads();
        int cc = t >> 3, g = t & 7;
        float w0 = tile[g * 4 + 0][cc], w1 = tile[g * 4 + 1][cc];
        float w2 = tile[g * 4 + 2][cc], w3 = tile[g * 4 + 3][cc];
        long long o = (long long)(c0 + cc) * NNODES + n0 + g * 4;
        uint2 hv, lv;
        hv.x = pack_hi(w0, w1); hv.y = pack_hi(w2, w3);
        lv.x = pack_lo(w0, w1); lv.y = pack_lo(w2, w3);
        *reinterpret_cast<uint2*>(th + o) = hv;
        *reinterpret_cast<uint2*>(tl + o) = lv;
    }
}

// ================= reduce partials + dinv2 + An =================
__global__ __launch_bounds__(256) void k_reduce_an() {
    int b = blockIdx.x, t = threadIdx.x;
    PDL_ENTRY();
    if (b == 0 && t < 128) {
        g_s2a[t] = 0.f; g_q2a[t] = 0.f; g_s2b[t] = 0.f; g_q2b[t] = 0.f;
        if (t == 0) g_bar = 0;
    }
    const long long PS = (long long)NB * CH * CH;
    const long long BO = (long long)b * CH * CH;
    __shared__ float sd[128];
    for (int idx = t; idx < CH * CH; idx += 256) {
        float s = 0.f;
#pragma unroll
        for (int p = 0; p < 8; p++) s += g_xpart[p * PS + BO + idx];
        g_x2[BO + idx] = s;
    }
    int w = t >> 5, lane = t & 31;
    for (int r = w; r < 128; r += 8) {
        float rsum = 0.f;
#pragma unroll
        for (int q = 0; q < 4; q++) {
            int idx = r * 128 + lane + q * 32;
            float s = 0.f;
#pragma unroll
            for (int p = 0; p < 8; p++) s += g_apart[p * PS + BO + idx];
            g_A2[BO + idx] = s;
            rsum += s;
        }
#pragma unroll
        for (int o = 16; o; o >>= 1) rsum += __shfl_down_sync(0xffffffffu, rsum, o);
        if (lane == 0) sd[r] = rsqrtf(rsum + 1.0f);
    }
    __syncthreads();
    for (int idx = t; idx < CH * CH; idx += 256) {
        int i = idx >> 7, j = idx & 127;
        float v = g_A2[BO + idx] + (i == j ? 1.f : 0.f);
        g_An[BO + idx] = sd[i] * v * sd[j];
    }
}

// ================= fused stack-2 (FFMA2, pitch-132 smem, 32 blocks) =================
__device__ __forceinline__ void gridbar(int target) {
    __syncthreads();
    __threadfence();
    if (threadIdx.x == 0) {
        atomicAdd(&g_bar, 1);
        while (*(volatile int*)&g_bar < target) __nanosleep(64);
    }
    __syncthreads();
    __threadfence();
}

__device__ __forceinline__ void gemm_sm128(const float* __restrict__ P, const float* __restrict__ Q,
                                           unsigned long long acc2[8][4], int tx, int ty)
{
#pragma unroll
    for (int i = 0; i < 8; i++)
#pragma unroll
        for (int j = 0; j < 4; j++) acc2[i][j] = 0ull;
#pragma unroll 2
    for (int k = 0; k < 128; k++) {
        float a[8];
#pragma unroll
        for (int i = 0; i < 8; i++) a[i] = P[(ty * 8 + i) * P2 + k];
        const unsigned long long* Qp =
            reinterpret_cast<const unsigned long long*>(&Q[k * P2 + tx * 8]);
        unsigned long long b0 = Qp[0], b1 = Qp[1], b2 = Qp[2], b3 = Qp[3];
#pragma unroll
        for (int i = 0; i < 8; i++) {
            unsigned long long ad = dup_f32(a[i]);
            ffma2(acc2[i][0], ad, b0);
            ffma2(acc2[i][1], ad, b1);
            ffma2(acc2[i][2], ad, b2);
            ffma2(acc2[i][3], ad, b3);
        }
    }
}

__global__ __launch_bounds__(256) void k_stack2(
    const float* __restrict__ w2a, const float* __restrict__ b2a,
    const float* __restrict__ g2a, const float* __restrict__ be2a,
    const float* __restrict__ w2b, const float* __restrict__ b2b,
    const float* __restrict__ g2b, const float* __restrict__ be2b,
    const float* __restrict__ wl, const float* __restrict__ bl,
    float* __restrict__ out, int out_size)
{
    extern __shared__ __align__(16) float sm2[];
    float* AN = sm2;                 // 128 * P2 floats each
    float* XB = sm2 + 128 * P2;
    float* WB = sm2 + 256 * P2;
    __shared__ float red[2048];
    __shared__ float gv[128];
    __shared__ float lg[10];
    __shared__ float lse;
    int b = blockIdx.x, t = threadIdx.x, tx = t & 15, ty = t >> 4;
    const float INVN = 1.f / (NB * CH);
    PDL_ENTRY();

    // pitched copy-in: read float4, store float4 (P2%4==0 keeps 16B alignment)
    {
        const float4* pAn = (const float4*)(g_An + (long long)b * 16384);
        const float4* pX2 = (const float4*)(g_x2 + (long long)b * 16384);
        const float4* pWa = (const float4*)w2a;
        for (int i = t; i < 4096; i += 256) {
            int r = i >> 5, c = (i & 31) * 4;
            *reinterpret_cast<float4*>(AN + r * P2 + c) = pAn[i];
            *reinterpret_cast<float4*>(XB + r * P2 + c) = pX2[i];
            *reinterpret_cast<float4*>(WB + r * P2 + c) = pWa[i];
        }
    }
    __syncthreads();

    unsigned long long acc2[8][4];
    float cs[8], cq[8];

    gemm_sm128(XB, WB, acc2, tx, ty);
    __syncthreads();
#pragma unroll
    for (int i = 0; i < 8; i++)
#pragma unroll
        for (int j = 0; j < 4; j++) {
            float2 p = u2f(acc2[i][j]);
            XB[(ty * 8 + i) * P2 + tx * 8 + 2 * j] = p.x;
            XB[(ty * 8 + i) * P2 + tx * 8 + 2 * j + 1] = p.y;
        }
    __syncthreads();

    gemm_sm128(AN, XB, acc2, tx, ty);
    __syncthreads();
#pragma unroll
    for (int j = 0; j < 8; j++) { cs[j] = 0.f; cq[j] = 0.f; }
#pragma unroll
    for (int i = 0; i < 8; i++)
#pragma unroll
        for (int j = 0; j < 4; j++) {
            float2 p = u2f(acc2[i][j]);
            float v0 = p.x + b2a[tx * 8 + 2 * j];
            float v1 = p.y + b2a[tx * 8 + 2 * j + 1];
            WB[(ty * 8 + i) * P2 + tx * 8 + 2 * j] = v0;
            WB[(ty * 8 + i) * P2 + tx * 8 + 2 * j + 1] = v1;
            cs[2 * j] += v0; cq[2 * j] += v0 * v0;
            cs[2 * j + 1] += v1; cq[2 * j + 1] += v1 * v1;
        }
#pragma unroll
    for (int j = 0; j < 8; j++) red[ty * 128 + tx * 8 + j] = cs[j];
    __syncthreads();
    if (t < 128) { float s = 0.f; for (int g = 0; g < 16; g++) s += red[g * 128 + t]; atomicAdd(&g_s2a[t], s); }
    __syncthreads();
#pragma unroll
    for (int j = 0; j < 8; j++) red[ty * 128 + tx * 8 + j] = cq[j];
    __syncthreads();
    if (t < 128) { float s = 0.f; for (int g = 0; g < 16; g++) s += red[g * 128 + t]; atomicAdd(&g_q2a[t], s); }

    gridbar(NB);

    float scv[8], shv[8];
#pragma unroll
    for (int j = 0; j < 8; j++) {
        int c = tx * 8 + j;
        float m = g_s2a[c] * INVN;
        float var = g_q2a[c] * INVN - m * m;
        float s = g2a[c] * rsqrtf(var + 1e-5f);
        scv[j] = s; shv[j] = be2a[c] - s * m;
    }
#pragma unroll
    for (int i = 0; i < 8; i++)
#pragma unroll
        for (int j = 0; j < 8; j++) {
            float v = WB[(ty * 8 + i) * P2 + tx * 8 + j];
            v = scv[j] * v + shv[j];
            v = v / (1.f + __expf(-v));
            XB[(ty * 8 + i) * P2 + tx * 8 + j] = v;
        }
    __syncthreads();

    {
        const float4* pWb = (const float4*)w2b;
        for (int i = t; i < 4096; i += 256) {
            int r = i >> 5, c = (i & 31) * 4;
            *reinterpret_cast<float4*>(WB + r * P2 + c) = pWb[i];
        }
    }
    __syncthreads();

    gemm_sm128(XB, WB, acc2, tx, ty);
    __syncthreads();
#pragma unroll
    for (int i = 0; i < 8; i++)
#pragma unroll
        for (int j = 0; j < 4; j++) {
            float2 p = u2f(acc2[i][j]);
            WB[(ty * 8 + i) * P2 + tx * 8 + 2 * j] = p.x;
            WB[(ty * 8 + i) * P2 + tx * 8 + 2 * j + 1] = p.y;
        }
    __syncthreads();

    gemm_sm128(AN, WB, acc2, tx, ty);
#pragma unroll
    for (int j = 0; j < 8; j++) { cs[j] = 0.f; cq[j] = 0.f; }
#pragma unroll
    for (int i = 0; i < 8; i++)
#pragma unroll
        for (int j = 0; j < 4; j++) {
            float2 p = u2f(acc2[i][j]);
            float v0 = p.x + b2b[tx * 8 + 2 * j];
            float v1 = p.y + b2b[tx * 8 + 2 * j + 1];
            cs[2 * j] += v0; cq[2 * j] += v0 * v0;
            cs[2 * j + 1] += v1; cq[2 * j + 1] += v1 * v1;
        }
    __syncthreads();
#pragma unroll
    for (int j = 0; j < 8; j++) red[ty * 128 + tx * 8 + j] = cs[j];
    __syncthreads();
    if (t < 128) { float s = 0.f; for (int g = 0; g < 16; g++) s += red[g * 128 + t]; atomicAdd(&g_s2b[t], s); }
    __syncthreads();
#pragma unroll
    for (int j = 0; j < 8; j++) red[ty * 128 + tx * 8 + j] = cq[j];
    __syncthreads();
    if (t < 128) { float s = 0.f; for (int g = 0; g < 16; g++) s += red[g * 128 + t]; atomicAdd(&g_q2b[t], s); }

    gridbar(2 * NB);

#pragma unroll
    for (int j = 0; j < 8; j++) {
        int c = tx * 8 + j;
        float m = g_s2b[c] * INVN;
        float var = g_q2b[c] * INVN - m * m;
        float s = g2b[c] * rsqrtf(var + 1e-5f);
        scv[j] = s; shv[j] = be2b[c] - s * m;
    }
    float colsum[8];
#pragma unroll
    for (int j = 0; j < 8; j++) colsum[j] = 0.f;
#pragma unroll
    for (int i = 0; i < 8; i++)
#pragma unroll
        for (int j = 0; j < 4; j++) {
            float2 p = u2f(acc2[i][j]);
            float v0 = scv[2 * j] * (p.x + b2b[tx * 8 + 2 * j]) + shv[2 * j];
            float v1 = scv[2 * j + 1] * (p.y + b2b[tx * 8 + 2 * j + 1]) + shv[2 * j + 1];
            v0 = v0 / (1.f + __expf(-v0));
            v1 = v1 / (1.f + __expf(-v1));
            v0 += XB[(ty * 8 + i) * P2 + tx * 8 + 2 * j];
            v1 += XB[(ty * 8 + i) * P2 + tx * 8 + 2 * j + 1];
            colsum[2 * j] += v0;
            colsum[2 * j + 1] += v1;
        }
    __syncthreads();
#pragma unroll
    for (int j = 0; j < 8; j++) red[ty * 128 + tx * 8 + j] = colsum[j];
    __syncthreads();
    if (t < 128) {
        float s = 0.f;
        for (int g = 0; g < 16; g++) s += red[g * 128 + t];
        gv[t] = s * (1.f / 32.f);
    }
    __syncthreads();
    if (t < 10) {
        float a = bl[t];
        for (int k = 0; k < 128; k++) a += gv[k] * wl[k * 10 + t];
        lg[t] = a;
    }
    __syncthreads();
    if (t == 0) {
        float mx = -1e30f;
        for (int j = 0; j < 10; j++) mx = fmaxf(mx, lg[j]);
        float se = 0.f;
        for (int j = 0; j < 10; j++) se += expf(lg[j] - mx);
        lse = mx + logf(se);
    }
    __syncthreads();
    if (t < 10) {
        int o = b * 10 + t;
        if (o < out_size) out[o] = lg[t] - lse;
    }
    if (b == 0) {
        for (int idx = NB * 10 + t; idx < out_size; idx += 256) out[idx] = 0.f;
    }
}

// ================= host orchestration =================
extern "C" void kernel_launch(void* const* d_in, const int* in_sizes, int n_in,
                              void* d_out, int out_size) {
    const float* x    = (const float*)d_in[0];
    const int*   ei   = (const int*)  d_in[1];
    const float* w1a  = (const float*)d_in[4];
    const float* b1a  = (const float*)d_in[5];
    const float* g1a  = (const float*)d_in[6];
    const float* be1a = (const float*)d_in[7];
    const float* w1b  = (const float*)d_in[8];
    const float* b1b  = (const float*)d_in[9];
    const float* g1b  = (const float*)d_in[10];
    const float* be1b = (const float*)d_in[11];
    const float* wp1  = (const float*)d_in[12];
    const float* bp1  = (const float*)d_in[13];
    const float* w2a  = (const float*)d_in[14];
    const float* b2a  = (const float*)d_in[15];
    const float* g2a  = (const float*)d_in[16];
    const float* be2a = (const float*)d_in[17];
    const float* w2b  = (const float*)d_in[18];
    const float* b2b  = (const float*)d_in[19];
    const float* g2b  = (const float*)d_in[20];
    const float* be2b = (const float*)d_in[21];
    const float* wl   = (const float*)d_in[24];
    const float* bl   = (const float*)d_in[25];
    float* outp = (float*)d_out;
    (void)n_in; (void)in_sizes;

    float *p_lin, *p_y, *p_h, *p_s, *p_xpart, *p_apart;
    float *p_sumA, *p_ssA, *p_sumB, *p_ssB, *p_dinv;
    __nv_bfloat16 *p_axh, *p_axl, *p_hah, *p_hal, *p_hbh, *p_hbl;
    __nv_bfloat16 *p_hTh, *p_hTl, *p_sTh, *p_sTl, *p_tTh, *p_tTl;
    __nv_bfloat16 *p_w1ah, *p_w1al, *p_w1bh, *p_w1bl, *p_wp1h, *p_wp1l;
    cudaGetSymbolAddress((void**)&p_lin,   g_lin);
    cudaGetSymbolAddress((void**)&p_y,     g_y);
    cudaGetSymbolAddress((void**)&p_h,     g_h);
    cudaGetSymbolAddress((void**)&p_s,     g_s);
    cudaGetSymbolAddress((void**)&p_xpart, g_xpart);
    cudaGetSymbolAddress((void**)&p_apart, g_apart);
    cudaGetSymbolAddress((void**)&p_sumA,  g_sumA);
    cudaGetSymbolAddress((void**)&p_ssA,   g_ssA);
    cudaGetSymbolAddress((void**)&p_sumB,  g_sumB);
    cudaGetSymbolAddress((void**)&p_ssB,   g_ssB);
    cudaGetSymbolAddress((void**)&p_dinv,  g_dinv);
    cudaGetSymbolAddress((void**)&p_axh,   g_axh);
    cudaGetSymbolAddress((void**)&p_axl,   g_axl);
    cudaGetSymbolAddress((void**)&p_hah,   g_hah);
    cudaGetSymbolAddress((void**)&p_hal,   g_hal);
    cudaGetSymbolAddress((void**)&p_hbh,   g_hbh);
    cudaGetSymbolAddress((void**)&p_hbl,   g_hbl);
    cudaGetSymbolAddress((void**)&p_hTh,   g_hTh);
    cudaGetSymbolAddress((void**)&p_hTl,   g_hTl);
    cudaGetSymbolAddress((void**)&p_sTh,   g_sTh);
    cudaGetSymbolAddress((void**)&p_sTl,   g_sTl);
    cudaGetSymbolAddress((void**)&p_tTh,   g_tTh);
    cudaGetSymbolAddress((void**)&p_tTl,   g_tTl);
    cudaGetSymbolAddress((void**)&p_w1ah,  g_w1ah);
    cudaGetSymbolAddress((void**)&p_w1al,  g_w1al);
    cudaGetSymbolAddress((void**)&p_w1bh,  g_w1bh);
    cudaGetSymbolAddress((void**)&p_w1bl,  g_w1bl);
    cudaGetSymbolAddress((void**)&p_wp1h,  g_wp1h);
    cudaGetSymbolAddress((void**)&p_wp1l,  g_wp1l);

    const int SM2 = 3 * 128 * P2 * 4;   // 202752 bytes

    static bool attrDone = false;
    if (!attrDone) {
        cudaFuncSetAttribute(k_stack2, cudaFuncAttributeMaxDynamicSharedMemorySize, SM2);
        cudaFuncSetAttribute(k_mma<false, true>,  cudaFuncAttributeMaxDynamicSharedMemorySize, 50176);
        cudaFuncSetAttribute(k_mma<false, false>, cudaFuncAttributeMaxDynamicSharedMemorySize, 50176);
        cudaFuncSetAttribute(k_mma<true, false>,  cudaFuncAttributeMaxDynamicSharedMemorySize, 50176);
        attrDone = true;
    }

    cudaLaunchAttribute pdl[1];
    pdl[0].id = cudaLaunchAttributeProgrammaticStreamSerialization;
    pdl[0].val.programmaticStreamSerializationAllowed = 1;
    auto cfg = [&](dim3 g, dim3 b, size_t smem) {
        cudaLaunchConfig_t c = {};
        c.gridDim = g; c.blockDim = b; c.dynamicSmemBytes = smem;
        c.stream = 0; c.attrs = pdl; c.numAttrs = 1;
        return c;
    };

    // graph structure + weight split
    { auto c = cfg(dim3(NNODES / 256), dim3(256), 0); cudaLaunchKernelEx(&c, k_zero_deg); }
    { auto c = cfg(dim3(NEDGES / 512), dim3(256), 0); cudaLaunchKernelEx(&c, k_build, ei); }
    { auto c = cfg(dim3(160), dim3(256), 0); cudaLaunchKernelEx(&c, k_wsplit, w1a, w1b, wp1); }

    // stack 1, layer a
    { auto c = cfg(dim3(NNODES / 8), dim3(256), 0); cudaLaunchKernelEx(&c, k_aggx, x); }
    { auto c = cfg(dim3(256), dim3(256), 50176);
      cudaLaunchKernelEx(&c, k_mma<false, true>,
          (const __nv_bfloat16*)p_axh, (const __nv_bfloat16*)p_axl, (long long)64,
          (const __nv_bfloat16*)p_w1ah, (const __nv_bfloat16*)p_w1al,
          (const __nv_bfloat16*)nullptr, (const __nv_bfloat16*)nullptr, (long long)64,
          b1a, (const float*)nullptr, p_y, (float*)nullptr, 64); }
    { auto c = cfg(dim3(NNODES / 32, 4), dim3(256), 0);
      cudaLaunchKernelEx(&c, k_bn<false, true, false>,
          (const float*)p_y, (const float*)nullptr, p_h, p_hah, p_hal,
          (__nv_bfloat16*)nullptr, (__nv_bfloat16*)nullptr, g1a, be1a,
          (const float*)p_sumA, (const float*)p_ssA); }

    // stack 1, layer b (residual)
    { auto c = cfg(dim3(256), dim3(256), 50176);
      cudaLaunchKernelEx(&c, k_mma<false, false>,
          (const __nv_bfloat16*)p_hah, (const __nv_bfloat16*)p_hal, (long long)128,
          (const __nv_bfloat16*)p_w1bh, (const __nv_bfloat16*)p_w1bl,
          (const __nv_bfloat16*)nullptr, (const __nv_bfloat16*)nullptr, (long long)128,
          (const float*)nullptr, (const float*)p_dinv, p_lin, (float*)nullptr, 128); }
    { auto c = cfg(dim3(NNODES / 8), dim3(256), 0);
      cudaLaunchKernelEx(&c, k_aggw<0>, (const float*)p_lin, b1b, p_y,
          (__nv_bfloat16*)nullptr, (__nv_bfloat16*)nullptr); }
    { auto c = cfg(dim3(NNODES / 32, 4), dim3(256), 0);
      cudaLaunchKernelEx(&c, k_bn<true, false, true>,
          (const float*)p_y, (const float*)p_h, (float*)nullptr, p_hbh, p_hbl,
          p_hTh, p_hTl, g1b, be1b, (const float*)p_sumB, (const float*)p_ssB); }

    // pooling 1
    { auto c = cfg(dim3(256), dim3(256), 50176);
      cudaLaunchKernelEx(&c, k_mma<false, false>,
          (const __nv_bfloat16*)p_hbh, (const __nv_bfloat16*)p_hbl, (long long)128,
          (const __nv_bfloat16*)p_wp1h, (const __nv_bfloat16*)p_wp1l,
          (const __nv_bfloat16*)nullptr, (const __nv_bfloat16*)nullptr, (long long)128,
          (const float*)nullptr, (const float*)p_dinv, p_lin, (float*)nullptr, 128); }
    { auto c = cfg(dim3(NNODES / 8), dim3(256), 0);
      cudaLaunchKernelEx(&c, k_aggw<1>, (const float*)p_lin, bp1, p_s, p_sTh, p_sTl); }
    { auto c = cfg(dim3(NNODES / 8), dim3(256), 0);
      cudaLaunchKernelEx(&c, k_aggw<2>, (const float*)p_s, (const float*)nullptr,
          (float*)nullptr, p_tTh, p_tTl); }

    // pooled einsums + reduce/An
    { auto c = cfg(dim3(1, 16, NB), dim3(256), 50176);
      cudaLaunchKernelEx(&c, k_mma<true, false>,
          (const __nv_bfloat16*)p_sTh, (const __nv_bfloat16*)p_sTl, (long long)NNODES,
          (const __nv_bfloat16*)p_hTh, (const __nv_bfloat16*)p_hTl,
          (const __nv_bfloat16*)p_tTh, (const __nv_bfloat16*)p_tTl, (long long)NNODES,
          (const float*)nullptr, (const float*)nullptr, p_xpart, p_apart, 128); }
    { auto c = cfg(dim3(NB), dim3(256), 0); cudaLaunchKernelEx(&c, k_reduce_an); }

    // fused stack 2 (FFMA2, pitch-132 smem) + head
    { auto c = cfg(dim3(NB), dim3(256), SM2);
      cudaLaunchKernelEx(&c, k_stack2, w2a, b2a, g2a, be2a, w2b, b2b, g2b, be2b,
          wl, bl, outp, out_size); }
}

// round 16
// speedup vs baseline: 1.0767x; 1.0318x over previous
#include <cuda_runtime.h>
#include <cuda_bf16.h>
#include <math.h>
#include <stdint.h>

#define NNODES 32768
#define NEDGES 524288
#define NB     32
#define NPG    1024
#define CH     128
#define CIN    64
#define SLOTCAP 72
#define P2     132

#define PDL_ENTRY() do { \
    cudaTriggerProgrammaticLaunchCompletion(); \
    cudaGridDependencySynchronize(); \
} while (0)

// ================= helpers =================
__device__ __forceinline__ uint32_t smem_u32(const void* p) {
    uint32_t a;
    asm("{ .reg .u64 t; cvta.to.shared.u64 t, %1; cvt.u32.u64 %0, t; }" : "=r"(a) : "l"(p));
    return a;
}
__device__ __forceinline__ void ffma2(unsigned long long& d, unsigned long long a, unsigned long long b) {
    asm("fma.rn.f32x2 %0, %1, %2, %0;" : "+l"(d) : "l"(a), "l"(b));
}
__device__ __forceinline__ unsigned long long dup_f32(float v) {
    unsigned long long r;
    asm("mov.b64 %0, {%1, %1};" : "=l"(r) : "f"(v));
    return r;
}
__device__ __forceinline__ float2 u2f(unsigned long long v) {
    float2 f;
    asm("mov.b64 {%0, %1}, %2;" : "=f"(f.x), "=f"(f.y) : "l"(v));
    return f;
}
__device__ __forceinline__ float bf_lo(uint32_t u) { return __uint_as_float(u << 16); }
__device__ __forceinline__ float bf_hi(uint32_t u) { return __uint_as_float(u & 0xffff0000u); }
#define CP_ASYNC16(dst, src) asm volatile("cp.async.ca.shared.global [%0], [%1], 16;" :: "r"(dst), "l"(src))
#define CP_COMMIT()          asm volatile("cp.async.commit_group;" ::: "memory")
#define CP_WAIT(n)           asm volatile("cp.async.wait_group %0;" :: "n"(n) : "memory")

#define MMA_BF16(cf, a0, a1, a2, a3, b0, b1) \
    asm volatile("mma.sync.aligned.m16n8k16.row.col.f32.bf16.bf16.f32 " \
        "{%0,%1,%2,%3},{%4,%5,%6,%7},{%8,%9},{%0,%1,%2,%3};" \
        : "+f"((cf)[0]), "+f"((cf)[1]), "+f"((cf)[2]), "+f"((cf)[3]) \
        : "r"(a0), "r"(a1), "r"(a2), "r"(a3), "r"(b0), "r"(b1))

__device__ __forceinline__ uint32_t pack_hi(float a, float b) {
    __nv_bfloat162 h;
    h.x = __float2bfloat16_rn(a); h.y = __float2bfloat16_rn(b);
    return *reinterpret_cast<uint32_t*>(&h);
}
__device__ __forceinline__ uint32_t pack_lo(float a, float b) {
    __nv_bfloat16 ha = __float2bfloat16_rn(a), hb = __float2bfloat16_rn(b);
    __nv_bfloat162 l;
    l.x = __float2bfloat16_rn(a - __bfloat162float(ha));
    l.y = __float2bfloat16_rn(b - __bfloat162float(hb));
    return *reinterpret_cast<uint32_t*>(&l);
}
__device__ __forceinline__ void split1(float v, __nv_bfloat16& h, __nv_bfloat16& l) {
    h = __float2bfloat16_rn(v);
    l = __float2bfloat16_rn(v - __bfloat162float(h));
}

// ================= device scratch =================
// bf16 gather sources have 8 extra rows; row NNODES is never written => zero sentinel.
__device__ int   g_deg[NNODES];
__device__ int   g_srcbuf[NNODES * SLOTCAP];
__device__ float g_dinv[NNODES];

__device__ float g_y  [NNODES * CH];
__device__ float g_h  [NNODES * CH];

__device__ __align__(16) __nv_bfloat16 g_linb[(NNODES + 8) * CH];  // bf16 gather source (lin)
__device__ __align__(16) __nv_bfloat16 g_sb  [(NNODES + 8) * CH];  // bf16 gather source (s)

__device__ __align__(16) __nv_bfloat16 g_axh[NNODES * CIN], g_axl[NNODES * CIN];
__device__ __align__(16) __nv_bfloat16 g_hah[NNODES * CH],  g_hal[NNODES * CH];
__device__ __align__(16) __nv_bfloat16 g_hbh[NNODES * CH],  g_hbl[NNODES * CH];
__device__ __align__(16) __nv_bfloat16 g_hTh[CH * NNODES],  g_hTl[CH * NNODES];
__device__ __align__(16) __nv_bfloat16 g_sTh[CH * NNODES],  g_sTl[CH * NNODES];
__device__ __align__(16) __nv_bfloat16 g_tTh[CH * NNODES],  g_tTl[CH * NNODES];
__device__ __align__(16) __nv_bfloat16 g_w1ah[CH * CIN], g_w1al[CH * CIN];
__device__ __align__(16) __nv_bfloat16 g_w1bh[CH * CH],  g_w1bl[CH * CH];
__device__ __align__(16) __nv_bfloat16 g_wp1h[CH * CH],  g_wp1l[CH * CH];

__device__ float g_xpart[8 * NB * CH * CH];
__device__ float g_apart[8 * NB * CH * CH];
__device__ float g_x2  [NB * CH * CH];
__device__ float g_A2  [NB * CH * CH];
__device__ float g_An  [NB * CH * CH];

__device__ float g_sumA[CH], g_ssA[CH], g_sumB[CH], g_ssB[CH];
__device__ float g_s2a[CH], g_q2a[CH], g_s2b[CH], g_q2b[CH];
__device__ int   g_bar;

// ================= graph structure =================
__global__ void k_zero_deg() {
    int i = blockIdx.x * 256 + threadIdx.x;
    cudaTriggerProgrammaticLaunchCompletion();
    g_deg[i] = 0;
    if (i < 128) { g_sumA[i] = 0.f; g_ssA[i] = 0.f; g_sumB[i] = 0.f; g_ssB[i] = 0.f; }
}
__global__ void k_build(const int* __restrict__ ei) {
    int e = (blockIdx.x * 256 + threadIdx.x) * 2;
    PDL_ENTRY();
    if (e < NEDGES) {
        int s0 = ei[e], s1 = ei[e + 1];
        int d0 = ei[NEDGES + e], d1 = ei[NEDGES + e + 1];
        int p0 = atomicAdd(&g_deg[d0], 1);
        int p1 = atomicAdd(&g_deg[d1], 1);
        g_srcbuf[d0 * SLOTCAP + p0] = s0;
        g_srcbuf[d1 * SLOTCAP + p1] = s1;
    }
}

__global__ void k_wsplit(const float* __restrict__ w1a, const float* __restrict__ w1b,
                         const float* __restrict__ wp1) {
    int idx = blockIdx.x * 256 + threadIdx.x;
    PDL_ENTRY();
    if (idx < NNODES) {
        int deg = g_deg[idx];
        g_dinv[idx] = rsqrtf((float)deg + 1.0f);
        int npad = (deg + 7) & ~7;
        if (npad > SLOTCAP) npad = SLOTCAP;
        for (int p = deg; p < npad; p++) g_srcbuf[idx * SLOTCAP + p] = NNODES;
    }
    if (idx < 8192) {
        int n = idx >> 6, k = idx & 63;
        split1(w1a[k * 128 + n], g_w1ah[idx], g_w1al[idx]);
    } else if (idx < 24576) {
        int j = idx - 8192;
        int n = j >> 7, k = j & 127;
        split1(w1b[k * 128 + n], g_w1bh[j], g_w1bl[j]);
    } else if (idx < 40960) {
        int j = idx - 24576;
        int n = j >> 7, k = j & 127;
        split1(wp1[k * 128 + n], g_wp1h[j], g_wp1l[j]);
    }
}

// ================= bf16-split mma.sync GEMM =================
// Cb16: optional row-major bf16 output (non-pooled only). C1 fp32 optional when Cb16 set.
template<bool POOLED, bool STATS>
__global__ __launch_bounds__(256) void k_mma(
    const __nv_bfloat16* __restrict__ Ah, const __nv_bfloat16* __restrict__ Al, long long pA,
    const __nv_bfloat16* __restrict__ B1h, const __nv_bfloat16* __restrict__ B1l,
    const __nv_bfloat16* __restrict__ B2h, const __nv_bfloat16* __restrict__ B2l, long long pB,
    const float* __restrict__ bias, const float* __restrict__ rowscale,
    float* __restrict__ C1, float* __restrict__ C2,
    __nv_bfloat16* __restrict__ Cb16, int K)
{
    extern __shared__ __align__(16) char smem[];
    __nv_bfloat16* SB = reinterpret_cast<__nv_bfloat16*>(smem);
    float* sstat = reinterpret_cast<float*>(smem + 49152);
    int t = threadIdx.x, lane = t & 31;
    int warpm = ((t >> 5) & 3) * 32, warpn = (t >> 7) * 64;

    const __nv_bfloat16 *Ahb, *Alb, *Bhb, *Blb;
    float* Cb = nullptr;
    long long m0 = 0;
    if (POOLED) {
        int g = blockIdx.z;
        int half = blockIdx.y >> 3, chunk = blockIdx.y & 7;
        long long ko = (long long)g * 1024 + (long long)chunk * 128;
        Ahb = Ah + ko; Alb = Al + ko;
        Bhb = (half ? B2h : B1h) + ko;
        Blb = (half ? B2l : B1l) + ko;
        Cb = (half ? C2 : C1) + (long long)(chunk * NB + g) * (CH * CH);
    } else {
        m0 = (long long)blockIdx.x * 128;
        Ahb = Ah + m0 * pA; Alb = Al + m0 * pA;
        Bhb = B1h; Blb = B1l;
        if (C1) Cb = C1 + m0 * 128;
    }
    PDL_ENTRY();
    if (STATS) { sstat[t] = 0.f; }

    uint32_t sbase = smem_u32(SB);
    int sr = t >> 1, sc = t & 1;
    uint32_t dofs = sbase + sr * 48 + sc * 16;
    CP_ASYNC16(dofs,         Ahb + (long long)sr * pA + sc * 8);
    CP_ASYNC16(dofs + 6144,  Alb + (long long)sr * pA + sc * 8);
    CP_ASYNC16(dofs + 12288, Bhb + (long long)sr * pB + sc * 8);
    CP_ASYNC16(dofs + 18432, Blb + (long long)sr * pB + sc * 8);
    CP_COMMIT();

    float c[2][8][4];
#pragma unroll
    for (int i = 0; i < 2; i++)
#pragma unroll
        for (int j = 0; j < 8; j++)
#pragma unroll
            for (int q = 0; q < 4; q++) c[i][j][q] = 0.f;

    int g8 = lane >> 2, kc = (lane & 3) * 2;
    int NT = K >> 4;
    for (int kt = 0; kt < NT; kt++) {
        if (kt + 1 < NT) {
            int k0 = (kt + 1) << 4;
            uint32_t d2 = dofs + ((kt + 1) & 1) * 24576;
            CP_ASYNC16(d2,         Ahb + (long long)sr * pA + k0 + sc * 8);
            CP_ASYNC16(d2 + 6144,  Alb + (long long)sr * pA + k0 + sc * 8);
            CP_ASYNC16(d2 + 12288, Bhb + (long long)sr * pB + k0 + sc * 8);
            CP_ASYNC16(d2 + 18432, Blb + (long long)sr * pB + k0 + sc * 8);
            CP_COMMIT();
            CP_WAIT(1);
        } else {
            CP_WAIT(0);
        }
        __syncthreads();
        const __nv_bfloat16* P = SB + (kt & 1) * 12288;
        uint32_t ah[2][4], al[2][4];
#pragma unroll
        for (int mt = 0; mt < 2; mt++) {
            int mb = warpm + mt * 16 + g8;
            ah[mt][0] = *(const uint32_t*)(P + mb * 24 + kc);
            ah[mt][1] = *(const uint32_t*)(P + (mb + 8) * 24 + kc);
            ah[mt][2] = *(const uint32_t*)(P + mb * 24 + kc + 8);
            ah[mt][3] = *(const uint32_t*)(P + (mb + 8) * 24 + kc + 8);
            al[mt][0] = *(const uint32_t*)(P + 3072 + mb * 24 + kc);
            al[mt][1] = *(const uint32_t*)(P + 3072 + (mb + 8) * 24 + kc);
            al[mt][2] = *(const uint32_t*)(P + 3072 + mb * 24 + kc + 8);
            al[mt][3] = *(const uint32_t*)(P + 3072 + (mb + 8) * 24 + kc + 8);
        }
#pragma unroll
        for (int nt = 0; nt < 8; nt++) {
            int nb = warpn + nt * 8 + g8;
            uint32_t bh0 = *(const uint32_t*)(P + 6144 + nb * 24 + kc);
            uint32_t bh1 = *(const uint32_t*)(P + 6144 + nb * 24 + kc + 8);
            uint32_t bl0 = *(const uint32_t*)(P + 9216 + nb * 24 + kc);
            uint32_t bl1 = *(const uint32_t*)(P + 9216 + nb * 24 + kc + 8);
#pragma unroll
            for (int mt = 0; mt < 2; mt++) {
                MMA_BF16(c[mt][nt], ah[mt][0], ah[mt][1], ah[mt][2], ah[mt][3], bh0, bh1);
                MMA_BF16(c[mt][nt], ah[mt][0], ah[mt][1], ah[mt][2], ah[mt][3], bl0, bl1);
                MMA_BF16(c[mt][nt], al[mt][0], al[mt][1], al[mt][2], al[mt][3], bh0, bh1);
            }
        }
        __syncthreads();
    }

    float cs[8][2], cq[8][2];
    if (STATS) {
#pragma unroll
        for (int j = 0; j < 8; j++) { cs[j][0] = cs[j][1] = 0.f; cq[j][0] = cq[j][1] = 0.f; }
    }
#pragma unroll
    for (int mt = 0; mt < 2; mt++) {
        int row = warpm + mt * 16 + g8;
        float rs0 = rowscale ? rowscale[m0 + row] : 1.f;
        float rs1 = rowscale ? rowscale[m0 + row + 8] : 1.f;
#pragma unroll
        for (int nt = 0; nt < 8; nt++) {
            int col = warpn + nt * 8 + kc;
            float b0 = bias ? bias[col] : 0.f;
            float b1 = bias ? bias[col + 1] : 0.f;
            float v00 = (c[mt][nt][0] + b0) * rs0, v01 = (c[mt][nt][1] + b1) * rs0;
            float v10 = (c[mt][nt][2] + b0) * rs1, v11 = (c[mt][nt][3] + b1) * rs1;
            if (Cb) {
                *reinterpret_cast<float2*>(Cb + (long long)row * 128 + col) = make_float2(v00, v01);
                *reinterpret_cast<float2*>(Cb + (long long)(row + 8) * 128 + col) = make_float2(v10, v11);
            }
            if (!POOLED && Cb16) {
                *reinterpret_cast<uint32_t*>(Cb16 + (m0 + row) * 128 + col) = pack_hi(v00, v01);
                *reinterpret_cast<uint32_t*>(Cb16 + (m0 + row + 8) * 128 + col) = pack_hi(v10, v11);
            }
            if (STATS) {
                cs[nt][0] += v00 + v10; cq[nt][0] += v00 * v00 + v10 * v10;
                cs[nt][1] += v01 + v11; cq[nt][1] += v01 * v01 + v11 * v11;
            }
        }
    }
    if (STATS) {
        __syncthreads();
#pragma unroll
        for (int nt = 0; nt < 8; nt++) {
            int col = warpn + nt * 8 + kc;
            atomicAdd(&sstat[col], cs[nt][0]);
            atomicAdd(&sstat[col + 1], cs[nt][1]);
            atomicAdd(&sstat[128 + col], cq[nt][0]);
            atomicAdd(&sstat[128 + col + 1], cq[nt][1]);
        }
        __syncthreads();
        if (t < 128) {
            atomicAdd(&g_sumA[t], sstat[t]);
            atomicAdd(&g_ssA[t], sstat[128 + t]);
        }
    }
}

// ================= warp-per-node aggregation over bf16 rows =================
// MODE 0: gcn+bias (+stats, fp32 out); 1: gcn+bias+softmax (bf16 row out + sT);
// MODE 2: plain sum (tT out only)
template<int MODE>
__global__ __launch_bounds__(256) void k_aggw(
    const __nv_bfloat16* __restrict__ in, const float* __restrict__ bias,
    float* __restrict__ out, __nv_bfloat16* __restrict__ ob,
    __nv_bfloat16* __restrict__ oTh, __nv_bfloat16* __restrict__ oTl)
{
    __shared__ float sred[8][128];
    __shared__ float st[8][132];
    int t = threadIdx.x, w = t >> 5, lane = t & 31;
    int i = blockIdx.x * 8 + w;
    int e0 = i * SLOTCAP;
    PDL_ENTRY();
    int n = g_deg[i];
    int npad = (n + 7) & ~7;
    if (npad > SLOTCAP) npad = SLOTCAP;
    float4 accA = {0.f, 0.f, 0.f, 0.f}, accB = {0.f, 0.f, 0.f, 0.f};
    for (int c0 = 0; c0 < npad; c0 += 32) {
        int m = npad - c0; if (m > 32) m = 32;
        int src = (lane < m) ? g_srcbuf[e0 + c0 + lane] : 0;
        for (int kk = 0; kk < m; kk += 8) {
#pragma unroll
            for (int u = 0; u < 8; u += 2) {
                int s0 = __shfl_sync(0xffffffffu, src, kk + u);
                int s1 = __shfl_sync(0xffffffffu, src, kk + u + 1);
                uint2 q0 = *reinterpret_cast<const uint2*>(in + (long long)s0 * 128 + lane * 4);
                uint2 q1 = *reinterpret_cast<const uint2*>(in + (long long)s1 * 128 + lane * 4);
                accA.x += bf_lo(q0.x); accA.y += bf_hi(q0.x);
                accA.z += bf_lo(q0.y); accA.w += bf_hi(q0.y);
                accB.x += bf_lo(q1.x); accB.y += bf_hi(q1.x);
                accB.z += bf_lo(q1.y); accB.w += bf_hi(q1.y);
            }
        }
    }
    float ax = accA.x + accB.x, ay = accA.y + accB.y;
    float az = accA.z + accB.z, aw = accA.w + accB.w;
    float di = g_dinv[i];
    float vx, vy, vz, vw;
    if (MODE != 2) {
        uint2 qs = *reinterpret_cast<const uint2*>(in + (long long)i * 128 + lane * 4);
        vx = di * (ax + bf_lo(qs.x)) + bias[lane * 4 + 0];
        vy = di * (ay + bf_hi(qs.x)) + bias[lane * 4 + 1];
        vz = di * (az + bf_lo(qs.y)) + bias[lane * 4 + 2];
        vw = di * (aw + bf_hi(qs.y)) + bias[lane * 4 + 3];
    } else {
        vx = ax; vy = ay; vz = az; vw = aw;
    }
    if (MODE == 1) {
        float mx = fmaxf(fmaxf(vx, vy), fmaxf(vz, vw));
#pragma unroll
        for (int o = 16; o; o >>= 1) mx = fmaxf(mx, __shfl_xor_sync(0xffffffffu, mx, o));
        vx = __expf(vx - mx); vy = __expf(vy - mx); vz = __expf(vz - mx); vw = __expf(vw - mx);
        float sm = vx + vy + vz + vw;
#pragma unroll
        for (int o = 16; o; o >>= 1) sm += __shfl_xor_sync(0xffffffffu, sm, o);
        float inv = 1.f / sm;
        vx *= inv; vy *= inv; vz *= inv; vw *= inv;
    }
    if (MODE == 0) {
        float4 o4 = { vx, vy, vz, vw };
        *reinterpret_cast<float4*>(out + (long long)i * 128 + lane * 4) = o4;
        sred[w][lane * 4 + 0] = vx; sred[w][lane * 4 + 1] = vy;
        sred[w][lane * 4 + 2] = vz; sred[w][lane * 4 + 3] = vw;
        __syncthreads();
        if (t < 128) {
            float s = 0.f, q = 0.f;
#pragma unroll
            for (int ww = 0; ww < 8; ww++) { float v = sred[ww][t]; s += v; q += v * v; }
            atomicAdd(&g_sumB[t], s);
            atomicAdd(&g_ssB[t], q);
        }
    } else {
        if (MODE == 1) {
            uint2 sb;
            sb.x = pack_hi(vx, vy); sb.y = pack_hi(vz, vw);
            *reinterpret_cast<uint2*>(ob + (long long)i * 128 + lane * 4) = sb;
        }
        st[w][lane * 4 + 0] = vx; st[w][lane * 4 + 1] = vy;
        st[w][lane * 4 + 2] = vz; st[w][lane * 4 + 3] = vw;
        __syncthreads();
        if (t < 128) {
            int c = t;
            float v0 = st[0][c], v1 = st[1][c], v2 = st[2][c], v3 = st[3][c];
            float v4 = st[4][c], v5 = st[5][c], v6 = st[6][c], v7 = st[7][c];
            long long o = (long long)c * NNODES + blockIdx.x * 8;
            uint4 hv, lv;
            hv.x = pack_hi(v0, v1); hv.y = pack_hi(v2, v3);
            hv.z = pack_hi(v4, v5); hv.w = pack_hi(v6, v7);
            lv.x = pack_lo(v0, v1); lv.y = pack_lo(v2, v3);
            lv.z = pack_lo(v4, v5); lv.w = pack_lo(v6, v7);
            *reinterpret_cast<uint4*>(oTh + o) = hv;
            *reinterpret_cast<uint4*>(oTl + o) = lv;
        }
    }
}

// agg of RAW x (64 ch, fp32) with shuffled dinv; warp-uniform tail
__global__ __launch_bounds__(256) void k_aggx(const float* __restrict__ x) {
    int t = threadIdx.x, w = t >> 5, lane = t & 31;
    int i = blockIdx.x * 8 + w;
    int e0 = i * SLOTCAP;
    PDL_ENTRY();
    int n = g_deg[i];
    float2 accA = {0.f, 0.f}, accB = {0.f, 0.f};
    int n8 = n & ~7;
    for (int c0 = 0; c0 < n8; c0 += 32) {
        int m = n8 - c0; if (m > 32) m = 32;
        int src = 0; float dv = 0.f;
        if (lane < m) { src = g_srcbuf[e0 + c0 + lane]; dv = g_dinv[src]; }
        for (int kk = 0; kk < m; kk += 8) {
#pragma unroll
            for (int u = 0; u < 8; u += 2) {
                int s0 = __shfl_sync(0xffffffffu, src, kk + u);
                int s1 = __shfl_sync(0xffffffffu, src, kk + u + 1);
                float d0 = __shfl_sync(0xffffffffu, dv, kk + u);
                float d1 = __shfl_sync(0xffffffffu, dv, kk + u + 1);
                float2 h0 = *reinterpret_cast<const float2*>(x + (long long)s0 * 64 + lane * 2);
                float2 h1 = *reinterpret_cast<const float2*>(x + (long long)s1 * 64 + lane * 2);
                accA.x += d0 * h0.x; accA.y += d0 * h0.y;
                accB.x += d1 * h1.x; accB.y += d1 * h1.y;
            }
        }
    }
    for (int e = n8; e < n; e++) {
        int s = g_srcbuf[e0 + e];
        float d = g_dinv[s];
        float2 hv = *reinterpret_cast<const float2*>(x + (long long)s * 64 + lane * 2);
        accA.x += d * hv.x; accA.y += d * hv.y;
    }
    float di = g_dinv[i];
    float2 hv = *reinterpret_cast<const float2*>(x + (long long)i * 64 + lane * 2);
    float ax = di * (accA.x + accB.x + di * hv.x);
    float ay = di * (accA.y + accB.y + di * hv.y);
    long long o = (long long)i * 64 + lane * 2;
    *reinterpret_cast<uint32_t*>(g_axh + o) = pack_hi(ax, ay);
    *reinterpret_cast<uint32_t*>(g_axl + o) = pack_lo(ax, ay);
}

// ================= BN+SiLU(+res) =================
template<bool RES, bool WH, bool WT>
__global__ __launch_bounds__(256) void k_bn(
    const float* __restrict__ y, const float* __restrict__ res, float* __restrict__ h,
    __nv_bfloat16* __restrict__ rh, __nv_bfloat16* __restrict__ rl,
    __nv_bfloat16* __restrict__ th, __nv_bfloat16* __restrict__ tl,
    const float* __restrict__ gw, const float* __restrict__ be,
    const float* __restrict__ sumArr, const float* __restrict__ ssArr)
{
    __shared__ float tile[32][33];
    __shared__ float sc[32], sh[32];
    int t = threadIdx.x;
    int n0 = blockIdx.x * 32, c0 = blockIdx.y * 32;
    PDL_ENTRY();
    if (t < 32) {
        int c = c0 + t;
        float m = sumArr[c] * (1.f / NNODES);
        float var = ssArr[c] * (1.f / NNODES) - m * m;
        float s = gw[c] * rsqrtf(var + 1e-5f);
        sc[t] = s;
        sh[t] = be[c] - s * m;
    }
    __syncthreads();
    int nl = t >> 3, cg = t & 7;
    long long idx = (long long)(n0 + nl) * 128 + c0 + cg * 4;
    float4 v = *reinterpret_cast<const float4*>(y + idx);
    float o0, o1, o2, o3;
    {
        float a;
        a = sc[cg * 4 + 0] * v.x + sh[cg * 4 + 0]; o0 = a / (1.f + __expf(-a));
        a = sc[cg * 4 + 1] * v.y + sh[cg * 4 + 1]; o1 = a / (1.f + __expf(-a));
        a = sc[cg * 4 + 2] * v.z + sh[cg * 4 + 2]; o2 = a / (1.f + __expf(-a));
        a = sc[cg * 4 + 3] * v.w + sh[cg * 4 + 3]; o3 = a / (1.f + __expf(-a));
    }
    if (RES) {
        float4 r = *reinterpret_cast<const float4*>(res + idx);
        o0 += r.x; o1 += r.y; o2 += r.z; o3 += r.w;
    }
    if (WH) {
        float4 ov = { o0, o1, o2, o3 };
        *reinterpret_cast<float4*>(h + idx) = ov;
    }
    {
        uint2 hv, lv;
        hv.x = pack_hi(o0, o1); hv.y = pack_hi(o2, o3);
        lv.x = pack_lo(o0, o1); lv.y = pack_lo(o2, o3);
        *reinterpret_cast<uint2*>(rh + idx) = hv;
        *reinterpret_cast<uint2*>(rl + idx) = lv;
    }
    if (WT) {
        tile[nl][cg * 4 + 0] = o0; tile[nl][cg * 4 + 1] = o1;
        tile[nl][cg * 4 + 2] = o2; tile[nl][cg * 4 + 3] = o3;
        __syncthreads();
        int cc = t >> 3, g = t & 7;
        float w0 = tile[g * 4 + 0][cc], w1 = tile[g * 4 + 1][cc];
        float w2 = tile[g * 4 + 2][cc], w3 = tile[g * 4 + 3][cc];
        long long o = (long long)(c0 + cc) * NNODES + n0 + g * 4;
        uint2 hv, lv;
        hv.x = pack_hi(w0, w1); hv.y = pack_hi(w2, w3);
        lv.x = pack_lo(w0, w1); lv.y = pack_lo(w2, w3);
        *reinterpret_cast<uint2*>(th + o) = hv;
        *reinterpret_cast<uint2*>(tl + o) = lv;
    }
}

// ================= reduce partials + dinv2 + An =================
__global__ __launch_bounds__(256) void k_reduce_an() {
    int b = blockIdx.x, t = threadIdx.x;
    PDL_ENTRY();
    if (b == 0 && t < 128) {
        g_s2a[t] = 0.f; g_q2a[t] = 0.f; g_s2b[t] = 0.f; g_q2b[t] = 0.f;
        if (t == 0) g_bar = 0;
    }
    const long long PS = (long long)NB * CH * CH;
    const long long BO = (long long)b * CH * CH;
    __shared__ float sd[128];
    for (int idx = t; idx < CH * CH; idx += 256) {
        float s = 0.f;
#pragma unroll
        for (int p = 0; p < 8; p++) s += g_xpart[p * PS + BO + idx];
        g_x2[BO + idx] = s;
    }
    int w = t >> 5, lane = t & 31;
    for (int r = w; r < 128; r += 8) {
        float rsum = 0.f;
#pragma unroll
        for (int q = 0; q < 4; q++) {
            int idx = r * 128 + lane + q * 32;
            float s = 0.f;
#pragma unroll
            for (int p = 0; p < 8; p++) s += g_apart[p * PS + BO + idx];
            g_A2[BO + idx] = s;
            rsum += s;
        }
#pragma unroll
        for (int o = 16; o; o >>= 1) rsum += __shfl_down_sync(0xffffffffu, rsum, o);
        if (lane == 0) sd[r] = rsqrtf(rsum + 1.0f);
    }
    __syncthreads();
    for (int idx = t; idx < CH * CH; idx += 256) {
        int i = idx >> 7, j = idx & 127;
        float v = g_A2[BO + idx] + (i == j ? 1.f : 0.f);
        g_An[BO + idx] = sd[i] * v * sd[j];
    }
}

// ================= fused stack-2 (FFMA2, pitch-132 smem, 32 blocks) =================
__device__ __forceinline__ void gridbar(int target) {
    __syncthreads();
    __threadfence();
    if (threadIdx.x == 0) {
        atomicAdd(&g_bar, 1);
        while (*(volatile int*)&g_bar < target) __nanosleep(64);
    }
    __syncthreads();
    __threadfence();
}

__device__ __forceinline__ void gemm_sm128(const float* __restrict__ P, const float* __restrict__ Q,
                                           unsigned long long acc2[8][4], int tx, int ty)
{
#pragma unroll
    for (int i = 0; i < 8; i++)
#pragma unroll
        for (int j = 0; j < 4; j++) acc2[i][j] = 0ull;
#pragma unroll 2
    for (int k = 0; k < 128; k++) {
        float a[8];
#pragma unroll
        for (int i = 0; i < 8; i++) a[i] = P[(ty * 8 + i) * P2 + k];
        const unsigned long long* Qp =
            reinterpret_cast<const unsigned long long*>(&Q[k * P2 + tx * 8]);
        unsigned long long b0 = Qp[0], b1 = Qp[1], b2 = Qp[2], b3 = Qp[3];
#pragma unroll
        for (int i = 0; i < 8; i++) {
            unsigned long long ad = dup_f32(a[i]);
            ffma2(acc2[i][0], ad, b0);
            ffma2(acc2[i][1], ad, b1);
            ffma2(acc2[i][2], ad, b2);
            ffma2(acc2[i][3], ad, b3);
        }
    }
}

__global__ __launch_bounds__(256) void k_stack2(
    const float* __restrict__ w2a, const float* __restrict__ b2a,
    const float* __restrict__ g2a, const float* __restrict__ be2a,
    const float* __restrict__ w2b, const float* __restrict__ b2b,
    const float* __restrict__ g2b, const float* __restrict__ be2b,
    const float* __restrict__ wl, const float* __restrict__ bl,
    float* __restrict__ out, int out_size)
{
    extern __shared__ __align__(16) float sm2[];
    float* AN = sm2;
    float* XB = sm2 + 128 * P2;
    float* WB = sm2 + 256 * P2;
    __shared__ float red[2048];
    __shared__ float gv[128];
    __shared__ float lg[10];
    __shared__ float lse;
    int b = blockIdx.x, t = threadIdx.x, tx = t & 15, ty = t >> 4;
    const float INVN = 1.f / (NB * CH);
    PDL_ENTRY();

    {
        const float4* pAn = (const float4*)(g_An + (long long)b * 16384);
        const float4* pX2 = (const float4*)(g_x2 + (long long)b * 16384);
        const float4* pWa = (const float4*)w2a;
        for (int i = t; i < 4096; i += 256) {
            int r = i >> 5, c = (i & 31) * 4;
            *reinterpret_cast<float4*>(AN + r * P2 + c) = pAn[i];
            *reinterpret_cast<float4*>(XB + r * P2 + c) = pX2[i];
            *reinterpret_cast<float4*>(WB + r * P2 + c) = pWa[i];
        }
    }
    __syncthreads();

    unsigned long long acc2[8][4];
    float cs[8], cq[8];

    gemm_sm128(XB, WB, acc2, tx, ty);
    __syncthreads();
#pragma unroll
    for (int i = 0; i < 8; i++)
#pragma unroll
        for (int j = 0; j < 4; j++) {
            float2 p = u2f(acc2[i][j]);
            XB[(ty * 8 + i) * P2 + tx * 8 + 2 * j] = p.x;
            XB[(ty * 8 + i) * P2 + tx * 8 + 2 * j + 1] = p.y;
        }
    __syncthreads();

    gemm_sm128(AN, XB, acc2, tx, ty);
    __syncthreads();
#pragma unroll
    for (int j = 0; j < 8; j++) { cs[j] = 0.f; cq[j] = 0.f; }
#pragma unroll
    for (int i = 0; i < 8; i++)
#pragma unroll
        for (int j = 0; j < 4; j++) {
            float2 p = u2f(acc2[i][j]);
            float v0 = p.x + b2a[tx * 8 + 2 * j];
            float v1 = p.y + b2a[tx * 8 + 2 * j + 1];
            WB[(ty * 8 + i) * P2 + tx * 8 + 2 * j] = v0;
            WB[(ty * 8 + i) * P2 + tx * 8 + 2 * j + 1] = v1;
            cs[2 * j] += v0; cq[2 * j] += v0 * v0;
            cs[2 * j + 1] += v1; cq[2 * j + 1] += v1 * v1;
        }
#pragma unroll
    for (int j = 0; j < 8; j++) red[ty * 128 + tx * 8 + j] = cs[j];
    __syncthreads();
    if (t < 128) { float s = 0.f; for (int g = 0; g < 16; g++) s += red[g * 128 + t]; atomicAdd(&g_s2a[t], s); }
    __syncthreads();
#pragma unroll
    for (int j = 0; j < 8; j++) red[ty * 128 + tx * 8 + j] = cq[j];
    __syncthreads();
    if (t < 128) { float s = 0.f; for (int g = 0; g < 16; g++) s += red[g * 128 + t]; atomicAdd(&g_q2a[t], s); }

    gridbar(NB);

    float scv[8], shv[8];
#pragma unroll
    for (int j = 0; j < 8; j++) {
        int c = tx * 8 + j;
        float m = g_s2a[c] * INVN;
        float var = g_q2a[c] * INVN - m * m;
        float s = g2a[c] * rsqrtf(var + 1e-5f);
        scv[j] = s; shv[j] = be2a[c] - s * m;
    }
#pragma unroll
    for (int i = 0; i < 8; i++)
#pragma unroll
        for (int j = 0; j < 8; j++) {
            float v = WB[(ty * 8 + i) * P2 + tx * 8 + j];
            v = scv[j] * v + shv[j];
            v = v / (1.f + __expf(-v));
            XB[(ty * 8 + i) * P2 + tx * 8 + j] = v;
        }
    __syncthreads();

    {
        const float4* pWb = (const float4*)w2b;
        for (int i = t; i < 4096; i += 256) {
            int r = i >> 5, c = (i & 31) * 4;
            *reinterpret_cast<float4*>(WB + r * P2 + c) = pWb[i];
        }
    }
    __syncthreads();

    gemm_sm128(XB, WB, acc2, tx, ty);
    __syncthreads();
#pragma unroll
    for (int i = 0; i < 8; i++)
#pragma unroll
        for (int j = 0; j < 4; j++) {
            float2 p = u2f(acc2[i][j]);
            WB[(ty * 8 + i) * P2 + tx * 8 + 2 * j] = p.x;
            WB[(ty * 8 + i) * P2 + tx * 8 + 2 * j + 1] = p.y;
        }
    __syncthreads();

    gemm_sm128(AN, WB, acc2, tx, ty);
#pragma unroll
    for (int j = 0; j < 8; j++) { cs[j] = 0.f; cq[j] = 0.f; }
#pragma unroll
    for (int i = 0; i < 8; i++)
#pragma unroll
        for (int j = 0; j < 4; j++) {
            float2 p = u2f(acc2[i][j]);
            float v0 = p.x + b2b[tx * 8 + 2 * j];
            float v1 = p.y + b2b[tx * 8 + 2 * j + 1];
            cs[2 * j] += v0; cq[2 * j] += v0 * v0;
            cs[2 * j + 1] += v1; cq[2 * j + 1] += v1 * v1;
        }
    __syncthreads();
#pragma unroll
    for (int j = 0; j < 8; j++) red[ty * 128 + tx * 8 + j] = cs[j];
    __syncthreads();
    if (t < 128) { float s = 0.f; for (int g = 0; g < 16; g++) s += red[g * 128 + t]; atomicAdd(&g_s2b[t], s); }
    __syncthreads();
#pragma unroll
    for (int j = 0; j < 8; j++) red[ty * 128 + tx * 8 + j] = cq[j];
    __syncthreads();
    if (t < 128) { float s = 0.f; for (int g = 0; g < 16; g++) s += red[g * 128 + t]; atomicAdd(&g_q2b[t], s); }

    gridbar(2 * NB);

#pragma unroll
    for (int j = 0; j < 8; j++) {
        int c = tx * 8 + j;
        float m = g_s2b[c] * INVN;
        float var = g_q2b[c] * INVN - m * m;
        float s = g2b[c] * rsqrtf(var + 1e-5f);
        scv[j] = s; shv[j] = be2b[c] - s * m;
    }
    float colsum[8];
#pragma unroll
    for (int j = 0; j < 8; j++) colsum[j] = 0.f;
#pragma unroll
    for (int i = 0; i < 8; i++)
#pragma unroll
        for (int j = 0; j < 4; j++) {
            float2 p = u2f(acc2[i][j]);
            float v0 = scv[2 * j] * (p.x + b2b[tx * 8 + 2 * j]) + shv[2 * j];
            float v1 = scv[2 * j + 1] * (p.y + b2b[tx * 8 + 2 * j + 1]) + shv[2 * j + 1];
            v0 = v0 / (1.f + __expf(-v0));
            v1 = v1 / (1.f + __expf(-v1));
            v0 += XB[(ty * 8 + i) * P2 + tx * 8 + 2 * j];
            v1 += XB[(ty * 8 + i) * P2 + tx * 8 + 2 * j + 1];
            colsum[2 * j] += v0;
            colsum[2 * j + 1] += v1;
        }
    __syncthreads();
#pragma unroll
    for (int j = 0; j < 8; j++) red[ty * 128 + tx * 8 + j] = colsum[j];
    __syncthreads();
    if (t < 128) {
        float s = 0.f;
        for (int g = 0; g < 16; g++) s += red[g * 128 + t];
        gv[t] = s * (1.f / 32.f);
    }
    __syncthreads();
    if (t < 10) {
        float a = bl[t];
        for (int k = 0; k < 128; k++) a += gv[k] * wl[k * 10 + t];
        lg[t] = a;
    }
    __syncthreads();
    if (t == 0) {
        float mx = -1e30f;
        for (int j = 0; j < 10; j++) mx = fmaxf(mx, lg[j]);
        float se = 0.f;
        for (int j = 0; j < 10; j++) se += expf(lg[j] - mx);
        lse = mx + logf(se);
    }
    __syncthreads();
    if (t < 10) {
        int o = b * 10 + t;
        if (o < out_size) out[o] = lg[t] - lse;
    }
    if (b == 0) {
        for (int idx = NB * 10 + t; idx < out_size; idx += 256) out[idx] = 0.f;
    }
}

// ================= host orchestration =================
extern "C" void kernel_launch(void* const* d_in, const int* in_sizes, int n_in,
                              void* d_out, int out_size) {
    const float* x    = (const float*)d_in[0];
    const int*   ei   = (const int*)  d_in[1];
    const float* w1a  = (const float*)d_in[4];
    const float* b1a  = (const float*)d_in[5];
    const float* g1a  = (const float*)d_in[6];
    const float* be1a = (const float*)d_in[7];
    const float* w1b  = (const float*)d_in[8];
    const float* b1b  = (const float*)d_in[9];
    const float* g1b  = (const float*)d_in[10];
    const float* be1b = (const float*)d_in[11];
    const float* wp1  = (const float*)d_in[12];
    const float* bp1  = (const float*)d_in[13];
    const float* w2a  = (const float*)d_in[14];
    const float* b2a  = (const float*)d_in[15];
    const float* g2a  = (const float*)d_in[16];
    const float* be2a = (const float*)d_in[17];
    const float* w2b  = (const float*)d_in[18];
    const float* b2b  = (const float*)d_in[19];
    const float* g2b  = (const float*)d_in[20];
    const float* be2b = (const float*)d_in[21];
    const float* wl   = (const float*)d_in[24];
    const float* bl   = (const float*)d_in[25];
    float* outp = (float*)d_out;
    (void)n_in; (void)in_sizes;

    float *p_y, *p_h, *p_xpart, *p_apart;
    float *p_sumA, *p_ssA, *p_sumB, *p_ssB, *p_dinv;
    __nv_bfloat16 *p_linb, *p_sb;
    __nv_bfloat16 *p_axh, *p_axl, *p_hah, *p_hal, *p_hbh, *p_hbl;
    __nv_bfloat16 *p_hTh, *p_hTl, *p_sTh, *p_sTl, *p_tTh, *p_tTl;
    __nv_bfloat16 *p_w1ah, *p_w1al, *p_w1bh, *p_w1bl, *p_wp1h, *p_wp1l;
    cudaGetSymbolAddress((void**)&p_y,     g_y);
    cudaGetSymbolAddress((void**)&p_h,     g_h);
    cudaGetSymbolAddress((void**)&p_linb,  g_linb);
    cudaGetSymbolAddress((void**)&p_sb,    g_sb);
    cudaGetSymbolAddress((void**)&p_xpart, g_xpart);
    cudaGetSymbolAddress((void**)&p_apart, g_apart);
    cudaGetSymbolAddress((void**)&p_sumA,  g_sumA);
    cudaGetSymbolAddress((void**)&p_ssA,   g_ssA);
    cudaGetSymbolAddress((void**)&p_sumB,  g_sumB);
    cudaGetSymbolAddress((void**)&p_ssB,   g_ssB);
    cudaGetSymbolAddress((void**)&p_dinv,  g_dinv);
    cudaGetSymbolAddress((void**)&p_axh,   g_axh);
    cudaGetSymbolAddress((void**)&p_axl,   g_axl);
    cudaGetSymbolAddress((void**)&p_hah,   g_hah);
    cudaGetSymbolAddress((void**)&p_hal,   g_hal);
    cudaGetSymbolAddress((void**)&p_hbh,   g_hbh);
    cudaGetSymbolAddress((void**)&p_hbl,   g_hbl);
    cudaGetSymbolAddress((void**)&p_hTh,   g_hTh);
    cudaGetSymbolAddress((void**)&p_hTl,   g_hTl);
    cudaGetSymbolAddress((void**)&p_sTh,   g_sTh);
    cudaGetSymbolAddress((void**)&p_sTl,   g_sTl);
    cudaGetSymbolAddress((void**)&p_tTh,   g_tTh);
    cudaGetSymbolAddress((void**)&p_tTl,   g_tTl);
    cudaGetSymbolAddress((void**)&p_w1ah,  g_w1ah);
    cudaGetSymbolAddress((void**)&p_w1al,  g_w1al);
    cudaGetSymbolAddress((void**)&p_w1bh,  g_w1bh);
    cudaGetSymbolAddress((void**)&p_w1bl,  g_w1bl);
    cudaGetSymbolAddress((void**)&p_wp1h,  g_wp1h);
    cudaGetSymbolAddress((void**)&p_wp1l,  g_wp1l);

    const int SM2 = 3 * 128 * P2 * 4;

    static bool attrDone = false;
    if (!attrDone) {
        cudaFuncSetAttribute(k_stack2, cudaFuncAttributeMaxDynamicSharedMemorySize, SM2);
        cudaFuncSetAttribute(k_mma<false, true>,  cudaFuncAttributeMaxDynamicSharedMemorySize, 50176);
        cudaFuncSetAttribute(k_mma<false, false>, cudaFuncAttributeMaxDynamicSharedMemorySize, 50176);
        cudaFuncSetAttribute(k_mma<true, false>,  cudaFuncAttributeMaxDynamicSharedMemorySize, 50176);
        attrDone = true;
    }

    cudaLaunchAttribute pdl[1];
    pdl[0].id = cudaLaunchAttributeProgrammaticStreamSerialization;
    pdl[0].val.programmaticStreamSerializationAllowed = 1;
    auto cfg = [&](dim3 g, dim3 b, size_t smem) {
        cudaLaunchConfig_t c = {};
        c.gridDim = g; c.blockDim = b; c.dynamicSmemBytes = smem;
        c.stream = 0; c.attrs = pdl; c.numAttrs = 1;
        return c;
    };

    // graph structure + weight split
    { auto c = cfg(dim3(NNODES / 256), dim3(256), 0); cudaLaunchKernelEx(&c, k_zero_deg); }
    { auto c = cfg(dim3(NEDGES / 512), dim3(256), 0); cudaLaunchKernelEx(&c, k_build, ei); }
    { auto c = cfg(dim3(160), dim3(256), 0); cudaLaunchKernelEx(&c, k_wsplit, w1a, w1b, wp1); }

    // stack 1, layer a
    { auto c = cfg(dim3(NNODES / 8), dim3(256), 0); cudaLaunchKernelEx(&c, k_aggx, x); }
    { auto c = cfg(dim3(256), dim3(256), 50176);
      cudaLaunchKernelEx(&c, k_mma<false, true>,
          (const __nv_bfloat16*)p_axh, (const __nv_bfloat16*)p_axl, (long long)64,
          (const __nv_bfloat16*)p_w1ah, (const __nv_bfloat16*)p_w1al,
          (const __nv_bfloat16*)nullptr, (const __nv_bfloat16*)nullptr, (long long)64,
          b1a, (const float*)nullptr, p_y, (float*)nullptr,
          (__nv_bfloat16*)nullptr, 64); }
    { auto c = cfg(dim3(NNODES / 32, 4), dim3(256), 0);
      cudaLaunchKernelEx(&c, k_bn<false, true, false>,
          (const float*)p_y, (const float*)nullptr, p_h, p_hah, p_hal,
          (__nv_bfloat16*)nullptr, (__nv_bfloat16*)nullptr, g1a, be1a,
          (const float*)p_sumA, (const float*)p_ssA); }

    // stack 1, layer b: GEMM -> bf16 rows only (dinv-prescaled)
    { auto c = cfg(dim3(256), dim3(256), 50176);
      cudaLaunchKernelEx(&c, k_mma<false, false>,
          (const __nv_bfloat16*)p_hah, (const __nv_bfloat16*)p_hal, (long long)128,
          (const __nv_bfloat16*)p_w1bh, (const __nv_bfloat16*)p_w1bl,
          (const __nv_bfloat16*)nullptr, (const __nv_bfloat16*)nullptr, (long long)128,
          (const float*)nullptr, (const float*)p_dinv,
          (float*)nullptr, (float*)nullptr, p_linb, 128); }
    { auto c = cfg(dim3(NNODES / 8), dim3(256), 0);
      cudaLaunchKernelEx(&c, k_aggw<0>, (const __nv_bfloat16*)p_linb, b1b, p_y,
          (__nv_bfloat16*)nullptr, (__nv_bfloat16*)nullptr, (__nv_bfloat16*)nullptr); }
    { auto c = cfg(dim3(NNODES / 32, 4), dim3(256), 0);
      cudaLaunchKernelEx(&c, k_bn<true, false, true>,
          (const float*)p_y, (const float*)p_h, (float*)nullptr, p_hbh, p_hbl,
          p_hTh, p_hTl, g1b, be1b, (const float*)p_sumB, (const float*)p_ssB); }

    // pooling 1: GEMM -> bf16 rows; softmax -> bf16 s + sT; t = A s -> tT
    { auto c = cfg(dim3(256), dim3(256), 50176);
      cudaLaunchKernelEx(&c, k_mma<false, false>,
          (const __nv_bfloat16*)p_hbh, (const __nv_bfloat16*)p_hbl, (long long)128,
          (const __nv_bfloat16*)p_wp1h, (const __nv_bfloat16*)p_wp1l,
          (const __nv_bfloat16*)nullptr, (const __nv_bfloat16*)nullptr, (long long)128,
          (const float*)nullptr, (const float*)p_dinv,
          (float*)nullptr, (float*)nullptr, p_linb, 128); }
    { auto c = cfg(dim3(NNODES / 8), dim3(256), 0);
      cudaLaunchKernelEx(&c, k_aggw<1>, (const __nv_bfloat16*)p_linb, bp1,
          (float*)nullptr, p_sb, p_sTh, p_sTl); }
    { auto c = cfg(dim3(NNODES / 8), dim3(256), 0);
      cudaLaunchKernelEx(&c, k_aggw<2>, (const __nv_bfloat16*)p_sb, (const float*)nullptr,
          (float*)nullptr, (__nv_bfloat16*)nullptr, p_tTh, p_tTl); }

    // pooled einsums + reduce/An
    { auto c = cfg(dim3(1, 16, NB), dim3(256), 50176);
      cudaLaunchKernelEx(&c, k_mma<true, false>,
          (const __nv_bfloat16*)p_sTh, (const __nv_bfloat16*)p_sTl, (long long)NNODES,
          (const __nv_bfloat16*)p_hTh, (const __nv_bfloat16*)p_hTl,
          (const __nv_bfloat16*)p_tTh, (const __nv_bfloat16*)p_tTl, (long long)NNODES,
          (const float*)nullptr, (const float*)nullptr,
          p_xpart, p_apart, (__nv_bfloat16*)nullptr, 128); }
    { auto c = cfg(dim3(NB), dim3(256), 0); cudaLaunchKernelEx(&c, k_reduce_an); }

    // fused stack 2 (FFMA2, pitch-132 smem) + head
    { auto c = cfg(dim3(NB), dim3(256), SM2);
      cudaLaunchKernelEx(&c, k_stack2, w2a, b2a, g2a, be2a, w2b, b2b, g2b, be2b,
          wl, bl, outp, out_size); }
}

// round 17
// speedup vs baseline: 1.0835x; 1.0063x over previous
#include <cuda_runtime.h>
#include <cuda_bf16.h>
#include <math.h>
#include <stdint.h>

#define NNODES 32768
#define NEDGES 524288
#define NB     32
#define NPG    1024
#define CH     128
#define CIN    64
#define SLOTCAP 72
#define P2     132

#define PDL_ENTRY() do { \
    cudaTriggerProgrammaticLaunchCompletion(); \
    cudaGridDependencySynchronize(); \
} while (0)

// ================= helpers =================
__device__ __forceinline__ uint32_t smem_u32(const void* p) {
    uint32_t a;
    asm("{ .reg .u64 t; cvta.to.shared.u64 t, %1; cvt.u32.u64 %0, t; }" : "=r"(a) : "l"(p));
    return a;
}
__device__ __forceinline__ void ffma2(unsigned long long& d, unsigned long long a, unsigned long long b) {
    asm("fma.rn.f32x2 %0, %1, %2, %0;" : "+l"(d) : "l"(a), "l"(b));
}
__device__ __forceinline__ unsigned long long dup_f32(float v) {
    unsigned long long r;
    asm("mov.b64 %0, {%1, %1};" : "=l"(r) : "f"(v));
    return r;
}
__device__ __forceinline__ float2 u2f(unsigned long long v) {
    float2 f;
    asm("mov.b64 {%0, %1}, %2;" : "=f"(f.x), "=f"(f.y) : "l"(v));
    return f;
}
__device__ __forceinline__ float bf_lo(uint32_t u) { return __uint_as_float(u << 16); }
__device__ __forceinline__ float bf_hi(uint32_t u) { return __uint_as_float(u & 0xffff0000u); }
#define CP_ASYNC16(dst, src) asm volatile("cp.async.ca.shared.global [%0], [%1], 16;" :: "r"(dst), "l"(src))
#define CP_COMMIT()          asm volatile("cp.async.commit_group;" ::: "memory")
#define CP_WAIT(n)           asm volatile("cp.async.wait_group %0;" :: "n"(n) : "memory")

#define MMA_BF16(cf, a0, a1, a2, a3, b0, b1) \
    asm volatile("mma.sync.aligned.m16n8k16.row.col.f32.bf16.bf16.f32 " \
        "{%0,%1,%2,%3},{%4,%5,%6,%7},{%8,%9},{%0,%1,%2,%3};" \
        : "+f"((cf)[0]), "+f"((cf)[1]), "+f"((cf)[2]), "+f"((cf)[3]) \
        : "r"(a0), "r"(a1), "r"(a2), "r"(a3), "r"(b0), "r"(b1))

__device__ __forceinline__ uint32_t pack_hi(float a, float b) {
    __nv_bfloat162 h;
    h.x = __float2bfloat16_rn(a); h.y = __float2bfloat16_rn(b);
    return *reinterpret_cast<uint32_t*>(&h);
}
__device__ __forceinline__ uint32_t pack_lo(float a, float b) {
    __nv_bfloat16 ha = __float2bfloat16_rn(a), hb = __float2bfloat16_rn(b);
    __nv_bfloat162 l;
    l.x = __float2bfloat16_rn(a - __bfloat162float(ha));
    l.y = __float2bfloat16_rn(b - __bfloat162float(hb));
    return *reinterpret_cast<uint32_t*>(&l);
}
__device__ __forceinline__ void split1(float v, __nv_bfloat16& h, __nv_bfloat16& l) {
    h = __float2bfloat16_rn(v);
    l = __float2bfloat16_rn(v - __bfloat162float(h));
}

// ================= device scratch =================
// bf16 gather sources have 8 extra rows; row NNODES is never written => zero sentinel.
__device__ int   g_deg[NNODES];
__device__ int   g_srcbuf[NNODES * SLOTCAP];
__device__ float g_dinv[NNODES];

__device__ float g_y  [NNODES * CH];
__device__ float g_h  [NNODES * CH];

__device__ __align__(16) __nv_bfloat16 g_xb  [(NNODES + 8) * CIN]; // bf16 dinv-prescaled x
__device__ __align__(16) __nv_bfloat16 g_linb[(NNODES + 8) * CH];  // bf16 gather source (lin)
__device__ __align__(16) __nv_bfloat16 g_sb  [(NNODES + 8) * CH];  // bf16 gather source (s)

__device__ __align__(16) __nv_bfloat16 g_axh[NNODES * CIN], g_axl[NNODES * CIN];
__device__ __align__(16) __nv_bfloat16 g_hah[NNODES * CH],  g_hal[NNODES * CH];
__device__ __align__(16) __nv_bfloat16 g_hbh[NNODES * CH],  g_hbl[NNODES * CH];
__device__ __align__(16) __nv_bfloat16 g_hTh[CH * NNODES],  g_hTl[CH * NNODES];
__device__ __align__(16) __nv_bfloat16 g_sTh[CH * NNODES],  g_sTl[CH * NNODES];
__device__ __align__(16) __nv_bfloat16 g_tTh[CH * NNODES],  g_tTl[CH * NNODES];
__device__ __align__(16) __nv_bfloat16 g_w1ah[CH * CIN], g_w1al[CH * CIN];
__device__ __align__(16) __nv_bfloat16 g_w1bh[CH * CH],  g_w1bl[CH * CH];
__device__ __align__(16) __nv_bfloat16 g_wp1h[CH * CH],  g_wp1l[CH * CH];

__device__ float g_xpart[8 * NB * CH * CH];
__device__ float g_apart[8 * NB * CH * CH];
__device__ float g_x2  [NB * CH * CH];
__device__ float g_A2  [NB * CH * CH];
__device__ float g_An  [NB * CH * CH];

__device__ float g_sumA[CH], g_ssA[CH], g_sumB[CH], g_ssB[CH];
__device__ float g_s2a[CH], g_q2a[CH], g_s2b[CH], g_q2b[CH];
__device__ int   g_bar;

// ================= graph structure =================
__global__ void k_zero_deg() {
    int i = blockIdx.x * 256 + threadIdx.x;
    cudaTriggerProgrammaticLaunchCompletion();
    g_deg[i] = 0;
    if (i < 128) { g_sumA[i] = 0.f; g_ssA[i] = 0.f; g_sumB[i] = 0.f; g_ssB[i] = 0.f; }
}
__global__ void k_build(const int* __restrict__ ei) {
    int e = (blockIdx.x * 256 + threadIdx.x) * 2;
    PDL_ENTRY();
    if (e < NEDGES) {
        int s0 = ei[e], s1 = ei[e + 1];
        int d0 = ei[NEDGES + e], d1 = ei[NEDGES + e + 1];
        int p0 = atomicAdd(&g_deg[d0], 1);
        int p1 = atomicAdd(&g_deg[d1], 1);
        g_srcbuf[d0 * SLOTCAP + p0] = s0;
        g_srcbuf[d1 * SLOTCAP + p1] = s1;
    }
}

__global__ void k_wsplit(const float* __restrict__ w1a, const float* __restrict__ w1b,
                         const float* __restrict__ wp1) {
    int idx = blockIdx.x * 256 + threadIdx.x;
    PDL_ENTRY();
    if (idx < NNODES) {
        int deg = g_deg[idx];
        g_dinv[idx] = rsqrtf((float)deg + 1.0f);
        int npad = (deg + 7) & ~7;
        if (npad > SLOTCAP) npad = SLOTCAP;
        for (int p = deg; p < npad; p++) g_srcbuf[idx * SLOTCAP + p] = NNODES;
    }
    if (idx < 8192) {
        int n = idx >> 6, k = idx & 63;
        split1(w1a[k * 128 + n], g_w1ah[idx], g_w1al[idx]);
    } else if (idx < 24576) {
        int j = idx - 8192;
        int n = j >> 7, k = j & 127;
        split1(w1b[k * 128 + n], g_w1bh[j], g_w1bl[j]);
    } else if (idx < 40960) {
        int j = idx - 24576;
        int n = j >> 7, k = j & 127;
        split1(wp1[k * 128 + n], g_wp1h[j], g_wp1l[j]);
    }
}

// x * dinv -> bf16 rows (dedicated wide launch)
__global__ __launch_bounds__(256) void k_xconv(const float* __restrict__ x) {
    int t = blockIdx.x * 256 + threadIdx.x;        // NNODES*32 threads
    PDL_ENTRY();
    int row = t >> 5, c2 = (t & 31) * 2;
    float d = g_dinv[row];
    float2 v = *reinterpret_cast<const float2*>(x + (long long)row * 64 + c2);
    *reinterpret_cast<uint32_t*>(g_xb + (long long)row * 64 + c2) = pack_hi(v.x * d, v.y * d);
}

// ================= bf16-split mma.sync GEMM =================
template<bool POOLED, bool STATS>
__global__ __launch_bounds__(256) void k_mma(
    const __nv_bfloat16* __restrict__ Ah, const __nv_bfloat16* __restrict__ Al, long long pA,
    const __nv_bfloat16* __restrict__ B1h, const __nv_bfloat16* __restrict__ B1l,
    const __nv_bfloat16* __restrict__ B2h, const __nv_bfloat16* __restrict__ B2l, long long pB,
    const float* __restrict__ bias, const float* __restrict__ rowscale,
    float* __restrict__ C1, float* __restrict__ C2,
    __nv_bfloat16* __restrict__ Cb16, int K)
{
    extern __shared__ __align__(16) char smem[];
    __nv_bfloat16* SB = reinterpret_cast<__nv_bfloat16*>(smem);
    float* sstat = reinterpret_cast<float*>(smem + 49152);
    int t = threadIdx.x, lane = t & 31;
    int warpm = ((t >> 5) & 3) * 32, warpn = (t >> 7) * 64;

    const __nv_bfloat16 *Ahb, *Alb, *Bhb, *Blb;
    float* Cb = nullptr;
    long long m0 = 0;
    if (POOLED) {
        int g = blockIdx.z;
        int half = blockIdx.y >> 3, chunk = blockIdx.y & 7;
        long long ko = (long long)g * 1024 + (long long)chunk * 128;
        Ahb = Ah + ko; Alb = Al + ko;
        Bhb = (half ? B2h : B1h) + ko;
        Blb = (half ? B2l : B1l) + ko;
        Cb = (half ? C2 : C1) + (long long)(chunk * NB + g) * (CH * CH);
    } else {
        m0 = (long long)blockIdx.x * 128;
        Ahb = Ah + m0 * pA; Alb = Al + m0 * pA;
        Bhb = B1h; Blb = B1l;
        if (C1) Cb = C1 + m0 * 128;
    }
    PDL_ENTRY();
    if (STATS) { sstat[t] = 0.f; }

    uint32_t sbase = smem_u32(SB);
    int sr = t >> 1, sc = t & 1;
    uint32_t dofs = sbase + sr * 48 + sc * 16;
    CP_ASYNC16(dofs,         Ahb + (long long)sr * pA + sc * 8);
    CP_ASYNC16(dofs + 6144,  Alb + (long long)sr * pA + sc * 8);
    CP_ASYNC16(dofs + 12288, Bhb + (long long)sr * pB + sc * 8);
    CP_ASYNC16(dofs + 18432, Blb + (long long)sr * pB + sc * 8);
    CP_COMMIT();

    float c[2][8][4];
#pragma unroll
    for (int i = 0; i < 2; i++)
#pragma unroll
        for (int j = 0; j < 8; j++)
#pragma unroll
            for (int q = 0; q < 4; q++) c[i][j][q] = 0.f;

    int g8 = lane >> 2, kc = (lane & 3) * 2;
    int NT = K >> 4;
    for (int kt = 0; kt < NT; kt++) {
        if (kt + 1 < NT) {
            int k0 = (kt + 1) << 4;
            uint32_t d2 = dofs + ((kt + 1) & 1) * 24576;
            CP_ASYNC16(d2,         Ahb + (long long)sr * pA + k0 + sc * 8);
            CP_ASYNC16(d2 + 6144,  Alb + (long long)sr * pA + k0 + sc * 8);
            CP_ASYNC16(d2 + 12288, Bhb + (long long)sr * pB + k0 + sc * 8);
            CP_ASYNC16(d2 + 18432, Blb + (long long)sr * pB + k0 + sc * 8);
            CP_COMMIT();
            CP_WAIT(1);
        } else {
            CP_WAIT(0);
        }
        __syncthreads();
        const __nv_bfloat16* P = SB + (kt & 1) * 12288;
        uint32_t ah[2][4], al[2][4];
#pragma unroll
        for (int mt = 0; mt < 2; mt++) {
            int mb = warpm + mt * 16 + g8;
            ah[mt][0] = *(const uint32_t*)(P + mb * 24 + kc);
            ah[mt][1] = *(const uint32_t*)(P + (mb + 8) * 24 + kc);
            ah[mt][2] = *(const uint32_t*)(P + mb * 24 + kc + 8);
            ah[mt][3] = *(const uint32_t*)(P + (mb + 8) * 24 + kc + 8);
            al[mt][0] = *(const uint32_t*)(P + 3072 + mb * 24 + kc);
            al[mt][1] = *(const uint32_t*)(P + 3072 + (mb + 8) * 24 + kc);
            al[mt][2] = *(const uint32_t*)(P + 3072 + mb * 24 + kc + 8);
            al[mt][3] = *(const uint32_t*)(P + 3072 + (mb + 8) * 24 + kc + 8);
        }
#pragma unroll
        for (int nt = 0; nt < 8; nt++) {
            int nb = warpn + nt * 8 + g8;
            uint32_t bh0 = *(const uint32_t*)(P + 6144 + nb * 24 + kc);
            uint32_t bh1 = *(const uint32_t*)(P + 6144 + nb * 24 + kc + 8);
            uint32_t bl0 = *(const uint32_t*)(P + 9216 + nb * 24 + kc);
            uint32_t bl1 = *(const uint32_t*)(P + 9216 + nb * 24 + kc + 8);
#pragma unroll
            for (int mt = 0; mt < 2; mt++) {
                MMA_BF16(c[mt][nt], ah[mt][0], ah[mt][1], ah[mt][2], ah[mt][3], bh0, bh1);
                MMA_BF16(c[mt][nt], ah[mt][0], ah[mt][1], ah[mt][2], ah[mt][3], bl0, bl1);
                MMA_BF16(c[mt][nt], al[mt][0], al[mt][1], al[mt][2], al[mt][3], bh0, bh1);
            }
        }
        __syncthreads();
    }

    float cs[8][2], cq[8][2];
    if (STATS) {
#pragma unroll
        for (int j = 0; j < 8; j++) { cs[j][0] = cs[j][1] = 0.f; cq[j][0] = cq[j][1] = 0.f; }
    }
#pragma unroll
    for (int mt = 0; mt < 2; mt++) {
        int row = warpm + mt * 16 + g8;
        float rs0 = rowscale ? rowscale[m0 + row] : 1.f;
        float rs1 = rowscale ? rowscale[m0 + row + 8] : 1.f;
#pragma unroll
        for (int nt = 0; nt < 8; nt++) {
            int col = warpn + nt * 8 + kc;
            float b0 = bias ? bias[col] : 0.f;
            float b1 = bias ? bias[col + 1] : 0.f;
            float v00 = (c[mt][nt][0] + b0) * rs0, v01 = (c[mt][nt][1] + b1) * rs0;
            float v10 = (c[mt][nt][2] + b0) * rs1, v11 = (c[mt][nt][3] + b1) * rs1;
            if (Cb) {
                *reinterpret_cast<float2*>(Cb + (long long)row * 128 + col) = make_float2(v00, v01);
                *reinterpret_cast<float2*>(Cb + (long long)(row + 8) * 128 + col) = make_float2(v10, v11);
            }
            if (!POOLED && Cb16) {
                *reinterpret_cast<uint32_t*>(Cb16 + (m0 + row) * 128 + col) = pack_hi(v00, v01);
                *reinterpret_cast<uint32_t*>(Cb16 + (m0 + row + 8) * 128 + col) = pack_hi(v10, v11);
            }
            if (STATS) {
                cs[nt][0] += v00 + v10; cq[nt][0] += v00 * v00 + v10 * v10;
                cs[nt][1] += v01 + v11; cq[nt][1] += v01 * v01 + v11 * v11;
            }
        }
    }
    if (STATS) {
        __syncthreads();
#pragma unroll
        for (int nt = 0; nt < 8; nt++) {
            int col = warpn + nt * 8 + kc;
            atomicAdd(&sstat[col], cs[nt][0]);
            atomicAdd(&sstat[col + 1], cs[nt][1]);
            atomicAdd(&sstat[128 + col], cq[nt][0]);
            atomicAdd(&sstat[128 + col + 1], cq[nt][1]);
        }
        __syncthreads();
        if (t < 128) {
            atomicAdd(&g_sumA[t], sstat[t]);
            atomicAdd(&g_ssA[t], sstat[128 + t]);
        }
    }
}

// ================= warp-per-node aggregation over bf16 rows =================
template<int MODE>
__global__ __launch_bounds__(256) void k_aggw(
    const __nv_bfloat16* __restrict__ in, const float* __restrict__ bias,
    float* __restrict__ out, __nv_bfloat16* __restrict__ ob,
    __nv_bfloat16* __restrict__ oTh, __nv_bfloat16* __restrict__ oTl)
{
    __shared__ float sred[8][128];
    __shared__ float st[8][132];
    int t = threadIdx.x, w = t >> 5, lane = t & 31;
    int i = blockIdx.x * 8 + w;
    int e0 = i * SLOTCAP;
    PDL_ENTRY();
    int n = g_deg[i];
    int npad = (n + 7) & ~7;
    if (npad > SLOTCAP) npad = SLOTCAP;
    float4 accA = {0.f, 0.f, 0.f, 0.f}, accB = {0.f, 0.f, 0.f, 0.f};
    for (int c0 = 0; c0 < npad; c0 += 32) {
        int m = npad - c0; if (m > 32) m = 32;
        int src = (lane < m) ? g_srcbuf[e0 + c0 + lane] : 0;
        for (int kk = 0; kk < m; kk += 8) {
#pragma unroll
            for (int u = 0; u < 8; u += 2) {
                int s0 = __shfl_sync(0xffffffffu, src, kk + u);
                int s1 = __shfl_sync(0xffffffffu, src, kk + u + 1);
                uint2 q0 = *reinterpret_cast<const uint2*>(in + (long long)s0 * 128 + lane * 4);
                uint2 q1 = *reinterpret_cast<const uint2*>(in + (long long)s1 * 128 + lane * 4);
                accA.x += bf_lo(q0.x); accA.y += bf_hi(q0.x);
                accA.z += bf_lo(q0.y); accA.w += bf_hi(q0.y);
                accB.x += bf_lo(q1.x); accB.y += bf_hi(q1.x);
                accB.z += bf_lo(q1.y); accB.w += bf_hi(q1.y);
            }
        }
    }
    float ax = accA.x + accB.x, ay = accA.y + accB.y;
    float az = accA.z + accB.z, aw = accA.w + accB.w;
    float di = g_dinv[i];
    float vx, vy, vz, vw;
    if (MODE != 2) {
        uint2 qs = *reinterpret_cast<const uint2*>(in + (long long)i * 128 + lane * 4);
        vx = di * (ax + bf_lo(qs.x)) + bias[lane * 4 + 0];
        vy = di * (ay + bf_hi(qs.x)) + bias[lane * 4 + 1];
        vz = di * (az + bf_lo(qs.y)) + bias[lane * 4 + 2];
        vw = di * (aw + bf_hi(qs.y)) + bias[lane * 4 + 3];
    } else {
        vx = ax; vy = ay; vz = az; vw = aw;
    }
    if (MODE == 1) {
        float mx = fmaxf(fmaxf(vx, vy), fmaxf(vz, vw));
#pragma unroll
        for (int o = 16; o; o >>= 1) mx = fmaxf(mx, __shfl_xor_sync(0xffffffffu, mx, o));
        vx = __expf(vx - mx); vy = __expf(vy - mx); vz = __expf(vz - mx); vw = __expf(vw - mx);
        float sm = vx + vy + vz + vw;
#pragma unroll
        for (int o = 16; o; o >>= 1) sm += __shfl_xor_sync(0xffffffffu, sm, o);
        float inv = 1.f / sm;
        vx *= inv; vy *= inv; vz *= inv; vw *= inv;
    }
    if (MODE == 0) {
        float4 o4 = { vx, vy, vz, vw };
        *reinterpret_cast<float4*>(out + (long long)i * 128 + lane * 4) = o4;
        sred[w][lane * 4 + 0] = vx; sred[w][lane * 4 + 1] = vy;
        sred[w][lane * 4 + 2] = vz; sred[w][lane * 4 + 3] = vw;
        __syncthreads();
        if (t < 128) {
            float s = 0.f, q = 0.f;
#pragma unroll
            for (int ww = 0; ww < 8; ww++) { float v = sred[ww][t]; s += v; q += v * v; }
            atomicAdd(&g_sumB[t], s);
            atomicAdd(&g_ssB[t], q);
        }
    } else {
        if (MODE == 1) {
            uint2 sb;
            sb.x = pack_hi(vx, vy); sb.y = pack_hi(vz, vw);
            *reinterpret_cast<uint2*>(ob + (long long)i * 128 + lane * 4) = sb;
        }
        st[w][lane * 4 + 0] = vx; st[w][lane * 4 + 1] = vy;
        st[w][lane * 4 + 2] = vz; st[w][lane * 4 + 3] = vw;
        __syncthreads();
        if (t < 128) {
            int c = t;
            float v0 = st[0][c], v1 = st[1][c], v2 = st[2][c], v3 = st[3][c];
            float v4 = st[4][c], v5 = st[5][c], v6 = st[6][c], v7 = st[7][c];
            long long o = (long long)c * NNODES + blockIdx.x * 8;
            uint4 hv, lv;
            hv.x = pack_hi(v0, v1); hv.y = pack_hi(v2, v3);
            hv.z = pack_hi(v4, v5); hv.w = pack_hi(v6, v7);
            lv.x = pack_lo(v0, v1); lv.y = pack_lo(v2, v3);
            lv.z = pack_lo(v4, v5); lv.w = pack_lo(v6, v7);
            *reinterpret_cast<uint4*>(oTh + o) = hv;
            *reinterpret_cast<uint4*>(oTl + o) = lv;
        }
    }
}

// agg of bf16 prescaled x (64 ch): sentinel-padded, 8x unrolled, dual acc
__global__ __launch_bounds__(256) void k_aggx() {
    int t = threadIdx.x, w = t >> 5, lane = t & 31;
    int i = blockIdx.x * 8 + w;
    int e0 = i * SLOTCAP;
    PDL_ENTRY();
    int n = g_deg[i];
    int npad = (n + 7) & ~7;
    if (npad > SLOTCAP) npad = SLOTCAP;
    float2 accA = {0.f, 0.f}, accB = {0.f, 0.f};
    for (int c0 = 0; c0 < npad; c0 += 32) {
        int m = npad - c0; if (m > 32) m = 32;
        int src = (lane < m) ? g_srcbuf[e0 + c0 + lane] : 0;
        for (int kk = 0; kk < m; kk += 8) {
#pragma unroll
            for (int u = 0; u < 8; u += 2) {
                int s0 = __shfl_sync(0xffffffffu, src, kk + u);
                int s1 = __shfl_sync(0xffffffffu, src, kk + u + 1);
                uint32_t q0 = *reinterpret_cast<const uint32_t*>(g_xb + (long long)s0 * 64 + lane * 2);
                uint32_t q1 = *reinterpret_cast<const uint32_t*>(g_xb + (long long)s1 * 64 + lane * 2);
                accA.x += bf_lo(q0); accA.y += bf_hi(q0);
                accB.x += bf_lo(q1); accB.y += bf_hi(q1);
            }
        }
    }
    float di = g_dinv[i];
    uint32_t qs = *reinterpret_cast<const uint32_t*>(g_xb + (long long)i * 64 + lane * 2);
    float ax = di * (accA.x + accB.x + bf_lo(qs));
    float ay = di * (accA.y + accB.y + bf_hi(qs));
    long long o = (long long)i * 64 + lane * 2;
    *reinterpret_cast<uint32_t*>(g_axh + o) = pack_hi(ax, ay);
    *reinterpret_cast<uint32_t*>(g_axl + o) = pack_lo(ax, ay);
}

// ================= BN+SiLU(+res) =================
template<bool RES, bool WH, bool WT>
__global__ __launch_bounds__(256) void k_bn(
    const float* __restrict__ y, const float* __restrict__ res, float* __restrict__ h,
    __nv_bfloat16* __restrict__ rh, __nv_bfloat16* __restrict__ rl,
    __nv_bfloat16* __restrict__ th, __nv_bfloat16* __restrict__ tl,
    const float* __restrict__ gw, const float* __restrict__ be,
    const float* __restrict__ sumArr, const float* __restrict__ ssArr)
{
    __shared__ float tile[32][33];
    __shared__ float sc[32], sh[32];
    int t = threadIdx.x;
    int n0 = blockIdx.x * 32, c0 = blockIdx.y * 32;
    PDL_ENTRY();
    if (t < 32) {
        int c = c0 + t;
        float m = sumArr[c] * (1.f / NNODES);
        float var = ssArr[c] * (1.f / NNODES) - m * m;
        float s = gw[c] * rsqrtf(var + 1e-5f);
        sc[t] = s;
        sh[t] = be[c] - s * m;
    }
    __syncthreads();
    int nl = t >> 3, cg = t & 7;
    long long idx = (long long)(n0 + nl) * 128 + c0 + cg * 4;
    float4 v = *reinterpret_cast<const float4*>(y + idx);
    float o0, o1, o2, o3;
    {
        float a;
        a = sc[cg * 4 + 0] * v.x + sh[cg * 4 + 0]; o0 = a / (1.f + __expf(-a));
        a = sc[cg * 4 + 1] * v.y + sh[cg * 4 + 1]; o1 = a / (1.f + __expf(-a));
        a = sc[cg * 4 + 2] * v.z + sh[cg * 4 + 2]; o2 = a / (1.f + __expf(-a));
        a = sc[cg * 4 + 3] * v.w + sh[cg * 4 + 3]; o3 = a / (1.f + __expf(-a));
    }
    if (RES) {
        float4 r = *reinterpret_cast<const float4*>(res + idx);
        o0 += r.x; o1 += r.y; o2 += r.z; o3 += r.w;
    }
    if (WH) {
        float4 ov = { o0, o1, o2, o3 };
        *reinterpret_cast<float4*>(h + idx) = ov;
    }
    {
        uint2 hv, lv;
        hv.x = pack_hi(o0, o1); hv.y = pack_hi(o2, o3);
        lv.x = pack_lo(o0, o1); lv.y = pack_lo(o2, o3);
        *reinterpret_cast<uint2*>(rh + idx) = hv;
        *reinterpret_cast<uint2*>(rl + idx) = lv;
    }
    if (WT) {
        tile[nl][cg * 4 + 0] = o0; tile[nl][cg * 4 + 1] = o1;
        tile[nl][cg * 4 + 2] = o2; tile[nl][cg * 4 + 3] = o3;
        __syncthreads();
        int cc = t >> 3, g = t & 7;
        float w0 = tile[g * 4 + 0][cc], w1 = tile[g * 4 + 1][cc];
        float w2 = tile[g * 4 + 2][cc], w3 = tile[g * 4 + 3][cc];
        long long o = (long long)(c0 + cc) * NNODES + n0 + g * 4;
        uint2 hv, lv;
        hv.x = pack_hi(w0, w1); hv.y = pack_hi(w2, w3);
        lv.x = pack_lo(w0, w1); lv.y = pack_lo(w2, w3);
        *reinterpret_cast<uint2*>(th + o) = hv;
        *reinterpret_cast<uint2*>(tl + o) = lv;
    }
}

// ================= reduce partials + dinv2 + An =================
__global__ __launch_bounds__(256) void k_reduce_an() {
    int b = blockIdx.x, t = threadIdx.x;
    PDL_ENTRY();
    if (b == 0 && t < 128) {
        g_s2a[t] = 0.f; g_q2a[t] = 0.f; g_s2b[t] = 0.f; g_q2b[t] = 0.f;
        if (t == 0) g_bar = 0;
    }
    const long long PS = (long long)NB * CH * CH;
    const long long BO = (long long)b * CH * CH;
    __shared__ float sd[128];
    for (int idx = t; idx < CH * CH; idx += 256) {
        float s = 0.f;
#pragma unroll
        for (int p = 0; p < 8; p++) s += g_xpart[p * PS + BO + idx];
        g_x2[BO + idx] = s;
    }
    int w = t >> 5, lane = t & 31;
    for (int r = w; r < 128; r += 8) {
        float rsum = 0.f;
#pragma unroll
        for (int q = 0; q < 4; q++) {
            int idx = r * 128 + lane + q * 32;
            float s = 0.f;
#pragma unroll
            for (int p = 0; p < 8; p++) s += g_apart[p * PS + BO + idx];
            g_A2[BO + idx] = s;
            rsum += s;
        }
#pragma unroll
        for (int o = 16; o; o >>= 1) rsum += __shfl_down_sync(0xffffffffu, rsum, o);
        if (lane == 0) sd[r] = rsqrtf(rsum + 1.0f);
    }
    __syncthreads();
    for (int idx = t; idx < CH * CH; idx += 256) {
        int i = idx >> 7, j = idx & 127;
        float v = g_A2[BO + idx] + (i == j ? 1.f : 0.f);
        g_An[BO + idx] = sd[i] * v * sd[j];
    }
}

// ================= fused stack-2 (FFMA2, pitch-132 smem, 32 blocks) =================
__device__ __forceinline__ void gridbar(int target) {
    __syncthreads();
    __threadfence();
    if (threadIdx.x == 0) {
        atomicAdd(&g_bar, 1);
        while (*(volatile int*)&g_bar < target) __nanosleep(64);
    }
    __syncthreads();
    __threadfence();
}

__device__ __forceinline__ void gemm_sm128(const float* __restrict__ P, const float* __restrict__ Q,
                                           unsigned long long acc2[8][4], int tx, int ty)
{
#pragma unroll
    for (int i = 0; i < 8; i++)
#pragma unroll
        for (int j = 0; j < 4; j++) acc2[i][j] = 0ull;
#pragma unroll 2
    for (int k = 0; k < 128; k++) {
        float a[8];
#pragma unroll
        for (int i = 0; i < 8; i++) a[i] = P[(ty * 8 + i) * P2 + k];
        const unsigned long long* Qp =
            reinterpret_cast<const unsigned long long*>(&Q[k * P2 + tx * 8]);
        unsigned long long b0 = Qp[0], b1 = Qp[1], b2 = Qp[2], b3 = Qp[3];
#pragma unroll
        for (int i = 0; i < 8; i++) {
            unsigned long long ad = dup_f32(a[i]);
            ffma2(acc2[i][0], ad, b0);
            ffma2(acc2[i][1], ad, b1);
            ffma2(acc2[i][2], ad, b2);
            ffma2(acc2[i][3], ad, b3);
        }
    }
}

__global__ __launch_bounds__(256) void k_stack2(
    const float* __restrict__ w2a, const float* __restrict__ b2a,
    const float* __restrict__ g2a, const float* __restrict__ be2a,
    const float* __restrict__ w2b, const float* __restrict__ b2b,
    const float* __restrict__ g2b, const float* __restrict__ be2b,
    const float* __restrict__ wl, const float* __restrict__ bl,
    float* __restrict__ out, int out_size)
{
    extern __shared__ __align__(16) float sm2[];
    float* AN = sm2;
    float* XB = sm2 + 128 * P2;
    float* WB = sm2 + 256 * P2;
    __shared__ float red[2048];
    __shared__ float gv[128];
    __shared__ float lg[10];
    __shared__ float lse;
    int b = blockIdx.x, t = threadIdx.x, tx = t & 15, ty = t >> 4;
    const float INVN = 1.f / (NB * CH);
    PDL_ENTRY();

    {
        const float4* pAn = (const float4*)(g_An + (long long)b * 16384);
        const float4* pX2 = (const float4*)(g_x2 + (long long)b * 16384);
        const float4* pWa = (const float4*)w2a;
        for (int i = t; i < 4096; i += 256) {
            int r = i >> 5, c = (i & 31) * 4;
            *reinterpret_cast<float4*>(AN + r * P2 + c) = pAn[i];
            *reinterpret_cast<float4*>(XB + r * P2 + c) = pX2[i];
            *reinterpret_cast<float4*>(WB + r * P2 + c) = pWa[i];
        }
    }
    __syncthreads();

    unsigned long long acc2[8][4];
    float cs[8], cq[8];

    gemm_sm128(XB, WB, acc2, tx, ty);
    __syncthreads();
#pragma unroll
    for (int i = 0; i < 8; i++)
#pragma unroll
        for (int j = 0; j < 4; j++) {
            float2 p = u2f(acc2[i][j]);
            XB[(ty * 8 + i) * P2 + tx * 8 + 2 * j] = p.x;
            XB[(ty * 8 + i) * P2 + tx * 8 + 2 * j + 1] = p.y;
        }
    __syncthreads();

    gemm_sm128(AN, XB, acc2, tx, ty);
    __syncthreads();
#pragma unroll
    for (int j = 0; j < 8; j++) { cs[j] = 0.f; cq[j] = 0.f; }
#pragma unroll
    for (int i = 0; i < 8; i++)
#pragma unroll
        for (int j = 0; j < 4; j++) {
            float2 p = u2f(acc2[i][j]);
            float v0 = p.x + b2a[tx * 8 + 2 * j];
            float v1 = p.y + b2a[tx * 8 + 2 * j + 1];
            WB[(ty * 8 + i) * P2 + tx * 8 + 2 * j] = v0;
            WB[(ty * 8 + i) * P2 + tx * 8 + 2 * j + 1] = v1;
            cs[2 * j] += v0; cq[2 * j] += v0 * v0;
            cs[2 * j + 1] += v1; cq[2 * j + 1] += v1 * v1;
        }
#pragma unroll
    for (int j = 0; j < 8; j++) red[ty * 128 + tx * 8 + j] = cs[j];
    __syncthreads();
    if (t < 128) { float s = 0.f; for (int g = 0; g < 16; g++) s += red[g * 128 + t]; atomicAdd(&g_s2a[t], s); }
    __syncthreads();
#pragma unroll
    for (int j = 0; j < 8; j++) red[ty * 128 + tx * 8 + j] = cq[j];
    __syncthreads();
    if (t < 128) { float s = 0.f; for (int g = 0; g < 16; g++) s += red[g * 128 + t]; atomicAdd(&g_q2a[t], s); }

    gridbar(NB);

    float scv[8], shv[8];
#pragma unroll
    for (int j = 0; j < 8; j++) {
        int c = tx * 8 + j;
        float m = g_s2a[c] * INVN;
        float var = g_q2a[c] * INVN - m * m;
        float s = g2a[c] * rsqrtf(var + 1e-5f);
        scv[j] = s; shv[j] = be2a[c] - s * m;
    }
#pragma unroll
    for (int i = 0; i < 8; i++)
#pragma unroll
        for (int j = 0; j < 8; j++) {
            float v = WB[(ty * 8 + i) * P2 + tx * 8 + j];
            v = scv[j] * v + shv[j];
            v = v / (1.f + __expf(-v));
            XB[(ty * 8 + i) * P2 + tx * 8 + j] = v;
        }
    __syncthreads();

    {
        const float4* pWb = (const float4*)w2b;
        for (int i = t; i < 4096; i += 256) {
            int r = i >> 5, c = (i & 31) * 4;
            *reinterpret_cast<float4*>(WB + r * P2 + c) = pWb[i];
        }
    }
    __syncthreads();

    gemm_sm128(XB, WB, acc2, tx, ty);
    __syncthreads();
#pragma unroll
    for (int i = 0; i < 8; i++)
#pragma unroll
        for (int j = 0; j < 4; j++) {
            float2 p = u2f(acc2[i][j]);
            WB[(ty * 8 + i) * P2 + tx * 8 + 2 * j] = p.x;
            WB[(ty * 8 + i) * P2 + tx * 8 + 2 * j + 1] = p.y;
        }
    __syncthreads();

    gemm_sm128(AN, WB, acc2, tx, ty);
#pragma unroll
    for (int j = 0; j < 8; j++) { cs[j] = 0.f; cq[j] = 0.f; }
#pragma unroll
    for (int i = 0; i < 8; i++)
#pragma unroll
        for (int j = 0; j < 4; j++) {
            float2 p = u2f(acc2[i][j]);
            float v0 = p.x + b2b[tx * 8 + 2 * j];
            float v1 = p.y + b2b[tx * 8 + 2 * j + 1];
            cs[2 * j] += v0; cq[2 * j] += v0 * v0;
            cs[2 * j + 1] += v1; cq[2 * j + 1] += v1 * v1;
        }
    __syncthreads();
#pragma unroll
    for (int j = 0; j < 8; j++) red[ty * 128 + tx * 8 + j] = cs[j];
    __syncthreads();
    if (t < 128) { float s = 0.f; for (int g = 0; g < 16; g++) s += red[g * 128 + t]; atomicAdd(&g_s2b[t], s); }
    __syncthreads();
#pragma unroll
    for (int j = 0; j < 8; j++) red[ty * 128 + tx * 8 + j] = cq[j];
    __syncthreads();
    if (t < 128) { float s = 0.f; for (int g = 0; g < 16; g++) s += red[g * 128 + t]; atomicAdd(&g_q2b[t], s); }

    gridbar(2 * NB);

#pragma unroll
    for (int j = 0; j < 8; j++) {
        int c = tx * 8 + j;
        float m = g_s2b[c] * INVN;
        float var = g_q2b[c] * INVN - m * m;
        float s = g2b[c] * rsqrtf(var + 1e-5f);
        scv[j] = s; shv[j] = be2b[c] - s * m;
    }
    float colsum[8];
#pragma unroll
    for (int j = 0; j < 8; j++) colsum[j] = 0.f;
#pragma unroll
    for (int i = 0; i < 8; i++)
#pragma unroll
        for (int j = 0; j < 4; j++) {
            float2 p = u2f(acc2[i][j]);
            float v0 = scv[2 * j] * (p.x + b2b[tx * 8 + 2 * j]) + shv[2 * j];
            float v1 = scv[2 * j + 1] * (p.y + b2b[tx * 8 + 2 * j + 1]) + shv[2 * j + 1];
            v0 = v0 / (1.f + __expf(-v0));
            v1 = v1 / (1.f + __expf(-v1));
            v0 += XB[(ty * 8 + i) * P2 + tx * 8 + 2 * j];
            v1 += XB[(ty * 8 + i) * P2 + tx * 8 + 2 * j + 1];
            colsum[2 * j] += v0;
            colsum[2 * j + 1] += v1;
        }
    __syncthreads();
#pragma unroll
    for (int j = 0; j < 8; j++) red[ty * 128 + tx * 8 + j] = colsum[j];
    __syncthreads();
    if (t < 128) {
        float s = 0.f;
        for (int g = 0; g < 16; g++) s += red[g * 128 + t];
        gv[t] = s * (1.f / 32.f);
    }
    __syncthreads();
    if (t < 10) {
        float a = bl[t];
        for (int k = 0; k < 128; k++) a += gv[k] * wl[k * 10 + t];
        lg[t] = a;
    }
    __syncthreads();
    if (t == 0) {
        float mx = -1e30f;
        for (int j = 0; j < 10; j++) mx = fmaxf(mx, lg[j]);
        float se = 0.f;
        for (int j = 0; j < 10; j++) se += expf(lg[j] - mx);
        lse = mx + logf(se);
    }
    __syncthreads();
    if (t < 10) {
        int o = b * 10 + t;
        if (o < out_size) out[o] = lg[t] - lse;
    }
    if (b == 0) {
        for (int idx = NB * 10 + t; idx < out_size; idx += 256) out[idx] = 0.f;
    }
}

// ================= host orchestration =================
extern "C" void kernel_launch(void* const* d_in, const int* in_sizes, int n_in,
                              void* d_out, int out_size) {
    const float* x    = (const float*)d_in[0];
    const int*   ei   = (const int*)  d_in[1];
    const float* w1a  = (const float*)d_in[4];
    const float* b1a  = (const float*)d_in[5];
    const float* g1a  = (const float*)d_in[6];
    const float* be1a = (const float*)d_in[7];
    const float* w1b  = (const float*)d_in[8];
    const float* b1b  = (const float*)d_in[9];
    const float* g1b  = (const float*)d_in[10];
    const float* be1b = (const float*)d_in[11];
    const float* wp1  = (const float*)d_in[12];
    const float* bp1  = (const float*)d_in[13];
    const float* w2a  = (const float*)d_in[14];
    const float* b2a  = (const float*)d_in[15];
    const float* g2a  = (const float*)d_in[16];
    const float* be2a = (const float*)d_in[17];
    const float* w2b  = (const float*)d_in[18];
    const float* b2b  = (const float*)d_in[19];
    const float* g2b  = (const float*)d_in[20];
    const float* be2b = (const float*)d_in[21];
    const float* wl   = (const float*)d_in[24];
    const float* bl   = (const float*)d_in[25];
    float* outp = (float*)d_out;
    (void)n_in; (void)in_sizes;

    float *p_y, *p_h, *p_xpart, *p_apart;
    float *p_sumA, *p_ssA, *p_sumB, *p_ssB, *p_dinv;
    __nv_bfloat16 *p_linb, *p_sb;
    __nv_bfloat16 *p_axh, *p_axl, *p_hah, *p_hal, *p_hbh, *p_hbl;
    __nv_bfloat16 *p_hTh, *p_hTl, *p_sTh, *p_sTl, *p_tTh, *p_tTl;
    __nv_bfloat16 *p_w1ah, *p_w1al, *p_w1bh, *p_w1bl, *p_wp1h, *p_wp1l;
    cudaGetSymbolAddress((void**)&p_y,     g_y);
    cudaGetSymbolAddress((void**)&p_h,     g_h);
    cudaGetSymbolAddress((void**)&p_linb,  g_linb);
    cudaGetSymbolAddress((void**)&p_sb,    g_sb);
    cudaGetSymbolAddress((void**)&p_xpart, g_xpart);
    cudaGetSymbolAddress((void**)&p_apart, g_apart);
    cudaGetSymbolAddress((void**)&p_sumA,  g_sumA);
    cudaGetSymbolAddress((void**)&p_ssA,   g_ssA);
    cudaGetSymbolAddress((void**)&p_sumB,  g_sumB);
    cudaGetSymbolAddress((void**)&p_ssB,   g_ssB);
    cudaGetSymbolAddress((void**)&p_dinv,  g_dinv);
    cudaGetSymbolAddress((void**)&p_axh,   g_axh);
    cudaGetSymbolAddress((void**)&p_axl,   g_axl);
    cudaGetSymbolAddress((void**)&p_hah,   g_hah);
    cudaGetSymbolAddress((void**)&p_hal,   g_hal);
    cudaGetSymbolAddress((void**)&p_hbh,   g_hbh);
    cudaGetSymbolAddress((void**)&p_hbl,   g_hbl);
    cudaGetSymbolAddress((void**)&p_hTh,   g_hTh);
    cudaGetSymbolAddress((void**)&p_hTl,   g_hTl);
    cudaGetSymbolAddress((void**)&p_sTh,   g_sTh);
    cudaGetSymbolAddress((void**)&p_sTl,   g_sTl);
    cudaGetSymbolAddress((void**)&p_tTh,   g_tTh);
    cudaGetSymbolAddress((void**)&p_tTl,   g_tTl);
    cudaGetSymbolAddress((void**)&p_w1ah,  g_w1ah);
    cudaGetSymbolAddress((void**)&p_w1al,  g_w1al);
    cudaGetSymbolAddress((void**)&p_w1bh,  g_w1bh);
    cudaGetSymbolAddress((void**)&p_w1bl,  g_w1bl);
    cudaGetSymbolAddress((void**)&p_wp1h,  g_wp1h);
    cudaGetSymbolAddress((void**)&p_wp1l,  g_wp1l);

    const int SM2 = 3 * 128 * P2 * 4;

    static bool attrDone = false;
    if (!attrDone) {
        cudaFuncSetAttribute(k_stack2, cudaFuncAttributeMaxDynamicSharedMemorySize, SM2);
        cudaFuncSetAttribute(k_mma<false, true>,  cudaFuncAttributeMaxDynamicSharedMemorySize, 50176);
        cudaFuncSetAttribute(k_mma<false, false>, cudaFuncAttributeMaxDynamicSharedMemorySize, 50176);
        cudaFuncSetAttribute(k_mma<true, false>,  cudaFuncAttributeMaxDynamicSharedMemorySize, 50176);
        attrDone = true;
    }

    cudaLaunchAttribute pdl[1];
    pdl[0].id = cudaLaunchAttributeProgrammaticStreamSerialization;
    pdl[0].val.programmaticStreamSerializationAllowed = 1;
    auto cfg = [&](dim3 g, dim3 b, size_t smem) {
        cudaLaunchConfig_t c = {};
        c.gridDim = g; c.blockDim = b; c.dynamicSmemBytes = smem;
        c.stream = 0; c.attrs = pdl; c.numAttrs = 1;
        return c;
    };

    // graph structure + weight split + x convert
    { auto c = cfg(dim3(NNODES / 256), dim3(256), 0); cudaLaunchKernelEx(&c, k_zero_deg); }
    { auto c = cfg(dim3(NEDGES / 512), dim3(256), 0); cudaLaunchKernelEx(&c, k_build, ei); }
    { auto c = cfg(dim3(160), dim3(256), 0); cudaLaunchKernelEx(&c, k_wsplit, w1a, w1b, wp1); }
    { auto c = cfg(dim3(NNODES / 8), dim3(256), 0); cudaLaunchKernelEx(&c, k_xconv, x); }

    // stack 1, layer a (bf16 gather)
    { auto c = cfg(dim3(NNODES / 8), dim3(256), 0); cudaLaunchKernelEx(&c, k_aggx); }
    { auto c = cfg(dim3(256), dim3(256), 50176);
      cudaLaunchKernelEx(&c, k_mma<false, true>,
          (const __nv_bfloat16*)p_axh, (const __nv_bfloat16*)p_axl, (long long)64,
          (const __nv_bfloat16*)p_w1ah, (const __nv_bfloat16*)p_w1al,
          (const __nv_bfloat16*)nullptr, (const __nv_bfloat16*)nullptr, (long long)64,
          b1a, (const float*)nullptr, p_y, (float*)nullptr,
          (__nv_bfloat16*)nullptr, 64); }
    { auto c = cfg(dim3(NNODES / 32, 4), dim3(256), 0);
      cudaLaunchKernelEx(&c, k_bn<false, true, false>,
          (const float*)p_y, (const float*)nullptr, p_h, p_hah, p_hal,
          (__nv_bfloat16*)nullptr, (__nv_bfloat16*)nullptr, g1a, be1a,
          (const float*)p_sumA, (const float*)p_ssA); }

    // stack 1, layer b: GEMM -> bf16 rows only (dinv-prescaled)
    { auto c = cfg(dim3(256), dim3(256), 50176);
      cudaLaunchKernelEx(&c, k_mma<false, false>,
          (const __nv_bfloat16*)p_hah, (const __nv_bfloat16*)p_hal, (long long)128,
          (const __nv_bfloat16*)p_w1bh, (const __nv_bfloat16*)p_w1bl,
          (const __nv_bfloat16*)nullptr, (const __nv_bfloat16*)nullptr, (long long)128,
          (const float*)nullptr, (const float*)p_dinv,
          (float*)nullptr, (float*)nullptr, p_linb, 128); }
    { auto c = cfg(dim3(NNODES / 8), dim3(256), 0);
      cudaLaunchKernelEx(&c, k_aggw<0>, (const __nv_bfloat16*)p_linb, b1b, p_y,
          (__nv_bfloat16*)nullptr, (__nv_bfloat16*)nullptr, (__nv_bfloat16*)nullptr); }
    { auto c = cfg(dim3(NNODES / 32, 4), dim3(256), 0);
      cudaLaunchKernelEx(&c, k_bn<true, false, true>,
          (const float*)p_y, (const float*)p_h, (float*)nullptr, p_hbh, p_hbl,
          p_hTh, p_hTl, g1b, be1b, (const float*)p_sumB, (const float*)p_ssB); }

    // pooling 1
    { auto c = cfg(dim3(256), dim3(256), 50176);
      cudaLaunchKernelEx(&c, k_mma<false, false>,
          (const __nv_bfloat16*)p_hbh, (const __nv_bfloat16*)p_hbl, (long long)128,
          (const __nv_bfloat16*)p_wp1h, (const __nv_bfloat16*)p_wp1l,
          (const __nv_bfloat16*)nullptr, (const __nv_bfloat16*)nullptr, (long long)128,
          (const float*)nullptr, (const float*)p_dinv,
          (float*)nullptr, (float*)nullptr, p_linb, 128); }
    { auto c = cfg(dim3(NNODES / 8), dim3(256), 0);
      cudaLaunchKernelEx(&c, k_aggw<1>, (const __nv_bfloat16*)p_linb, bp1,
          (float*)nullptr, p_sb, p_sTh, p_sTl); }
    { auto c = cfg(dim3(NNODES / 8), dim3(256), 0);
      cudaLaunchKernelEx(&c, k_aggw<2>, (const __nv_bfloat16*)p_sb, (const float*)nullptr,
          (float*)nullptr, (__nv_bfloat16*)nullptr, p_tTh, p_tTl); }

    // pooled einsums + reduce/An
    { auto c = cfg(dim3(1, 16, NB), dim3(256), 50176);
      cudaLaunchKernelEx(&c, k_mma<true, false>,
          (const __nv_bfloat16*)p_sTh, (const __nv_bfloat16*)p_sTl, (long long)NNODES,
          (const __nv_bfloat16*)p_hTh, (const __nv_bfloat16*)p_hTl,
          (const __nv_bfloat16*)p_tTh, (const __nv_bfloat16*)p_tTl, (long long)NNODES,
          (const float*)nullptr, (const float*)nullptr,
          p_xpart, p_apart, (__nv_bfloat16*)nullptr, 128); }
    { auto c = cfg(dim3(NB), dim3(256), 0); cudaLaunchKernelEx(&c, k_reduce_an); }

    // fused stack 2 (FFMA2, pitch-132 smem) + head
    { auto c = cfg(dim3(NB), dim3(256), SM2);
      cudaLaunchKernelEx(&c, k_stack2, w2a, b2a, g2a, be2a, w2b, b2b, g2b, be2b,
          wl, bl, outp, out_size); }
}